// round 2
// baseline (speedup 1.0000x reference)
#include <cuda_runtime.h>

#define NB 2
#define CD 256
#define LL 4096
#define NH 4
#define DKH 64

static constexpr float LOG2E = 1.4426950408889634f;

// Scratch (device globals; no allocations allowed)
__device__ float g_x[NB * LL * CD];        // x transposed: [b][l][c]
__device__ float g_q[NB * NH * LL * DKH];  // qkv heads:    [b][h][l][d]
__device__ float g_att[NB * LL * CD];      // attn out:     [b][l][h*64+d]
__device__ float g_y[NB * LL * CD];        // fc+residual:  [b][l][c]

// ---------------------------------------------------------------------------
// Kernel 1: QKV projection + write transposed x.
// out[l,o] = sum_c x_in[b][c][l] * W[o][c]     (x_in is the [B,C,H,W] input)
// Tile 64(l) x 64(o), k-chunks of 64. 256 threads, 4x4 microtile per thread.
// ---------------------------------------------------------------------------
__global__ __launch_bounds__(256) void k_qkv(const float* __restrict__ qin,
                                             const float* __restrict__ wqkv) {
    __shared__ float As[64][68];  // As[c][l]
    __shared__ float Ws[64][68];  // Ws[c][o]
    const int bt = blockIdx.z;
    const int o0 = blockIdx.y * 64;
    const int l0 = blockIdx.x * 64;
    const int tid = threadIdx.x;
    const int tx = tid & 15, ty = tid >> 4;

    float acc[4][4] = {};
    for (int c0 = 0; c0 < CD; c0 += 64) {
        __syncthreads();
        #pragma unroll
        for (int idx = tid; idx < 64 * 64; idx += 256) {
            int ci = idx >> 6, lj = idx & 63;
            As[ci][lj] = qin[bt * CD * LL + (c0 + ci) * LL + l0 + lj];
        }
        #pragma unroll
        for (int idx = tid; idx < 64 * 64; idx += 256) {
            int oi = idx >> 6, cj = idx & 63;
            Ws[cj][oi] = wqkv[(o0 + oi) * CD + c0 + cj];
        }
        __syncthreads();
        if (blockIdx.y == 0) {
            // write x transposed for the residual path
            #pragma unroll
            for (int idx = tid; idx < 64 * 64; idx += 256) {
                int li = idx >> 6, cj = idx & 63;
                g_x[(bt * LL + l0 + li) * CD + c0 + cj] = As[cj][li];
            }
        }
        #pragma unroll 8
        for (int c = 0; c < 64; c++) {
            float4 a = *(const float4*)&As[c][ty * 4];
            float4 w = *(const float4*)&Ws[c][tx * 4];
            float av[4] = {a.x, a.y, a.z, a.w};
            float wv[4] = {w.x, w.y, w.z, w.w};
            #pragma unroll
            for (int i = 0; i < 4; i++)
                #pragma unroll
                for (int j = 0; j < 4; j++) acc[i][j] += av[i] * wv[j];
        }
    }
    const int h = blockIdx.y;  // o-tile == head (64 wide each)
    #pragma unroll
    for (int i = 0; i < 4; i++) {
        float4 v = make_float4(acc[i][0], acc[i][1], acc[i][2], acc[i][3]);
        *(float4*)&g_q[((bt * NH + h) * LL + l0 + ty * 4 + i) * DKH + tx * 4] = v;
    }
}

// ---------------------------------------------------------------------------
// Kernel 2: flash attention (fp32). Q == K == V (shared projection).
// Per CTA: one (b,h), 64 query rows. Loop over 64 key tiles of 64.
// smem: Qt[d][m], Kt[d][n] (transposed for float4 operand loads),
//       Vs[n][v], Ps[m][n]. 4 x 64 x 68 floats = 68 KB -> dynamic smem.
// ---------------------------------------------------------------------------
extern __shared__ float sm_attn[];
__global__ __launch_bounds__(256, 2) void k_attn() {
    float* Qt = sm_attn;               // [64][68]
    float* Kt = sm_attn + 64 * 68;     // [64][68]
    float* Vs = sm_attn + 2 * 64 * 68; // [64][68]
    float* Ps = sm_attn + 3 * 64 * 68; // [64][68]

    const int bh = blockIdx.y;                    // b*NH + h
    const float* qb = g_q + bh * LL * DKH;
    const int m0 = blockIdx.x * 64;
    const int tid = threadIdx.x;
    const int tx = tid & 15, ty = tid >> 4;

    // load Q tile transposed (once)
    for (int idx = tid; idx < 64 * 64; idx += 256) {
        int m = idx >> 6, d = idx & 63;
        Qt[d * 68 + m] = qb[(m0 + m) * DKH + d];
    }

    float O[4][4] = {};
    float mr[4], lr[4];
    #pragma unroll
    for (int i = 0; i < 4; i++) { mr[i] = -1e30f; lr[i] = 0.f; }

    for (int n0 = 0; n0 < LL; n0 += 64) {
        __syncthreads();
        // K tile == V tile (same data, two smem layouts)
        for (int idx = tid; idx < 64 * 64; idx += 256) {
            int n = idx >> 6, d = idx & 63;
            float v = qb[(n0 + n) * DKH + d];
            Kt[d * 68 + n] = v;
            Vs[n * 68 + d] = v;
        }
        __syncthreads();

        // S = Q K^T (4x4 microtile per thread)
        float s[4][4] = {};
        #pragma unroll 4
        for (int d = 0; d < 64; d++) {
            float4 a = *(const float4*)&Qt[d * 68 + ty * 4];
            float4 b = *(const float4*)&Kt[d * 68 + tx * 4];
            float av[4] = {a.x, a.y, a.z, a.w};
            float bv[4] = {b.x, b.y, b.z, b.w};
            #pragma unroll
            for (int i = 0; i < 4; i++)
                #pragma unroll
                for (int j = 0; j < 4; j++) s[i][j] += av[i] * bv[j];
        }

        // online softmax per row (reduce across the 16 tx lanes)
        #pragma unroll
        for (int i = 0; i < 4; i++) {
            #pragma unroll
            for (int j = 0; j < 4; j++) s[i][j] *= 0.125f;  // 1/sqrt(64)
            float mx = fmaxf(fmaxf(s[i][0], s[i][1]), fmaxf(s[i][2], s[i][3]));
            #pragma unroll
            for (int off = 1; off < 16; off <<= 1)
                mx = fmaxf(mx, __shfl_xor_sync(0xffffffffu, mx, off));
            float mnew = fmaxf(mr[i], mx);
            float corr = exp2f((mr[i] - mnew) * LOG2E);
            float p[4]; float rs = 0.f;
            #pragma unroll
            for (int j = 0; j < 4; j++) {
                p[j] = exp2f((s[i][j] - mnew) * LOG2E);
                rs += p[j];
            }
            #pragma unroll
            for (int off = 1; off < 16; off <<= 1)
                rs += __shfl_xor_sync(0xffffffffu, rs, off);
            lr[i] = lr[i] * corr + rs;
            mr[i] = mnew;
            #pragma unroll
            for (int j = 0; j < 4; j++) O[i][j] *= corr;
            *(float4*)&Ps[(ty * 4 + i) * 68 + tx * 4] =
                make_float4(p[0], p[1], p[2], p[3]);
        }
        __syncthreads();

        // O += P @ V
        #pragma unroll 4
        for (int n = 0; n < 64; n++) {
            float4 b = *(const float4*)&Vs[n * 68 + tx * 4];
            float bv[4] = {b.x, b.y, b.z, b.w};
            #pragma unroll
            for (int i = 0; i < 4; i++) {
                float a = Ps[(ty * 4 + i) * 68 + n];
                #pragma unroll
                for (int j = 0; j < 4; j++) O[i][j] += a * bv[j];
            }
        }
    }

    const int b = bh >> 2, h = bh & 3;
    #pragma unroll
    for (int i = 0; i < 4; i++) {
        float inv = 1.0f / lr[i];
        float4 o = make_float4(O[i][0] * inv, O[i][1] * inv,
                               O[i][2] * inv, O[i][3] * inv);
        *(float4*)&g_att[(b * LL + m0 + ty * 4 + i) * CD + h * DKH + tx * 4] = o;
    }
}

// ---------------------------------------------------------------------------
// Kernel 3: fc GEMM + bias + residual.  y[r,o] = att[r,:] . fc_w[o,:] + b + x
// ---------------------------------------------------------------------------
__global__ __launch_bounds__(256) void k_fc(const float* __restrict__ fw,
                                            const float* __restrict__ fb) {
    __shared__ float At[64][68];  // At[k][r]
    __shared__ float Ws[64][68];  // Ws[k][o]
    const int r0 = blockIdx.x * 64;   // row in [0, B*L)
    const int o0 = blockIdx.y * 64;
    const int tid = threadIdx.x;
    const int tx = tid & 15, ty = tid >> 4;

    float acc[4][4] = {};
    for (int k0 = 0; k0 < CD; k0 += 64) {
        __syncthreads();
        #pragma unroll
        for (int idx = tid; idx < 64 * 64; idx += 256) {
            int ri = idx >> 6, kj = idx & 63;
            At[kj][ri] = g_att[(r0 + ri) * CD + k0 + kj];
        }
        #pragma unroll
        for (int idx = tid; idx < 64 * 64; idx += 256) {
            int oi = idx >> 6, kj = idx & 63;
            Ws[kj][oi] = fw[(o0 + oi) * CD + k0 + kj];
        }
        __syncthreads();
        #pragma unroll 8
        for (int k = 0; k < 64; k++) {
            float4 a = *(const float4*)&At[k][ty * 4];
            float4 w = *(const float4*)&Ws[k][tx * 4];
            float av[4] = {a.x, a.y, a.z, a.w};
            float wv[4] = {w.x, w.y, w.z, w.w};
            #pragma unroll
            for (int i = 0; i < 4; i++)
                #pragma unroll
                for (int j = 0; j < 4; j++) acc[i][j] += av[i] * wv[j];
        }
    }
    #pragma unroll
    for (int i = 0; i < 4; i++) {
        int r = r0 + ty * 4 + i;
        float4 bias = *(const float4*)&fb[o0 + tx * 4];
        float4 res  = *(const float4*)&g_x[r * CD + o0 + tx * 4];
        float4 v = make_float4(acc[i][0] + bias.x + res.x,
                               acc[i][1] + bias.y + res.y,
                               acc[i][2] + bias.z + res.z,
                               acc[i][3] + bias.w + res.w);
        *(float4*)&g_y[r * CD + o0 + tx * 4] = v;
    }
}

// ---------------------------------------------------------------------------
// Kernel 4: LayerNorm over C=256. One warp per row, 8 rows per block.
// ---------------------------------------------------------------------------
__global__ __launch_bounds__(256) void k_ln(const float* __restrict__ gam,
                                            const float* __restrict__ bet,
                                            float* __restrict__ out) {
    const int row = blockIdx.x * 8 + (threadIdx.x >> 5);
    const int lane = threadIdx.x & 31;
    const float* y = g_y + row * CD;
    float v[8], s = 0.f, s2 = 0.f;
    #pragma unroll
    for (int k = 0; k < 8; k++) {
        v[k] = y[lane + 32 * k];
        s += v[k];
        s2 += v[k] * v[k];
    }
    #pragma unroll
    for (int off = 16; off; off >>= 1) {
        s  += __shfl_xor_sync(0xffffffffu, s, off);
        s2 += __shfl_xor_sync(0xffffffffu, s2, off);
    }
    const float mu = s * (1.f / CD);
    const float rstd = rsqrtf(s2 * (1.f / CD) - mu * mu + 1e-5f);
    #pragma unroll
    for (int k = 0; k < 8; k++) {
        int c = lane + 32 * k;
        out[row * CD + c] = (v[k] - mu) * rstd * gam[c] + bet[c];
    }
}

// ---------------------------------------------------------------------------
extern "C" void kernel_launch(void* const* d_in, const int* in_sizes, int n_in,
                              void* d_out, int out_size) {
    const float* qin = (const float*)d_in[0];
    const float* wq  = (const float*)d_in[1];
    const float* fw  = (const float*)d_in[2];
    const float* fb  = (const float*)d_in[3];
    const float* lg  = (const float*)d_in[4];
    const float* lb  = (const float*)d_in[5];
    float* out = (float*)d_out;

    const int attn_smem = 4 * 64 * 68 * (int)sizeof(float);  // 69,632 B
    cudaFuncSetAttribute(k_attn, cudaFuncAttributeMaxDynamicSharedMemorySize,
                         attn_smem);

    k_qkv<<<dim3(LL / 64, NH, NB), 256>>>(qin, wq);
    k_attn<<<dim3(LL / 64, NB * NH), 256, attn_smem>>>();
    k_fc<<<dim3(NB * LL / 64, CD / 64), 256>>>(fw, fb);
    k_ln<<<NB * LL / 8, 256>>>(lg, lb, out);
}

// round 5
// speedup vs baseline: 3.8054x; 3.8054x over previous
#include <cuda_runtime.h>
#include <cuda_bf16.h>
#include <cuda_fp16.h>
#include <stdint.h>

#define NB 2
#define CD 256
#define LL 4096
#define NH 4
#define DKH 64

static constexpr float LOG2E = 1.4426950408889634f;

__device__ float g_x[NB * LL * CD];        // x transposed: [b][l][c]
__device__ float g_q[NB * NH * LL * DKH];  // qkv heads:    [b][h][l][d]
__device__ float g_att[NB * LL * CD];      // attn out:     [b][l][h*64+d]
__device__ float g_y[NB * LL * CD];        // fc+residual:  [b][l][c]

// ------------------------- helpers -------------------------
__device__ __forceinline__ uint32_t smem_u32(const void* p) {
    uint32_t a;
    asm("{ .reg .u64 t; cvta.to.shared.u64 t, %1; cvt.u32.u64 %0, t; }"
        : "=r"(a) : "l"(p));
    return a;
}
__device__ __forceinline__ uint32_t SWZ(uint32_t o) {
    return o ^ ((o >> 3) & 0x70);
}
__device__ __forceinline__ void ldsm4(uint32_t* r, uint32_t a) {
    asm volatile("ldmatrix.sync.aligned.m8n8.x4.shared.b16 {%0,%1,%2,%3}, [%4];"
                 : "=r"(r[0]), "=r"(r[1]), "=r"(r[2]), "=r"(r[3]) : "r"(a));
}
__device__ __forceinline__ void ldsm4t(uint32_t* r, uint32_t a) {
    asm volatile("ldmatrix.sync.aligned.m8n8.x4.trans.shared.b16 {%0,%1,%2,%3}, [%4];"
                 : "=r"(r[0]), "=r"(r[1]), "=r"(r[2]), "=r"(r[3]) : "r"(a));
}
__device__ __forceinline__ void mma_bf16(float* d, const uint32_t* a,
                                         uint32_t b0, uint32_t b1) {
    asm volatile(
        "mma.sync.aligned.m16n8k16.row.col.f32.bf16.bf16.f32 "
        "{%0,%1,%2,%3}, {%4,%5,%6,%7}, {%8,%9}, {%0,%1,%2,%3};"
        : "+f"(d[0]), "+f"(d[1]), "+f"(d[2]), "+f"(d[3])
        : "r"(a[0]), "r"(a[1]), "r"(a[2]), "r"(a[3]), "r"(b0), "r"(b1));
}
__device__ __forceinline__ void mma_f16(float* d, uint32_t a0, uint32_t a1,
                                        uint32_t a2, uint32_t a3,
                                        uint32_t b0, uint32_t b1) {
    asm volatile(
        "mma.sync.aligned.m16n8k16.row.col.f32.f16.f16.f32 "
        "{%0,%1,%2,%3}, {%4,%5,%6,%7}, {%8,%9}, {%0,%1,%2,%3};"
        : "+f"(d[0]), "+f"(d[1]), "+f"(d[2]), "+f"(d[3])
        : "r"(a0), "r"(a1), "r"(a2), "r"(a3), "r"(b0), "r"(b1));
}
__device__ __forceinline__ float ex2f(float x) {
    float y;
    asm("ex2.approx.ftz.f32 %0, %1;" : "=f"(y) : "f"(x));
    return y;
}
__device__ __forceinline__ uint32_t pk_bf(__nv_bfloat16 a, __nv_bfloat16 b) {
    __nv_bfloat162 v; v.x = a; v.y = b;
    return *(uint32_t*)&v;
}
__device__ __forceinline__ uint32_t pk_h2(float a, float b) {
    __half2 h = __floats2half2_rn(a, b);
    return *(uint32_t*)&h;
}
__device__ __forceinline__ void hilo(float x, __nv_bfloat16& h, __nv_bfloat16& l) {
    h = __float2bfloat16(x);
    l = __float2bfloat16(x - __bfloat162float(h));
}

// ---------------------------------------------------------------------------
// Kernel 1: QKV projection + write transposed x.
// ---------------------------------------------------------------------------
__global__ __launch_bounds__(256) void k_qkv(const float* __restrict__ qin,
                                             const float* __restrict__ wqkv) {
    __shared__ float As[64][68];
    __shared__ float Ws[64][68];
    const int bt = blockIdx.z;
    const int h = blockIdx.y;
    const int o0 = h * 64;
    const int l0 = blockIdx.x * 64;
    const int tid = threadIdx.x;
    const int tx = tid & 15, ty = tid >> 4;

    float acc[4][4] = {};
    for (int c0 = 0; c0 < CD; c0 += 64) {
        __syncthreads();
        #pragma unroll
        for (int idx = tid; idx < 64 * 64; idx += 256) {
            int ci = idx >> 6, lj = idx & 63;
            As[ci][lj] = qin[bt * CD * LL + (c0 + ci) * LL + l0 + lj];
        }
        #pragma unroll
        for (int idx = tid; idx < 64 * 64; idx += 256) {
            int oi = idx >> 6, cj = idx & 63;
            Ws[cj][oi] = wqkv[(o0 + oi) * CD + c0 + cj];
        }
        __syncthreads();
        if (h == 0) {
            #pragma unroll
            for (int idx = tid; idx < 64 * 64; idx += 256) {
                int li = idx >> 6, cj = idx & 63;
                g_x[(bt * LL + l0 + li) * CD + c0 + cj] = As[cj][li];
            }
        }
        #pragma unroll 8
        for (int c = 0; c < 64; c++) {
            float4 a = *(const float4*)&As[c][ty * 4];
            float4 w = *(const float4*)&Ws[c][tx * 4];
            float av[4] = {a.x, a.y, a.z, a.w};
            float wv[4] = {w.x, w.y, w.z, w.w};
            #pragma unroll
            for (int i = 0; i < 4; i++)
                #pragma unroll
                for (int j = 0; j < 4; j++) acc[i][j] += av[i] * wv[j];
        }
    }
    const int bh = bt * NH + h;
    #pragma unroll
    for (int i = 0; i < 4; i++) {
        float4 v = make_float4(acc[i][0], acc[i][1], acc[i][2], acc[i][3]);
        *(float4*)&g_q[((size_t)bh * LL + l0 + ty * 4 + i) * DKH + tx * 4] = v;
    }
}

// ---------------------------------------------------------------------------
// Kernel 2: HMMA flash attention. 128 threads / 4 warps, 64 q-rows per CTA,
// key tiles of 128. SMEM: Khi(bf16) 16K | Klo(bf16) 16K | V(f16) 16K.
// S = QhKh + QlKh + QhKl (bf16 hi/lo), online softmax in registers,
// P (fp16, in-register) @ V (fp16 via ldmatrix.trans).
// ---------------------------------------------------------------------------
__global__ __launch_bounds__(128) void k_attn_mma() {
    extern __shared__ char sm[];
    char* sKhi = sm;
    char* sKlo = sm + 16384;
    char* sV   = sm + 32768;
    const uint32_t KhiB = smem_u32(sKhi);
    const uint32_t KloB = KhiB + 16384;
    const uint32_t VB   = KhiB + 32768;

    const int tid = threadIdx.x;
    const int lane = tid & 31;
    const int wid = tid >> 5;
    const int bh = blockIdx.y;
    const int m0 = blockIdx.x * 64;
    const float* qb = g_q + (size_t)bh * LL * DKH;

    const uint32_t laneRow = lane & 15;
    const uint32_t laneCol = ((lane >> 4) & 1) * 16;   // bytes (8 elements)

    // ---- stage this CTA's 64 Q rows as bf16 hi/lo into Khi/Klo ----
    #pragma unroll
    for (int it = 0; it < 8; it++) {
        int idx = tid + it * 128;
        int r = idx >> 4, k4 = idx & 15;
        float4 v = *(const float4*)(qb + (size_t)(m0 + r) * DKH + k4 * 4);
        __nv_bfloat16 h0, e0, h1, e1, h2, e2, h3, e3;
        hilo(v.x, h0, e0); hilo(v.y, h1, e1);
        hilo(v.z, h2, e2); hilo(v.w, h3, e3);
        uint32_t off = SWZ(r * 128 + k4 * 8);
        *(uint2*)(sKhi + off) = make_uint2(pk_bf(h0, h1), pk_bf(h2, h3));
        *(uint2*)(sKlo + off) = make_uint2(pk_bf(e0, e1), pk_bf(e2, e3));
    }
    __syncthreads();

    // ---- Q fragments (A, m16k16 x 4 chunks, hi & lo) ----
    uint32_t qh[4][4], ql[4][4];
    {
        uint32_t rowb = (wid * 16 + laneRow) * 128;
        #pragma unroll
        for (int c = 0; c < 4; c++) {
            uint32_t off = SWZ(rowb + c * 32 + laneCol);
            ldsm4(qh[c], KhiB + off);
            ldsm4(ql[c], KloB + off);
        }
    }

    float o[8][4] = {};
    float mr0 = -1e30f, mr1 = -1e30f, l0 = 0.f, l1 = 0.f;
    const float c1 = LOG2E * 0.125f;

    for (int t = 0; t < LL / 128; t++) {
        const float* kb = qb + (size_t)t * 128 * DKH;
        __syncthreads();
        // ---- load K/V tile: fp32 -> bf16 hi/lo + fp16 ----
        #pragma unroll
        for (int it = 0; it < 16; it++) {
            int idx = tid + it * 128;
            int n = idx >> 4, k4 = idx & 15;
            float4 v = *(const float4*)(kb + (size_t)n * DKH + k4 * 4);
            __nv_bfloat16 h0, e0, h1, e1, h2, e2, h3, e3;
            hilo(v.x, h0, e0); hilo(v.y, h1, e1);
            hilo(v.z, h2, e2); hilo(v.w, h3, e3);
            uint32_t off = SWZ(n * 128 + k4 * 8);
            *(uint2*)(sKhi + off) = make_uint2(pk_bf(h0, h1), pk_bf(h2, h3));
            *(uint2*)(sKlo + off) = make_uint2(pk_bf(e0, e1), pk_bf(e2, e3));
            *(uint2*)(sV + off)   = make_uint2(pk_h2(v.x, v.y), pk_h2(v.z, v.w));
        }
        __syncthreads();

        // ---- S = Q K^T : 16 n-tiles of 8 ----
        float s[16][4];
        #pragma unroll
        for (int j = 0; j < 16; j++)
            #pragma unroll
            for (int k = 0; k < 4; k++) s[j][k] = 0.f;

        #pragma unroll
        for (int jp = 0; jp < 8; jp++) {
            #pragma unroll
            for (int c = 0; c < 4; c++) {
                uint32_t off = SWZ((jp * 16 + laneRow) * 128 + c * 32 + laneCol);
                uint32_t bhf[4], blf[4];
                ldsm4(bhf, KhiB + off);
                ldsm4(blf, KloB + off);
                // ldsm4 reg map: [0]=n-lo/k-lo [1]=n-hi/k-lo [2]=n-lo/k-hi [3]=n-hi/k-hi
                // MMA B operand = {k-lo, k-hi} of SAME n-group.
                mma_bf16(s[2 * jp],     qh[c], bhf[0], bhf[2]);
                mma_bf16(s[2 * jp],     ql[c], bhf[0], bhf[2]);
                mma_bf16(s[2 * jp],     qh[c], blf[0], blf[2]);
                mma_bf16(s[2 * jp + 1], qh[c], bhf[1], bhf[3]);
                mma_bf16(s[2 * jp + 1], ql[c], bhf[1], bhf[3]);
                mma_bf16(s[2 * jp + 1], qh[c], blf[1], blf[3]);
            }
        }

        // ---- online softmax (rows lane/4 and lane/4+8 of this warp tile) ----
        float mt0 = -1e30f, mt1 = -1e30f;
        #pragma unroll
        for (int j = 0; j < 16; j++) {
            mt0 = fmaxf(mt0, fmaxf(s[j][0], s[j][1]));
            mt1 = fmaxf(mt1, fmaxf(s[j][2], s[j][3]));
        }
        mt0 = fmaxf(mt0, __shfl_xor_sync(0xffffffffu, mt0, 1));
        mt0 = fmaxf(mt0, __shfl_xor_sync(0xffffffffu, mt0, 2));
        mt1 = fmaxf(mt1, __shfl_xor_sync(0xffffffffu, mt1, 1));
        mt1 = fmaxf(mt1, __shfl_xor_sync(0xffffffffu, mt1, 2));
        float mn0 = fmaxf(mr0, mt0), mn1 = fmaxf(mr1, mt1);
        float cr0 = ex2f((mr0 - mn0) * c1), cr1 = ex2f((mr1 - mn1) * c1);
        mr0 = mn0; mr1 = mn1;
        l0 *= cr0; l1 *= cr1;
        #pragma unroll
        for (int vt = 0; vt < 8; vt++) {
            o[vt][0] *= cr0; o[vt][1] *= cr0;
            o[vt][2] *= cr1; o[vt][3] *= cr1;
        }
        const float mc0 = mn0 * c1, mc1 = mn1 * c1;
        uint32_t p[16][2];
        #pragma unroll
        for (int j = 0; j < 16; j++) {
            float e0 = ex2f(fmaf(s[j][0], c1, -mc0));
            float e1 = ex2f(fmaf(s[j][1], c1, -mc0));
            float e2 = ex2f(fmaf(s[j][2], c1, -mc1));
            float e3 = ex2f(fmaf(s[j][3], c1, -mc1));
            l0 += e0 + e1;
            l1 += e2 + e3;
            p[j][0] = pk_h2(e0, e1);
            p[j][1] = pk_h2(e2, e3);
        }

        // ---- O += P @ V ----
        #pragma unroll
        for (int c = 0; c < 8; c++) {
            uint32_t a0 = p[2 * c][0], a1 = p[2 * c][1];
            uint32_t a2 = p[2 * c + 1][0], a3 = p[2 * c + 1][1];
            #pragma unroll
            for (int vp = 0; vp < 4; vp++) {
                uint32_t off = SWZ((c * 16 + laneRow) * 128 + vp * 32 + laneCol);
                uint32_t bv[4];
                ldsm4t(bv, VB + off);
                // trans ldsm: [0]=k-lo/d-lo [1]=k-hi/d-lo [2]=k-lo/d-hi [3]=k-hi/d-hi
                mma_f16(o[2 * vp],     a0, a1, a2, a3, bv[0], bv[1]);
                mma_f16(o[2 * vp + 1], a0, a1, a2, a3, bv[2], bv[3]);
            }
        }
    }

    // ---- epilogue ----
    l0 += __shfl_xor_sync(0xffffffffu, l0, 1);
    l0 += __shfl_xor_sync(0xffffffffu, l0, 2);
    l1 += __shfl_xor_sync(0xffffffffu, l1, 1);
    l1 += __shfl_xor_sync(0xffffffffu, l1, 2);
    const float inv0 = 1.f / l0, inv1 = 1.f / l1;
    const int b = bh >> 2, h = bh & 3;
    const int r0 = m0 + wid * 16 + (lane >> 2);
    const int cb = (lane & 3) * 2;
    #pragma unroll
    for (int vt = 0; vt < 8; vt++) {
        float* p0 = g_att + (size_t)(b * LL + r0) * CD + h * 64 + vt * 8 + cb;
        float* p1 = g_att + (size_t)(b * LL + r0 + 8) * CD + h * 64 + vt * 8 + cb;
        *(float2*)p0 = make_float2(o[vt][0] * inv0, o[vt][1] * inv0);
        *(float2*)p1 = make_float2(o[vt][2] * inv1, o[vt][3] * inv1);
    }
}

// ---------------------------------------------------------------------------
// Kernel 3: fc GEMM + bias + residual
// ---------------------------------------------------------------------------
__global__ __launch_bounds__(256) void k_fc(const float* __restrict__ fw,
                                            const float* __restrict__ fb) {
    __shared__ float At[64][68];
    __shared__ float Ws[64][68];
    const int r0 = blockIdx.x * 64;
    const int o0 = blockIdx.y * 64;
    const int tid = threadIdx.x;
    const int tx = tid & 15, ty = tid >> 4;

    float acc[4][4] = {};
    for (int k0 = 0; k0 < CD; k0 += 64) {
        __syncthreads();
        #pragma unroll
        for (int idx = tid; idx < 64 * 64; idx += 256) {
            int ri = idx >> 6, kj = idx & 63;
            At[kj][ri] = g_att[(r0 + ri) * CD + k0 + kj];
        }
        #pragma unroll
        for (int idx = tid; idx < 64 * 64; idx += 256) {
            int oi = idx >> 6, kj = idx & 63;
            Ws[kj][oi] = fw[(o0 + oi) * CD + k0 + kj];
        }
        __syncthreads();
        #pragma unroll 8
        for (int k = 0; k < 64; k++) {
            float4 a = *(const float4*)&At[k][ty * 4];
            float4 w = *(const float4*)&Ws[k][tx * 4];
            float av[4] = {a.x, a.y, a.z, a.w};
            float wv[4] = {w.x, w.y, w.z, w.w};
            #pragma unroll
            for (int i = 0; i < 4; i++)
                #pragma unroll
                for (int j = 0; j < 4; j++) acc[i][j] += av[i] * wv[j];
        }
    }
    #pragma unroll
    for (int i = 0; i < 4; i++) {
        int r = r0 + ty * 4 + i;
        float4 bias = *(const float4*)&fb[o0 + tx * 4];
        float4 res  = *(const float4*)&g_x[r * CD + o0 + tx * 4];
        float4 v = make_float4(acc[i][0] + bias.x + res.x,
                               acc[i][1] + bias.y + res.y,
                               acc[i][2] + bias.z + res.z,
                               acc[i][3] + bias.w + res.w);
        *(float4*)&g_y[r * CD + o0 + tx * 4] = v;
    }
}

// ---------------------------------------------------------------------------
// Kernel 4: LayerNorm over C=256
// ---------------------------------------------------------------------------
__global__ __launch_bounds__(256) void k_ln(const float* __restrict__ gam,
                                            const float* __restrict__ bet,
                                            float* __restrict__ out) {
    const int row = blockIdx.x * 8 + (threadIdx.x >> 5);
    const int lane = threadIdx.x & 31;
    const float* y = g_y + row * CD;
    float v[8], s = 0.f, s2 = 0.f;
    #pragma unroll
    for (int k = 0; k < 8; k++) {
        v[k] = y[lane + 32 * k];
        s += v[k];
        s2 += v[k] * v[k];
    }
    #pragma unroll
    for (int off = 16; off; off >>= 1) {
        s  += __shfl_xor_sync(0xffffffffu, s, off);
        s2 += __shfl_xor_sync(0xffffffffu, s2, off);
    }
    const float mu = s * (1.f / CD);
    const float rstd = rsqrtf(s2 * (1.f / CD) - mu * mu + 1e-5f);
    #pragma unroll
    for (int k = 0; k < 8; k++) {
        int c = lane + 32 * k;
        out[row * CD + c] = (v[k] - mu) * rstd * gam[c] + bet[c];
    }
}

// ---------------------------------------------------------------------------
extern "C" void kernel_launch(void* const* d_in, const int* in_sizes, int n_in,
                              void* d_out, int out_size) {
    const float* qin = (const float*)d_in[0];
    const float* wq  = (const float*)d_in[1];
    const float* fw  = (const float*)d_in[2];
    const float* fb  = (const float*)d_in[3];
    const float* lg  = (const float*)d_in[4];
    const float* lb  = (const float*)d_in[5];
    float* out = (float*)d_out;

    const int attn_smem = 49152;
    cudaFuncSetAttribute(k_attn_mma,
                         cudaFuncAttributeMaxDynamicSharedMemorySize, attn_smem);

    k_qkv<<<dim3(LL / 64, NH, NB), 256>>>(qin, wq);
    k_attn_mma<<<dim3(LL / 64, NB * NH), 128, attn_smem>>>();
    k_fc<<<dim3(NB * LL / 64, CD / 64), 256>>>(fw, fb);
    k_ln<<<NB * LL / 8, 256>>>(lg, lb, out);
}

// round 6
// speedup vs baseline: 4.1761x; 1.0974x over previous
#include <cuda_runtime.h>
#include <cuda_bf16.h>
#include <cuda_fp16.h>
#include <stdint.h>

#define NB 2
#define CD 256
#define LL 4096
#define NH 4
#define DKH 64

static constexpr float LOG2E = 1.4426950408889634f;

__device__ float g_x[NB * LL * CD];               // x transposed: [b][l][c]
__device__ float g_att[NB * LL * CD];             // attn out
__device__ float g_y[NB * LL * CD];               // fc+residual
__device__ __nv_bfloat16 g_kh[NB * NH * LL * DKH];  // q/k hi (bf16)
__device__ __nv_bfloat16 g_kl[NB * NH * LL * DKH];  // q/k lo (bf16)
__device__ __half        g_v [NB * NH * LL * DKH];  // v (fp16)

// ------------------------- helpers -------------------------
__device__ __forceinline__ uint32_t smem_u32(const void* p) {
    uint32_t a;
    asm("{ .reg .u64 t; cvta.to.shared.u64 t, %1; cvt.u32.u64 %0, t; }"
        : "=r"(a) : "l"(p));
    return a;
}
__device__ __forceinline__ uint32_t SWZ(uint32_t o) {
    return o ^ ((o >> 3) & 0x70);
}
__device__ __forceinline__ void ldsm4(uint32_t* r, uint32_t a) {
    asm volatile("ldmatrix.sync.aligned.m8n8.x4.shared.b16 {%0,%1,%2,%3}, [%4];"
                 : "=r"(r[0]), "=r"(r[1]), "=r"(r[2]), "=r"(r[3]) : "r"(a));
}
__device__ __forceinline__ void ldsm4t(uint32_t* r, uint32_t a) {
    asm volatile("ldmatrix.sync.aligned.m8n8.x4.trans.shared.b16 {%0,%1,%2,%3}, [%4];"
                 : "=r"(r[0]), "=r"(r[1]), "=r"(r[2]), "=r"(r[3]) : "r"(a));
}
__device__ __forceinline__ void mma_bf16(float* d, const uint32_t* a,
                                         uint32_t b0, uint32_t b1) {
    asm volatile(
        "mma.sync.aligned.m16n8k16.row.col.f32.bf16.bf16.f32 "
        "{%0,%1,%2,%3}, {%4,%5,%6,%7}, {%8,%9}, {%0,%1,%2,%3};"
        : "+f"(d[0]), "+f"(d[1]), "+f"(d[2]), "+f"(d[3])
        : "r"(a[0]), "r"(a[1]), "r"(a[2]), "r"(a[3]), "r"(b0), "r"(b1));
}
__device__ __forceinline__ void mma_f16(float* d, uint32_t a0, uint32_t a1,
                                        uint32_t a2, uint32_t a3,
                                        uint32_t b0, uint32_t b1) {
    asm volatile(
        "mma.sync.aligned.m16n8k16.row.col.f32.f16.f16.f32 "
        "{%0,%1,%2,%3}, {%4,%5,%6,%7}, {%8,%9}, {%0,%1,%2,%3};"
        : "+f"(d[0]), "+f"(d[1]), "+f"(d[2]), "+f"(d[3])
        : "r"(a0), "r"(a1), "r"(a2), "r"(a3), "r"(b0), "r"(b1));
}
__device__ __forceinline__ float ex2f(float x) {
    float y;
    asm("ex2.approx.ftz.f32 %0, %1;" : "=f"(y) : "f"(x));
    return y;
}
__device__ __forceinline__ uint32_t pk_bf(__nv_bfloat16 a, __nv_bfloat16 b) {
    __nv_bfloat162 v; v.x = a; v.y = b;
    return *(uint32_t*)&v;
}
__device__ __forceinline__ uint32_t pk_h2(float a, float b) {
    __half2 h = __floats2half2_rn(a, b);
    return *(uint32_t*)&h;
}
__device__ __forceinline__ void hilo(float x, __nv_bfloat16& h, __nv_bfloat16& l) {
    h = __float2bfloat16(x);
    l = __float2bfloat16(x - __bfloat162float(h));
}
__device__ __forceinline__ void cpa16(uint32_t s, const void* g) {
    asm volatile("cp.async.cg.shared.global [%0], [%1], 16;" :: "r"(s), "l"(g));
}
__device__ __forceinline__ void cpa_commit() {
    asm volatile("cp.async.commit_group;" ::: "memory");
}
template <int N>
__device__ __forceinline__ void cpa_wait() {
    asm volatile("cp.async.wait_group %0;" :: "n"(N) : "memory");
}

// ---------------------------------------------------------------------------
// Kernel 1: QKV projection + write transposed x + bf16 hi/lo + fp16 copies.
// ---------------------------------------------------------------------------
__global__ __launch_bounds__(256) void k_qkv(const float* __restrict__ qin,
                                             const float* __restrict__ wqkv) {
    __shared__ float As[64][68];
    __shared__ float Ws[64][68];
    const int bt = blockIdx.z;
    const int h = blockIdx.y;
    const int o0 = h * 64;
    const int l0 = blockIdx.x * 64;
    const int tid = threadIdx.x;
    const int tx = tid & 15, ty = tid >> 4;

    float acc[4][4] = {};
    for (int c0 = 0; c0 < CD; c0 += 64) {
        __syncthreads();
        #pragma unroll
        for (int idx = tid; idx < 64 * 64; idx += 256) {
            int ci = idx >> 6, lj = idx & 63;
            As[ci][lj] = qin[bt * CD * LL + (c0 + ci) * LL + l0 + lj];
        }
        #pragma unroll
        for (int idx = tid; idx < 64 * 64; idx += 256) {
            int oi = idx >> 6, cj = idx & 63;
            Ws[cj][oi] = wqkv[(o0 + oi) * CD + c0 + cj];
        }
        __syncthreads();
        if (h == 0) {
            #pragma unroll
            for (int idx = tid; idx < 64 * 64; idx += 256) {
                int li = idx >> 6, cj = idx & 63;
                g_x[(bt * LL + l0 + li) * CD + c0 + cj] = As[cj][li];
            }
        }
        #pragma unroll 8
        for (int c = 0; c < 64; c++) {
            float4 a = *(const float4*)&As[c][ty * 4];
            float4 w = *(const float4*)&Ws[c][tx * 4];
            float av[4] = {a.x, a.y, a.z, a.w};
            float wv[4] = {w.x, w.y, w.z, w.w};
            #pragma unroll
            for (int i = 0; i < 4; i++)
                #pragma unroll
                for (int j = 0; j < 4; j++) acc[i][j] += av[i] * wv[j];
        }
    }
    const int bh = bt * NH + h;
    #pragma unroll
    for (int i = 0; i < 4; i++) {
        size_t idx = (size_t)(bh * LL + l0 + ty * 4 + i) * DKH + tx * 4;
        __nv_bfloat16 h0, e0, h1, e1, h2, e2, h3, e3;
        hilo(acc[i][0], h0, e0); hilo(acc[i][1], h1, e1);
        hilo(acc[i][2], h2, e2); hilo(acc[i][3], h3, e3);
        *(uint2*)&g_kh[idx] = make_uint2(pk_bf(h0, h1), pk_bf(h2, h3));
        *(uint2*)&g_kl[idx] = make_uint2(pk_bf(e0, e1), pk_bf(e2, e3));
        *(uint2*)&g_v[idx]  = make_uint2(pk_h2(acc[i][0], acc[i][1]),
                                         pk_h2(acc[i][2], acc[i][3]));
    }
}

// ---------------------------------------------------------------------------
// Kernel 2: HMMA flash attention. 256 threads / 8 warps, 128 q-rows per CTA,
// key tiles of 128, cp.async double-buffered (2 x 48KB smem).
// ---------------------------------------------------------------------------
__device__ __forceinline__ void prefetch_tile(uint32_t khiB, uint32_t kloB,
                                              uint32_t vB, const char* gh,
                                              const char* gl, const char* gv,
                                              int tid) {
    #pragma unroll
    for (int i = 0; i < 4; i++) {
        int c = tid + i * 256;           // 1024 16B-chunks per array
        int n = c >> 3, c8 = c & 7;
        uint32_t go = n * 128 + c8 * 16;
        uint32_t so = SWZ(go);
        cpa16(khiB + so, gh + go);
        cpa16(kloB + so, gl + go);
        cpa16(vB + so, gv + go);
    }
}

__global__ __launch_bounds__(256) void k_attn_mma() {
    extern __shared__ char sm[];
    const uint32_t base = smem_u32(sm);

    const int tid = threadIdx.x;
    const int lane = tid & 31;
    const int wid = tid >> 5;
    const int bh = blockIdx.y;
    const int m0 = blockIdx.x * 128;

    const char* ghb = (const char*)(g_kh + (size_t)bh * LL * DKH);
    const char* glb = (const char*)(g_kl + (size_t)bh * LL * DKH);
    const char* gvb = (const char*)(g_v + (size_t)bh * LL * DKH);

    const uint32_t laneRow = lane & 15;
    const uint32_t laneCol = ((lane >> 4) & 1) * 16;  // bytes

    // buffers: buf b at base + b*49152; Khi +0, Klo +16K, V +32K
    const uint32_t B0 = base, B1 = base + 49152;

    // ---- stage Q (rows m0..m0+127, hi/lo) into buf1 Khi/Klo ----
    #pragma unroll
    for (int i = 0; i < 4; i++) {
        int c = tid + i * 256;
        int n = c >> 3, c8 = c & 7;
        uint32_t go = (m0 + n) * 128 + c8 * 16;
        uint32_t so = SWZ(n * 128 + c8 * 16);
        cpa16(B1 + so, ghb + go);
        cpa16(B1 + 16384 + so, glb + go);
    }
    cpa_commit();
    // ---- prefetch tile 0 into buf0 ----
    prefetch_tile(B0, B0 + 16384, B0 + 32768, ghb, glb, gvb, tid);
    cpa_commit();

    cpa_wait<1>();   // Q staged
    __syncthreads();

    // ---- Q fragments ----
    uint32_t qh[4][4], ql[4][4];
    {
        uint32_t rowb = (wid * 16 + laneRow) * 128;
        #pragma unroll
        for (int c = 0; c < 4; c++) {
            uint32_t off = SWZ(rowb + c * 32 + laneCol);
            ldsm4(qh[c], B1 + off);
            ldsm4(ql[c], B1 + 16384 + off);
        }
    }
    __syncthreads();  // Q regs loaded before buf1 reuse

    float o[8][4] = {};
    float mr0 = -1e30f, mr1 = -1e30f, l0 = 0.f, l1 = 0.f;
    const float c1 = LOG2E * 0.125f;

    const int NT = LL / 128;
    for (int t = 0; t < NT; t++) {
        const uint32_t BB = (t & 1) ? B1 : B0;
        const uint32_t KhiB = BB, KloB = BB + 16384, VB = BB + 32768;

        if (t + 1 < NT) {
            const uint32_t PB = ((t + 1) & 1) ? B1 : B0;
            size_t toff = (size_t)(t + 1) * 128 * 128;
            prefetch_tile(PB, PB + 16384, PB + 32768,
                          ghb + toff, glb + toff, gvb + toff, tid);
            cpa_commit();
            cpa_wait<1>();
        } else {
            cpa_wait<0>();
        }
        __syncthreads();

        // ---- S = Q K^T : 16 n-tiles of 8 ----
        float s[16][4];
        #pragma unroll
        for (int j = 0; j < 16; j++)
            #pragma unroll
            for (int k = 0; k < 4; k++) s[j][k] = 0.f;

        #pragma unroll
        for (int jp = 0; jp < 8; jp++) {
            #pragma unroll
            for (int c = 0; c < 4; c++) {
                uint32_t off = SWZ((jp * 16 + laneRow) * 128 + c * 32 + laneCol);
                uint32_t bhf[4], blf[4];
                ldsm4(bhf, KhiB + off);
                ldsm4(blf, KloB + off);
                mma_bf16(s[2 * jp],     qh[c], bhf[0], bhf[2]);
                mma_bf16(s[2 * jp],     ql[c], bhf[0], bhf[2]);
                mma_bf16(s[2 * jp],     qh[c], blf[0], blf[2]);
                mma_bf16(s[2 * jp + 1], qh[c], bhf[1], bhf[3]);
                mma_bf16(s[2 * jp + 1], ql[c], bhf[1], bhf[3]);
                mma_bf16(s[2 * jp + 1], qh[c], blf[1], blf[3]);
            }
        }

        // ---- online softmax ----
        float mt0 = -1e30f, mt1 = -1e30f;
        #pragma unroll
        for (int j = 0; j < 16; j++) {
            mt0 = fmaxf(mt0, fmaxf(s[j][0], s[j][1]));
            mt1 = fmaxf(mt1, fmaxf(s[j][2], s[j][3]));
        }
        mt0 = fmaxf(mt0, __shfl_xor_sync(0xffffffffu, mt0, 1));
        mt0 = fmaxf(mt0, __shfl_xor_sync(0xffffffffu, mt0, 2));
        mt1 = fmaxf(mt1, __shfl_xor_sync(0xffffffffu, mt1, 1));
        mt1 = fmaxf(mt1, __shfl_xor_sync(0xffffffffu, mt1, 2));
        float mn0 = fmaxf(mr0, mt0), mn1 = fmaxf(mr1, mt1);
        float cr0 = ex2f((mr0 - mn0) * c1), cr1 = ex2f((mr1 - mn1) * c1);
        mr0 = mn0; mr1 = mn1;
        l0 *= cr0; l1 *= cr1;
        #pragma unroll
        for (int vt = 0; vt < 8; vt++) {
            o[vt][0] *= cr0; o[vt][1] *= cr0;
            o[vt][2] *= cr1; o[vt][3] *= cr1;
        }
        const float mc0 = mn0 * c1, mc1 = mn1 * c1;
        uint32_t p[16][2];
        #pragma unroll
        for (int j = 0; j < 16; j++) {
            float e0 = ex2f(fmaf(s[j][0], c1, -mc0));
            float e1 = ex2f(fmaf(s[j][1], c1, -mc0));
            float e2 = ex2f(fmaf(s[j][2], c1, -mc1));
            float e3 = ex2f(fmaf(s[j][3], c1, -mc1));
            l0 += e0 + e1;
            l1 += e2 + e3;
            p[j][0] = pk_h2(e0, e1);
            p[j][1] = pk_h2(e2, e3);
        }

        // ---- O += P @ V ----
        #pragma unroll
        for (int c = 0; c < 8; c++) {
            uint32_t a0 = p[2 * c][0], a1 = p[2 * c][1];
            uint32_t a2 = p[2 * c + 1][0], a3 = p[2 * c + 1][1];
            #pragma unroll
            for (int vp = 0; vp < 4; vp++) {
                uint32_t off = SWZ((c * 16 + laneRow) * 128 + vp * 32 + laneCol);
                uint32_t bv[4];
                ldsm4t(bv, VB + off);
                mma_f16(o[2 * vp],     a0, a1, a2, a3, bv[0], bv[1]);
                mma_f16(o[2 * vp + 1], a0, a1, a2, a3, bv[2], bv[3]);
            }
        }
        __syncthreads();  // done reading BB before it is re-prefetched
    }

    // ---- epilogue ----
    l0 += __shfl_xor_sync(0xffffffffu, l0, 1);
    l0 += __shfl_xor_sync(0xffffffffu, l0, 2);
    l1 += __shfl_xor_sync(0xffffffffu, l1, 1);
    l1 += __shfl_xor_sync(0xffffffffu, l1, 2);
    const float inv0 = 1.f / l0, inv1 = 1.f / l1;
    const int b = bh >> 2, h = bh & 3;
    const int r0 = m0 + wid * 16 + (lane >> 2);
    const int cb = (lane & 3) * 2;
    #pragma unroll
    for (int vt = 0; vt < 8; vt++) {
        float* p0 = g_att + (size_t)(b * LL + r0) * CD + h * 64 + vt * 8 + cb;
        float* p1 = g_att + (size_t)(b * LL + r0 + 8) * CD + h * 64 + vt * 8 + cb;
        *(float2*)p0 = make_float2(o[vt][0] * inv0, o[vt][1] * inv0);
        *(float2*)p1 = make_float2(o[vt][2] * inv1, o[vt][3] * inv1);
    }
}

// ---------------------------------------------------------------------------
// Kernel 3: fc GEMM + bias + residual
// ---------------------------------------------------------------------------
__global__ __launch_bounds__(256) void k_fc(const float* __restrict__ fw,
                                            const float* __restrict__ fb) {
    __shared__ float At[64][68];
    __shared__ float Ws[64][68];
    const int r0 = blockIdx.x * 64;
    const int o0 = blockIdx.y * 64;
    const int tid = threadIdx.x;
    const int tx = tid & 15, ty = tid >> 4;

    float acc[4][4] = {};
    for (int k0 = 0; k0 < CD; k0 += 64) {
        __syncthreads();
        #pragma unroll
        for (int idx = tid; idx < 64 * 64; idx += 256) {
            int ri = idx >> 6, kj = idx & 63;
            At[kj][ri] = g_att[(r0 + ri) * CD + k0 + kj];
        }
        #pragma unroll
        for (int idx = tid; idx < 64 * 64; idx += 256) {
            int oi = idx >> 6, kj = idx & 63;
            Ws[kj][oi] = fw[(o0 + oi) * CD + k0 + kj];
        }
        __syncthreads();
        #pragma unroll 8
        for (int k = 0; k < 64; k++) {
            float4 a = *(const float4*)&At[k][ty * 4];
            float4 w = *(const float4*)&Ws[k][tx * 4];
            float av[4] = {a.x, a.y, a.z, a.w};
            float wv[4] = {w.x, w.y, w.z, w.w};
            #pragma unroll
            for (int i = 0; i < 4; i++)
                #pragma unroll
                for (int j = 0; j < 4; j++) acc[i][j] += av[i] * wv[j];
        }
    }
    #pragma unroll
    for (int i = 0; i < 4; i++) {
        int r = r0 + ty * 4 + i;
        float4 bias = *(const float4*)&fb[o0 + tx * 4];
        float4 res  = *(const float4*)&g_x[r * CD + o0 + tx * 4];
        float4 v = make_float4(acc[i][0] + bias.x + res.x,
                               acc[i][1] + bias.y + res.y,
                               acc[i][2] + bias.z + res.z,
                               acc[i][3] + bias.w + res.w);
        *(float4*)&g_y[r * CD + o0 + tx * 4] = v;
    }
}

// ---------------------------------------------------------------------------
// Kernel 4: LayerNorm over C=256
// ---------------------------------------------------------------------------
__global__ __launch_bounds__(256) void k_ln(const float* __restrict__ gam,
                                            const float* __restrict__ bet,
                                            float* __restrict__ out) {
    const int row = blockIdx.x * 8 + (threadIdx.x >> 5);
    const int lane = threadIdx.x & 31;
    const float* y = g_y + row * CD;
    float v[8], s = 0.f, s2 = 0.f;
    #pragma unroll
    for (int k = 0; k < 8; k++) {
        v[k] = y[lane + 32 * k];
        s += v[k];
        s2 += v[k] * v[k];
    }
    #pragma unroll
    for (int off = 16; off; off >>= 1) {
        s  += __shfl_xor_sync(0xffffffffu, s, off);
        s2 += __shfl_xor_sync(0xffffffffu, s2, off);
    }
    const float mu = s * (1.f / CD);
    const float rstd = rsqrtf(s2 * (1.f / CD) - mu * mu + 1e-5f);
    #pragma unroll
    for (int k = 0; k < 8; k++) {
        int c = lane + 32 * k;
        out[row * CD + c] = (v[k] - mu) * rstd * gam[c] + bet[c];
    }
}

// ---------------------------------------------------------------------------
extern "C" void kernel_launch(void* const* d_in, const int* in_sizes, int n_in,
                              void* d_out, int out_size) {
    const float* qin = (const float*)d_in[0];
    const float* wq  = (const float*)d_in[1];
    const float* fw  = (const float*)d_in[2];
    const float* fb  = (const float*)d_in[3];
    const float* lg  = (const float*)d_in[4];
    const float* lb  = (const float*)d_in[5];
    float* out = (float*)d_out;

    const int attn_smem = 98304;  // 2 x 48KB
    cudaFuncSetAttribute(k_attn_mma,
                         cudaFuncAttributeMaxDynamicSharedMemorySize, attn_smem);

    k_qkv<<<dim3(LL / 64, NH, NB), 256>>>(qin, wq);
    k_attn_mma<<<dim3(LL / 128, NB * NH), 256, attn_smem>>>();
    k_fc<<<dim3(NB * LL / 64, CD / 64), 256>>>(fw, fb);
    k_ln<<<NB * LL / 8, 256>>>(lg, lb, out);
}

// round 7
// speedup vs baseline: 5.8456x; 1.3998x over previous
#include <cuda_runtime.h>
#include <cuda_bf16.h>
#include <cuda_fp16.h>
#include <stdint.h>

#define NB 2
#define CD 256
#define LL 4096
#define NH 4
#define DKH 64

static constexpr float LOG2E = 1.4426950408889634f;

__device__ float g_x[NB * LL * CD];                // x transposed: [b][l][c]
__device__ float g_att[NB * LL * CD];              // attn out
__device__ float g_y[NB * LL * CD];                // fc+residual
__device__ __half g_v[NB * NH * LL * DKH];         // q/k/v heads (fp16)

// ------------------------- helpers -------------------------
__device__ __forceinline__ uint32_t smem_u32(const void* p) {
    uint32_t a;
    asm("{ .reg .u64 t; cvta.to.shared.u64 t, %1; cvt.u32.u64 %0, t; }"
        : "=r"(a) : "l"(p));
    return a;
}
__device__ __forceinline__ uint32_t SWZ(uint32_t o) {
    return o ^ ((o >> 3) & 0x70);
}
__device__ __forceinline__ void ldsm4(uint32_t* r, uint32_t a) {
    asm volatile("ldmatrix.sync.aligned.m8n8.x4.shared.b16 {%0,%1,%2,%3}, [%4];"
                 : "=r"(r[0]), "=r"(r[1]), "=r"(r[2]), "=r"(r[3]) : "r"(a));
}
__device__ __forceinline__ void ldsm4t(uint32_t* r, uint32_t a) {
    asm volatile("ldmatrix.sync.aligned.m8n8.x4.trans.shared.b16 {%0,%1,%2,%3}, [%4];"
                 : "=r"(r[0]), "=r"(r[1]), "=r"(r[2]), "=r"(r[3]) : "r"(a));
}
__device__ __forceinline__ void mma_f16(float* d, const uint32_t* a,
                                        uint32_t b0, uint32_t b1) {
    asm volatile(
        "mma.sync.aligned.m16n8k16.row.col.f32.f16.f16.f32 "
        "{%0,%1,%2,%3}, {%4,%5,%6,%7}, {%8,%9}, {%0,%1,%2,%3};"
        : "+f"(d[0]), "+f"(d[1]), "+f"(d[2]), "+f"(d[3])
        : "r"(a[0]), "r"(a[1]), "r"(a[2]), "r"(a[3]), "r"(b0), "r"(b1));
}
__device__ __forceinline__ void mma_f16s(float* d, uint32_t a0, uint32_t a1,
                                         uint32_t a2, uint32_t a3,
                                         uint32_t b0, uint32_t b1) {
    asm volatile(
        "mma.sync.aligned.m16n8k16.row.col.f32.f16.f16.f32 "
        "{%0,%1,%2,%3}, {%4,%5,%6,%7}, {%8,%9}, {%0,%1,%2,%3};"
        : "+f"(d[0]), "+f"(d[1]), "+f"(d[2]), "+f"(d[3])
        : "r"(a0), "r"(a1), "r"(a2), "r"(a3), "r"(b0), "r"(b1));
}
__device__ __forceinline__ float ex2f(float x) {
    float y;
    asm("ex2.approx.ftz.f32 %0, %1;" : "=f"(y) : "f"(x));
    return y;
}
__device__ __forceinline__ uint32_t pk_h2(float a, float b) {
    __half2 h = __floats2half2_rn(a, b);
    return *(uint32_t*)&h;
}
__device__ __forceinline__ void cpa16(uint32_t s, const void* g) {
    asm volatile("cp.async.cg.shared.global [%0], [%1], 16;" :: "r"(s), "l"(g));
}
__device__ __forceinline__ void cpa_commit() {
    asm volatile("cp.async.commit_group;" ::: "memory");
}
template <int N>
__device__ __forceinline__ void cpa_wait() {
    asm volatile("cp.async.wait_group %0;" :: "n"(N) : "memory");
}

// ---------------------------------------------------------------------------
// Kernel 1: QKV projection + write transposed x + fp16 head copy.
// ---------------------------------------------------------------------------
__global__ __launch_bounds__(256) void k_qkv(const float* __restrict__ qin,
                                             const float* __restrict__ wqkv) {
    __shared__ float As[64][68];
    __shared__ float Ws[64][68];
    const int bt = blockIdx.z;
    const int h = blockIdx.y;
    const int o0 = h * 64;
    const int l0 = blockIdx.x * 64;
    const int tid = threadIdx.x;
    const int tx = tid & 15, ty = tid >> 4;

    float acc[4][4] = {};
    for (int c0 = 0; c0 < CD; c0 += 64) {
        __syncthreads();
        #pragma unroll
        for (int idx = tid; idx < 64 * 64; idx += 256) {
            int ci = idx >> 6, lj = idx & 63;
            As[ci][lj] = qin[bt * CD * LL + (c0 + ci) * LL + l0 + lj];
        }
        #pragma unroll
        for (int idx = tid; idx < 64 * 64; idx += 256) {
            int oi = idx >> 6, cj = idx & 63;
            Ws[cj][oi] = wqkv[(o0 + oi) * CD + c0 + cj];
        }
        __syncthreads();
        if (h == 0) {
            #pragma unroll
            for (int idx = tid; idx < 64 * 64; idx += 256) {
                int li = idx >> 6, cj = idx & 63;
                g_x[(bt * LL + l0 + li) * CD + c0 + cj] = As[cj][li];
            }
        }
        #pragma unroll 8
        for (int c = 0; c < 64; c++) {
            float4 a = *(const float4*)&As[c][ty * 4];
            float4 w = *(const float4*)&Ws[c][tx * 4];
            float av[4] = {a.x, a.y, a.z, a.w};
            float wv[4] = {w.x, w.y, w.z, w.w};
            #pragma unroll
            for (int i = 0; i < 4; i++)
                #pragma unroll
                for (int j = 0; j < 4; j++) acc[i][j] += av[i] * wv[j];
        }
    }
    const int bh = bt * NH + h;
    #pragma unroll
    for (int i = 0; i < 4; i++) {
        size_t idx = (size_t)(bh * LL + l0 + ty * 4 + i) * DKH + tx * 4;
        *(uint2*)&g_v[idx] = make_uint2(pk_h2(acc[i][0], acc[i][1]),
                                        pk_h2(acc[i][2], acc[i][3]));
    }
}

// ---------------------------------------------------------------------------
// Kernel 2: HMMA flash attention. 256 threads / 8 warps, 128 q-rows per CTA,
// key tiles of 128. One fp16 K/V buffer per tile (K and V are the same data);
// 3-stage cp.async ring (3 x 16KB) + 16KB Q staging = 64KB smem.
// ---------------------------------------------------------------------------
__device__ __forceinline__ void prefetch_kv(uint32_t buf, const char* g, int tid) {
    #pragma unroll
    for (int i = 0; i < 4; i++) {
        int c = tid + i * 256;         // 1024 16B-chunks
        int n = c >> 3, c8 = c & 7;
        uint32_t go = n * 128 + c8 * 16;
        cpa16(buf + SWZ(go), g + go);
    }
}

__global__ __launch_bounds__(256) void k_attn_mma() {
    extern __shared__ char sm[];
    const uint32_t base = smem_u32(sm);

    const int tid = threadIdx.x;
    const int lane = tid & 31;
    const int wid = tid >> 5;
    const int bh = blockIdx.y;
    const int m0 = blockIdx.x * 128;

    const char* gvb = (const char*)(g_v + (size_t)bh * LL * DKH);

    const uint32_t laneRow = lane & 15;
    const uint32_t laneCol = ((lane >> 4) & 1) * 16;  // bytes

    const uint32_t Qb = base + 3 * 16384;

    // ---- stage Q (rows m0..m0+127, fp16) ----
    #pragma unroll
    for (int i = 0; i < 4; i++) {
        int c = tid + i * 256;
        int n = c >> 3, c8 = c & 7;
        cpa16(Qb + SWZ(n * 128 + c8 * 16), gvb + (m0 + n) * 128 + c8 * 16);
    }
    cpa_commit();
    // ---- prefetch tiles 0 and 1 ----
    prefetch_kv(base, gvb, tid);
    cpa_commit();
    prefetch_kv(base + 16384, gvb + 16384, tid);
    cpa_commit();

    cpa_wait<2>();  // Q staged
    __syncthreads();

    // ---- Q fragments (fp16) ----
    uint32_t qh[4][4];
    {
        uint32_t rowb = (wid * 16 + laneRow) * 128;
        #pragma unroll
        for (int c = 0; c < 4; c++)
            ldsm4(qh[c], Qb + SWZ(rowb + c * 32 + laneCol));
    }

    float o[8][4] = {};
    float mr0 = -1e30f, mr1 = -1e30f, l0 = 0.f, l1 = 0.f;
    const float c1 = LOG2E * 0.125f;

    const int NT = LL / 128;
    for (int t = 0; t < NT; t++) {
        const uint32_t KVb = base + (uint32_t)(t % 3) * 16384;

        if (t + 1 < NT) cpa_wait<1>(); else cpa_wait<0>();
        __syncthreads();
        if (t + 2 < NT) {
            prefetch_kv(base + (uint32_t)((t + 2) % 3) * 16384,
                        gvb + (size_t)(t + 2) * 16384, tid);
            cpa_commit();
        }

        // ---- S = Q K^T : single fp16 MMA per fragment ----
        float s[16][4];
        #pragma unroll
        for (int j = 0; j < 16; j++)
            #pragma unroll
            for (int k = 0; k < 4; k++) s[j][k] = 0.f;

        #pragma unroll
        for (int jp = 0; jp < 8; jp++) {
            #pragma unroll
            for (int c = 0; c < 4; c++) {
                uint32_t off = SWZ((jp * 16 + laneRow) * 128 + c * 32 + laneCol);
                uint32_t bv[4];
                ldsm4(bv, KVb + off);
                // [0]=n-lo/k-lo [1]=n-hi/k-lo [2]=n-lo/k-hi [3]=n-hi/k-hi
                mma_f16(s[2 * jp],     qh[c], bv[0], bv[2]);
                mma_f16(s[2 * jp + 1], qh[c], bv[1], bv[3]);
            }
        }

        // ---- online softmax ----
        float mt0 = -1e30f, mt1 = -1e30f;
        #pragma unroll
        for (int j = 0; j < 16; j++) {
            mt0 = fmaxf(mt0, fmaxf(s[j][0], s[j][1]));
            mt1 = fmaxf(mt1, fmaxf(s[j][2], s[j][3]));
        }
        mt0 = fmaxf(mt0, __shfl_xor_sync(0xffffffffu, mt0, 1));
        mt0 = fmaxf(mt0, __shfl_xor_sync(0xffffffffu, mt0, 2));
        mt1 = fmaxf(mt1, __shfl_xor_sync(0xffffffffu, mt1, 1));
        mt1 = fmaxf(mt1, __shfl_xor_sync(0xffffffffu, mt1, 2));
        float mn0 = fmaxf(mr0, mt0), mn1 = fmaxf(mr1, mt1);
        float cr0 = ex2f((mr0 - mn0) * c1), cr1 = ex2f((mr1 - mn1) * c1);
        mr0 = mn0; mr1 = mn1;
        l0 *= cr0; l1 *= cr1;
        #pragma unroll
        for (int vt = 0; vt < 8; vt++) {
            o[vt][0] *= cr0; o[vt][1] *= cr0;
            o[vt][2] *= cr1; o[vt][3] *= cr1;
        }
        const float mc0 = mn0 * c1, mc1 = mn1 * c1;
        uint32_t p[16][2];
        #pragma unroll
        for (int j = 0; j < 16; j++) {
            float e0 = ex2f(fmaf(s[j][0], c1, -mc0));
            float e1 = ex2f(fmaf(s[j][1], c1, -mc0));
            float e2 = ex2f(fmaf(s[j][2], c1, -mc1));
            float e3 = ex2f(fmaf(s[j][3], c1, -mc1));
            l0 += e0 + e1;
            l1 += e2 + e3;
            p[j][0] = pk_h2(e0, e1);
            p[j][1] = pk_h2(e2, e3);
        }

        // ---- O += P @ V (V = same buffer, trans load) ----
        #pragma unroll
        for (int c = 0; c < 8; c++) {
            uint32_t a0 = p[2 * c][0], a1 = p[2 * c][1];
            uint32_t a2 = p[2 * c + 1][0], a3 = p[2 * c + 1][1];
            #pragma unroll
            for (int vp = 0; vp < 4; vp++) {
                uint32_t off = SWZ((c * 16 + laneRow) * 128 + vp * 32 + laneCol);
                uint32_t bv[4];
                ldsm4t(bv, KVb + off);
                mma_f16s(o[2 * vp],     a0, a1, a2, a3, bv[0], bv[1]);
                mma_f16s(o[2 * vp + 1], a0, a1, a2, a3, bv[2], bv[3]);
            }
        }
        __syncthreads();  // finished reading KVb before ring reuse
    }

    // ---- epilogue ----
    l0 += __shfl_xor_sync(0xffffffffu, l0, 1);
    l0 += __shfl_xor_sync(0xffffffffu, l0, 2);
    l1 += __shfl_xor_sync(0xffffffffu, l1, 1);
    l1 += __shfl_xor_sync(0xffffffffu, l1, 2);
    const float inv0 = 1.f / l0, inv1 = 1.f / l1;
    const int b = bh >> 2, h = bh & 3;
    const int r0 = m0 + wid * 16 + (lane >> 2);
    const int cb = (lane & 3) * 2;
    #pragma unroll
    for (int vt = 0; vt < 8; vt++) {
        float* p0 = g_att + (size_t)(b * LL + r0) * CD + h * 64 + vt * 8 + cb;
        float* p1 = g_att + (size_t)(b * LL + r0 + 8) * CD + h * 64 + vt * 8 + cb;
        *(float2*)p0 = make_float2(o[vt][0] * inv0, o[vt][1] * inv0);
        *(float2*)p1 = make_float2(o[vt][2] * inv1, o[vt][3] * inv1);
    }
}

// ---------------------------------------------------------------------------
// Kernel 3: fc GEMM + bias + residual
// ---------------------------------------------------------------------------
__global__ __launch_bounds__(256) void k_fc(const float* __restrict__ fw,
                                            const float* __restrict__ fb) {
    __shared__ float At[64][68];
    __shared__ float Ws[64][68];
    const int r0 = blockIdx.x * 64;
    const int o0 = blockIdx.y * 64;
    const int tid = threadIdx.x;
    const int tx = tid & 15, ty = tid >> 4;

    float acc[4][4] = {};
    for (int k0 = 0; k0 < CD; k0 += 64) {
        __syncthreads();
        #pragma unroll
        for (int idx = tid; idx < 64 * 64; idx += 256) {
            int ri = idx >> 6, kj = idx & 63;
            At[kj][ri] = g_att[(r0 + ri) * CD + k0 + kj];
        }
        #pragma unroll
        for (int idx = tid; idx < 64 * 64; idx += 256) {
            int oi = idx >> 6, kj = idx & 63;
            Ws[kj][oi] = fw[(o0 + oi) * CD + k0 + kj];
        }
        __syncthreads();
        #pragma unroll 8
        for (int k = 0; k < 64; k++) {
            float4 a = *(const float4*)&At[k][ty * 4];
            float4 w = *(const float4*)&Ws[k][tx * 4];
            float av[4] = {a.x, a.y, a.z, a.w};
            float wv[4] = {w.x, w.y, w.z, w.w};
            #pragma unroll
            for (int i = 0; i < 4; i++)
                #pragma unroll
                for (int j = 0; j < 4; j++) acc[i][j] += av[i] * wv[j];
        }
    }
    #pragma unroll
    for (int i = 0; i < 4; i++) {
        int r = r0 + ty * 4 + i;
        float4 bias = *(const float4*)&fb[o0 + tx * 4];
        float4 res  = *(const float4*)&g_x[r * CD + o0 + tx * 4];
        float4 v = make_float4(acc[i][0] + bias.x + res.x,
                               acc[i][1] + bias.y + res.y,
                               acc[i][2] + bias.z + res.z,
                               acc[i][3] + bias.w + res.w);
        *(float4*)&g_y[r * CD + o0 + tx * 4] = v;
    }
}

// ---------------------------------------------------------------------------
// Kernel 4: LayerNorm over C=256
// ---------------------------------------------------------------------------
__global__ __launch_bounds__(256) void k_ln(const float* __restrict__ gam,
                                            const float* __restrict__ bet,
                                            float* __restrict__ out) {
    const int row = blockIdx.x * 8 + (threadIdx.x >> 5);
    const int lane = threadIdx.x & 31;
    const float* y = g_y + row * CD;
    float v[8], s = 0.f, s2 = 0.f;
    #pragma unroll
    for (int k = 0; k < 8; k++) {
        v[k] = y[lane + 32 * k];
        s += v[k];
        s2 += v[k] * v[k];
    }
    #pragma unroll
    for (int off = 16; off; off >>= 1) {
        s  += __shfl_xor_sync(0xffffffffu, s, off);
        s2 += __shfl_xor_sync(0xffffffffu, s2, off);
    }
    const float mu = s * (1.f / CD);
    const float rstd = rsqrtf(s2 * (1.f / CD) - mu * mu + 1e-5f);
    #pragma unroll
    for (int k = 0; k < 8; k++) {
        int c = lane + 32 * k;
        out[row * CD + c] = (v[k] - mu) * rstd * gam[c] + bet[c];
    }
}

// ---------------------------------------------------------------------------
extern "C" void kernel_launch(void* const* d_in, const int* in_sizes, int n_in,
                              void* d_out, int out_size) {
    const float* qin = (const float*)d_in[0];
    const float* wq  = (const float*)d_in[1];
    const float* fw  = (const float*)d_in[2];
    const float* fb  = (const float*)d_in[3];
    const float* lg  = (const float*)d_in[4];
    const float* lb  = (const float*)d_in[5];
    float* out = (float*)d_out;

    const int attn_smem = 65536;  // 3 x 16KB ring + 16KB Q
    cudaFuncSetAttribute(k_attn_mma,
                         cudaFuncAttributeMaxDynamicSharedMemorySize, attn_smem);

    k_qkv<<<dim3(LL / 64, NH, NB), 256>>>(qin, wq);
    k_attn_mma<<<dim3(LL / 128, NB * NH), 256, attn_smem>>>();
    k_fc<<<dim3(NB * LL / 64, CD / 64), 256>>>(fw, fb);
    k_ln<<<NB * LL / 8, 256>>>(lg, lb, out);
}

// round 8
// speedup vs baseline: 7.8284x; 1.3392x over previous
#include <cuda_runtime.h>
#include <cuda_fp16.h>
#include <stdint.h>

#define NB 2
#define CD 256
#define LL 4096
#define NH 4
#define DKH 64

static constexpr float LOG2E = 1.4426950408889634f;

__device__ float  g_x  [NB * LL * CD];        // residual: [b][l][c] fp32
__device__ __half g_xh [NB * LL * CD];        // x hi (fp16)
__device__ __half g_xl [NB * LL * CD];        // x lo (fp16)
__device__ __half g_v  [NB * NH * LL * DKH];  // q/k/v heads (fp16)
__device__ __half g_ath[NB * LL * CD];        // attn out hi
__device__ __half g_atl[NB * LL * CD];        // attn out lo
__device__ float  g_y  [NB * LL * CD];        // fc+residual

// ------------------------- helpers -------------------------
__device__ __forceinline__ uint32_t smem_u32(const void* p) {
    uint32_t a;
    asm("{ .reg .u64 t; cvta.to.shared.u64 t, %1; cvt.u32.u64 %0, t; }"
        : "=r"(a) : "l"(p));
    return a;
}
__device__ __forceinline__ uint32_t SWZ(uint32_t o) {
    return o ^ ((o >> 3) & 0x70);
}
__device__ __forceinline__ void ldsm4(uint32_t* r, uint32_t a) {
    asm volatile("ldmatrix.sync.aligned.m8n8.x4.shared.b16 {%0,%1,%2,%3}, [%4];"
                 : "=r"(r[0]), "=r"(r[1]), "=r"(r[2]), "=r"(r[3]) : "r"(a));
}
__device__ __forceinline__ void ldsm4t(uint32_t* r, uint32_t a) {
    asm volatile("ldmatrix.sync.aligned.m8n8.x4.trans.shared.b16 {%0,%1,%2,%3}, [%4];"
                 : "=r"(r[0]), "=r"(r[1]), "=r"(r[2]), "=r"(r[3]) : "r"(a));
}
__device__ __forceinline__ void mma_f16(float* d, const uint32_t* a,
                                        uint32_t b0, uint32_t b1) {
    asm volatile(
        "mma.sync.aligned.m16n8k16.row.col.f32.f16.f16.f32 "
        "{%0,%1,%2,%3}, {%4,%5,%6,%7}, {%8,%9}, {%0,%1,%2,%3};"
        : "+f"(d[0]), "+f"(d[1]), "+f"(d[2]), "+f"(d[3])
        : "r"(a[0]), "r"(a[1]), "r"(a[2]), "r"(a[3]), "r"(b0), "r"(b1));
}
__device__ __forceinline__ void mma_f16s(float* d, uint32_t a0, uint32_t a1,
                                         uint32_t a2, uint32_t a3,
                                         uint32_t b0, uint32_t b1) {
    asm volatile(
        "mma.sync.aligned.m16n8k16.row.col.f32.f16.f16.f32 "
        "{%0,%1,%2,%3}, {%4,%5,%6,%7}, {%8,%9}, {%0,%1,%2,%3};"
        : "+f"(d[0]), "+f"(d[1]), "+f"(d[2]), "+f"(d[3])
        : "r"(a0), "r"(a1), "r"(a2), "r"(a3), "r"(b0), "r"(b1));
}
__device__ __forceinline__ float ex2f(float x) {
    float y;
    asm("ex2.approx.ftz.f32 %0, %1;" : "=f"(y) : "f"(x));
    return y;
}
__device__ __forceinline__ uint32_t pk_h2(float a, float b) {
    __half2 h = __floats2half2_rn(a, b);
    return *(uint32_t*)&h;
}
__device__ __forceinline__ void cpa16(uint32_t s, const void* g) {
    asm volatile("cp.async.cg.shared.global [%0], [%1], 16;" :: "r"(s), "l"(g));
}
__device__ __forceinline__ void cpa_commit() {
    asm volatile("cp.async.commit_group;" ::: "memory");
}
template <int N>
__device__ __forceinline__ void cpa_wait() {
    asm volatile("cp.async.wait_group %0;" :: "n"(N) : "memory");
}

// ---------------------------------------------------------------------------
// Kernel 0: transpose input -> g_x (fp32) + g_xh/g_xl (fp16 hi/lo)
// ---------------------------------------------------------------------------
__global__ __launch_bounds__(256) void k_prep(const float* __restrict__ qin) {
    __shared__ float T[64][65];
    const int bt = blockIdx.z, c0 = blockIdx.y * 64, l0 = blockIdx.x * 64;
    const int tid = threadIdx.x;
    #pragma unroll
    for (int i = 0; i < 16; i++) {
        int idx = tid + i * 256;
        int ci = idx >> 6, lj = idx & 63;
        T[ci][lj] = qin[(size_t)bt * CD * LL + (size_t)(c0 + ci) * LL + l0 + lj];
    }
    __syncthreads();
    #pragma unroll
    for (int i = 0; i < 16; i++) {
        int idx = tid + i * 256;
        int li = idx >> 6, cj = idx & 63;
        float v = T[cj][li];
        size_t o = (size_t)(bt * LL + l0 + li) * CD + c0 + cj;
        g_x[o] = v;
        __half h = __float2half_rn(v);
        g_xh[o] = h;
        g_xl[o] = __float2half_rn(v - __half2float(h));
    }
}

// ---------------------------------------------------------------------------
// GEMM mainloop (shared by qkv/fc): M=256 x N=64 x K=256, fp16 hi/lo 3-MMA.
// 8 warps x m32. 2-stage smem: per stage Ahi 32K | Alo 32K | Bhi 8K | Blo 8K.
// ---------------------------------------------------------------------------
#define GEMM_MAIN(gah, gal, Bw, acc)                                           \
    {                                                                          \
        const uint32_t laneRow = lane & 15;                                    \
        const uint32_t laneCol = ((lane >> 4) & 1) * 16;                       \
        auto prefA = [&](int kc) {                                             \
            uint32_t st = base + (uint32_t)(kc & 1) * 81920u;                  \
            _Pragma("unroll")                                                  \
            for (int i = 0; i < 8; i++) {                                      \
                int idx = tid + i * 256;                                       \
                int r = idx >> 3, c8 = idx & 7;                                \
                uint32_t so = SWZ(r * 128 + c8 * 16);                          \
                size_t go = (size_t)r * CD * 2 + kc * 128 + c8 * 16;           \
                cpa16(st + so, gah + go);                                      \
                cpa16(st + 32768 + so, gal + go);                              \
            }                                                                  \
        };                                                                     \
        auto loadB = [&](int kc) {                                             \
            char* sp = smg + (kc & 1) * 81920;                                 \
            _Pragma("unroll")                                                  \
            for (int i = 0; i < 4; i++) {                                      \
                int idx = tid + i * 256;                                       \
                int r = idx >> 4, q = idx & 15;                                \
                float4 v = *(const float4*)(Bw + (size_t)r * CD + kc * 64 + q * 4); \
                __half h0 = __float2half_rn(v.x), h1 = __float2half_rn(v.y);   \
                __half h2 = __float2half_rn(v.z), h3 = __float2half_rn(v.w);   \
                __half e0 = __float2half_rn(v.x - __half2float(h0));           \
                __half e1 = __float2half_rn(v.y - __half2float(h1));           \
                __half e2 = __float2half_rn(v.z - __half2float(h2));           \
                __half e3 = __float2half_rn(v.w - __half2float(h3));           \
                uint32_t so = SWZ(r * 128 + q * 8);                            \
                __half2 hh0; hh0.x = h0; hh0.y = h1;                           \
                __half2 hh1; hh1.x = h2; hh1.y = h3;                           \
                __half2 le0; le0.x = e0; le0.y = e1;                           \
                __half2 le1; le1.x = e2; le1.y = e3;                           \
                *(uint2*)(sp + 65536 + so) =                                   \
                    make_uint2(*(uint32_t*)&hh0, *(uint32_t*)&hh1);            \
                *(uint2*)(sp + 73728 + so) =                                   \
                    make_uint2(*(uint32_t*)&le0, *(uint32_t*)&le1);            \
            }                                                                  \
        };                                                                     \
        prefA(0); loadB(0); cpa_commit();                                      \
        for (int kc = 0; kc < 4; kc++) {                                       \
            cpa_wait<0>();                                                     \
            __syncthreads();                                                   \
            if (kc < 3) { prefA(kc + 1); loadB(kc + 1); cpa_commit(); }        \
            uint32_t sb = base + (uint32_t)(kc & 1) * 81920u;                  \
            uint32_t Ahi = sb, Alo = sb + 32768, Bhi = sb + 65536,             \
                     Blo = sb + 73728;                                         \
            _Pragma("unroll")                                                  \
            for (int s = 0; s < 4; s++) {                                      \
                uint32_t ah[2][4], al[2][4];                                   \
                _Pragma("unroll")                                              \
                for (int mi = 0; mi < 2; mi++) {                               \
                    uint32_t off = SWZ((wid * 32 + mi * 16 + laneRow) * 128 +  \
                                       s * 32 + laneCol);                      \
                    ldsm4(ah[mi], Ahi + off);                                  \
                    ldsm4(al[mi], Alo + off);                                  \
                }                                                              \
                _Pragma("unroll")                                              \
                for (int nf = 0; nf < 4; nf++) {                               \
                    uint32_t off = SWZ((nf * 16 + laneRow) * 128 + s * 32 +    \
                                       laneCol);                               \
                    uint32_t b4[4], c4[4];                                     \
                    ldsm4(b4, Bhi + off);                                      \
                    ldsm4(c4, Blo + off);                                      \
                    _Pragma("unroll")                                          \
                    for (int mi = 0; mi < 2; mi++) {                           \
                        mma_f16(acc[mi][2 * nf], ah[mi], b4[0], b4[2]);        \
                        mma_f16(acc[mi][2 * nf], al[mi], b4[0], b4[2]);        \
                        mma_f16(acc[mi][2 * nf], ah[mi], c4[0], c4[2]);        \
                        mma_f16(acc[mi][2 * nf + 1], ah[mi], b4[1], b4[3]);    \
                        mma_f16(acc[mi][2 * nf + 1], al[mi], b4[1], b4[3]);    \
                        mma_f16(acc[mi][2 * nf + 1], ah[mi], c4[1], c4[3]);    \
                    }                                                          \
                }                                                              \
            }                                                                  \
        }                                                                      \
    }

// ---------------------------------------------------------------------------
// Kernel 1: QKV projection (HMMA) -> g_v fp16
// ---------------------------------------------------------------------------
__global__ __launch_bounds__(256) void k_qkv_mma(const float* __restrict__ wqkv) {
    extern __shared__ char smg[];
    const uint32_t base = smem_u32(smg);
    const int tid = threadIdx.x, lane = tid & 31, wid = tid >> 5;
    const int m0 = blockIdx.x * 256;
    const int h = blockIdx.y, bt = blockIdx.z, bh = bt * NH + h;
    const char* gah = (const char*)(g_xh + (size_t)(bt * LL + m0) * CD);
    const char* gal = (const char*)(g_xl + (size_t)(bt * LL + m0) * CD);
    const float* Bw = wqkv + (size_t)h * 64 * CD;

    float acc[2][8][4] = {};
    GEMM_MAIN(gah, gal, Bw, acc)

    __half* gv = g_v + (size_t)bh * LL * DKH;
    const int rr = wid * 32 + (lane >> 2);
    const int cb = (lane & 3) * 2;
    #pragma unroll
    for (int mi = 0; mi < 2; mi++) {
        int r = m0 + rr + mi * 16;
        #pragma unroll
        for (int f = 0; f < 8; f++) {
            int c = f * 8 + cb;
            *(uint32_t*)&gv[(size_t)r * DKH + c] =
                pk_h2(acc[mi][f][0], acc[mi][f][1]);
            *(uint32_t*)&gv[(size_t)(r + 8) * DKH + c] =
                pk_h2(acc[mi][f][2], acc[mi][f][3]);
        }
    }
}

// ---------------------------------------------------------------------------
// Kernel 3: fc GEMM (HMMA) + bias + residual -> g_y fp32
// ---------------------------------------------------------------------------
__global__ __launch_bounds__(256) void k_fc_mma(const float* __restrict__ fw,
                                                const float* __restrict__ fb) {
    extern __shared__ char smg[];
    const uint32_t base = smem_u32(smg);
    const int tid = threadIdx.x, lane = tid & 31, wid = tid >> 5;
    const int m0 = blockIdx.x * 256;       // row in [0, B*L)
    const int o0 = blockIdx.y * 64;
    const char* gah = (const char*)(g_ath + (size_t)m0 * CD);
    const char* gal = (const char*)(g_atl + (size_t)m0 * CD);
    const float* Bw = fw + (size_t)o0 * CD;

    float acc[2][8][4] = {};
    GEMM_MAIN(gah, gal, Bw, acc)

    const int rr = wid * 32 + (lane >> 2);
    const int cb = (lane & 3) * 2;
    #pragma unroll
    for (int mi = 0; mi < 2; mi++) {
        int r = m0 + rr + mi * 16;
        #pragma unroll
        for (int f = 0; f < 8; f++) {
            int c = o0 + f * 8 + cb;
            float b0 = fb[c], b1 = fb[c + 1];
            float2 res0 = *(const float2*)&g_x[(size_t)r * CD + c];
            float2 res1 = *(const float2*)&g_x[(size_t)(r + 8) * CD + c];
            *(float2*)&g_y[(size_t)r * CD + c] =
                make_float2(acc[mi][f][0] + b0 + res0.x,
                            acc[mi][f][1] + b1 + res0.y);
            *(float2*)&g_y[(size_t)(r + 8) * CD + c] =
                make_float2(acc[mi][f][2] + b0 + res1.x,
                            acc[mi][f][3] + b1 + res1.y);
        }
    }
}

// ---------------------------------------------------------------------------
// Kernel 2: HMMA flash attention (unchanged math; epilogue -> fp16 hi/lo)
// ---------------------------------------------------------------------------
__device__ __forceinline__ void prefetch_kv(uint32_t buf, const char* g, int tid) {
    #pragma unroll
    for (int i = 0; i < 4; i++) {
        int c = tid + i * 256;
        int n = c >> 3, c8 = c & 7;
        uint32_t go = n * 128 + c8 * 16;
        cpa16(buf + SWZ(go), g + go);
    }
}

__global__ __launch_bounds__(256) void k_attn_mma() {
    extern __shared__ char sm[];
    const uint32_t base = smem_u32(sm);

    const int tid = threadIdx.x;
    const int lane = tid & 31;
    const int wid = tid >> 5;
    const int bh = blockIdx.y;
    const int m0 = blockIdx.x * 128;

    const char* gvb = (const char*)(g_v + (size_t)bh * LL * DKH);

    const uint32_t laneRow = lane & 15;
    const uint32_t laneCol = ((lane >> 4) & 1) * 16;

    const uint32_t Qb = base + 3 * 16384;

    #pragma unroll
    for (int i = 0; i < 4; i++) {
        int c = tid + i * 256;
        int n = c >> 3, c8 = c & 7;
        cpa16(Qb + SWZ(n * 128 + c8 * 16), gvb + (m0 + n) * 128 + c8 * 16);
    }
    cpa_commit();
    prefetch_kv(base, gvb, tid);
    cpa_commit();
    prefetch_kv(base + 16384, gvb + 16384, tid);
    cpa_commit();

    cpa_wait<2>();
    __syncthreads();

    uint32_t qh[4][4];
    {
        uint32_t rowb = (wid * 16 + laneRow) * 128;
        #pragma unroll
        for (int c = 0; c < 4; c++)
            ldsm4(qh[c], Qb + SWZ(rowb + c * 32 + laneCol));
    }

    float o[8][4] = {};
    float mr0 = -1e30f, mr1 = -1e30f, l0 = 0.f, l1 = 0.f;
    const float c1 = LOG2E * 0.125f;

    const int NT = LL / 128;
    for (int t = 0; t < NT; t++) {
        const uint32_t KVb = base + (uint32_t)(t % 3) * 16384;

        if (t + 1 < NT) cpa_wait<1>(); else cpa_wait<0>();
        __syncthreads();
        if (t + 2 < NT) {
            prefetch_kv(base + (uint32_t)((t + 2) % 3) * 16384,
                        gvb + (size_t)(t + 2) * 16384, tid);
            cpa_commit();
        }

        float s[16][4];
        #pragma unroll
        for (int j = 0; j < 16; j++)
            #pragma unroll
            for (int k = 0; k < 4; k++) s[j][k] = 0.f;

        #pragma unroll
        for (int jp = 0; jp < 8; jp++) {
            #pragma unroll
            for (int c = 0; c < 4; c++) {
                uint32_t off = SWZ((jp * 16 + laneRow) * 128 + c * 32 + laneCol);
                uint32_t bv[4];
                ldsm4(bv, KVb + off);
                mma_f16(s[2 * jp],     qh[c], bv[0], bv[2]);
                mma_f16(s[2 * jp + 1], qh[c], bv[1], bv[3]);
            }
        }

        float mt0 = -1e30f, mt1 = -1e30f;
        #pragma unroll
        for (int j = 0; j < 16; j++) {
            mt0 = fmaxf(mt0, fmaxf(s[j][0], s[j][1]));
            mt1 = fmaxf(mt1, fmaxf(s[j][2], s[j][3]));
        }
        mt0 = fmaxf(mt0, __shfl_xor_sync(0xffffffffu, mt0, 1));
        mt0 = fmaxf(mt0, __shfl_xor_sync(0xffffffffu, mt0, 2));
        mt1 = fmaxf(mt1, __shfl_xor_sync(0xffffffffu, mt1, 1));
        mt1 = fmaxf(mt1, __shfl_xor_sync(0xffffffffu, mt1, 2));
        float mn0 = fmaxf(mr0, mt0), mn1 = fmaxf(mr1, mt1);
        float cr0 = ex2f((mr0 - mn0) * c1), cr1 = ex2f((mr1 - mn1) * c1);
        mr0 = mn0; mr1 = mn1;
        l0 *= cr0; l1 *= cr1;
        #pragma unroll
        for (int vt = 0; vt < 8; vt++) {
            o[vt][0] *= cr0; o[vt][1] *= cr0;
            o[vt][2] *= cr1; o[vt][3] *= cr1;
        }
        const float mc0 = mn0 * c1, mc1 = mn1 * c1;
        uint32_t p[16][2];
        #pragma unroll
        for (int j = 0; j < 16; j++) {
            float e0 = ex2f(fmaf(s[j][0], c1, -mc0));
            float e1 = ex2f(fmaf(s[j][1], c1, -mc0));
            float e2 = ex2f(fmaf(s[j][2], c1, -mc1));
            float e3 = ex2f(fmaf(s[j][3], c1, -mc1));
            l0 += e0 + e1;
            l1 += e2 + e3;
            p[j][0] = pk_h2(e0, e1);
            p[j][1] = pk_h2(e2, e3);
        }

        #pragma unroll
        for (int c = 0; c < 8; c++) {
            uint32_t a0 = p[2 * c][0], a1 = p[2 * c][1];
            uint32_t a2 = p[2 * c + 1][0], a3 = p[2 * c + 1][1];
            #pragma unroll
            for (int vp = 0; vp < 4; vp++) {
                uint32_t off = SWZ((c * 16 + laneRow) * 128 + vp * 32 + laneCol);
                uint32_t bv[4];
                ldsm4t(bv, KVb + off);
                mma_f16s(o[2 * vp],     a0, a1, a2, a3, bv[0], bv[1]);
                mma_f16s(o[2 * vp + 1], a0, a1, a2, a3, bv[2], bv[3]);
            }
        }
        __syncthreads();
    }

    // ---- epilogue: normalize, split hi/lo fp16, store ----
    l0 += __shfl_xor_sync(0xffffffffu, l0, 1);
    l0 += __shfl_xor_sync(0xffffffffu, l0, 2);
    l1 += __shfl_xor_sync(0xffffffffu, l1, 1);
    l1 += __shfl_xor_sync(0xffffffffu, l1, 2);
    const float inv0 = 1.f / l0, inv1 = 1.f / l1;
    const int b = bh >> 2, h = bh & 3;
    const int r0 = m0 + wid * 16 + (lane >> 2);
    const int cb = (lane & 3) * 2;
    #pragma unroll
    for (int vt = 0; vt < 8; vt++) {
        size_t i0 = (size_t)(b * LL + r0) * CD + h * 64 + vt * 8 + cb;
        size_t i1 = (size_t)(b * LL + r0 + 8) * CD + h * 64 + vt * 8 + cb;
        float v00 = o[vt][0] * inv0, v01 = o[vt][1] * inv0;
        float v10 = o[vt][2] * inv1, v11 = o[vt][3] * inv1;
        __half h00 = __float2half_rn(v00), h01 = __float2half_rn(v01);
        __half h10 = __float2half_rn(v10), h11 = __float2half_rn(v11);
        __half2 hh0; hh0.x = h00; hh0.y = h01;
        __half2 hh1; hh1.x = h10; hh1.y = h11;
        *(uint32_t*)&g_ath[i0] = *(uint32_t*)&hh0;
        *(uint32_t*)&g_ath[i1] = *(uint32_t*)&hh1;
        *(uint32_t*)&g_atl[i0] =
            pk_h2(v00 - __half2float(h00), v01 - __half2float(h01));
        *(uint32_t*)&g_atl[i1] =
            pk_h2(v10 - __half2float(h10), v11 - __half2float(h11));
    }
}

// ---------------------------------------------------------------------------
// Kernel 4: LayerNorm over C=256
// ---------------------------------------------------------------------------
__global__ __launch_bounds__(256) void k_ln(const float* __restrict__ gam,
                                            const float* __restrict__ bet,
                                            float* __restrict__ out) {
    const int row = blockIdx.x * 8 + (threadIdx.x >> 5);
    const int lane = threadIdx.x & 31;
    const float* y = g_y + (size_t)row * CD;
    float v[8], s = 0.f, s2 = 0.f;
    #pragma unroll
    for (int k = 0; k < 8; k++) {
        v[k] = y[lane + 32 * k];
        s += v[k];
        s2 += v[k] * v[k];
    }
    #pragma unroll
    for (int off = 16; off; off >>= 1) {
        s  += __shfl_xor_sync(0xffffffffu, s, off);
        s2 += __shfl_xor_sync(0xffffffffu, s2, off);
    }
    const float mu = s * (1.f / CD);
    const float rstd = rsqrtf(s2 * (1.f / CD) - mu * mu + 1e-5f);
    #pragma unroll
    for (int k = 0; k < 8; k++) {
        int c = lane + 32 * k;
        out[(size_t)row * CD + c] = (v[k] - mu) * rstd * gam[c] + bet[c];
    }
}

// ---------------------------------------------------------------------------
extern "C" void kernel_launch(void* const* d_in, const int* in_sizes, int n_in,
                              void* d_out, int out_size) {
    const float* qin = (const float*)d_in[0];
    const float* wq  = (const float*)d_in[1];
    const float* fw  = (const float*)d_in[2];
    const float* fb  = (const float*)d_in[3];
    const float* lg  = (const float*)d_in[4];
    const float* lb  = (const float*)d_in[5];
    float* out = (float*)d_out;

    const int attn_smem = 65536;   // 3 x 16KB ring + 16KB Q
    const int gemm_smem = 163840;  // 2 x 80KB
    cudaFuncSetAttribute(k_attn_mma,
                         cudaFuncAttributeMaxDynamicSharedMemorySize, attn_smem);
    cudaFuncSetAttribute(k_qkv_mma,
                         cudaFuncAttributeMaxDynamicSharedMemorySize, gemm_smem);
    cudaFuncSetAttribute(k_fc_mma,
                         cudaFuncAttributeMaxDynamicSharedMemorySize, gemm_smem);

    k_prep<<<dim3(LL / 64, CD / 64, NB), 256>>>(qin);
    k_qkv_mma<<<dim3(LL / 256, NH, NB), 256, gemm_smem>>>(wq);
    k_attn_mma<<<dim3(LL / 128, NB * NH), 256, attn_smem>>>();
    k_fc_mma<<<dim3(NB * LL / 256, CD / 64), 256, gemm_smem>>>(fw, fb);
    k_ln<<<NB * LL / 8, 256>>>(lg, lb, out);
}

// round 9
// speedup vs baseline: 7.9309x; 1.0131x over previous
#include <cuda_runtime.h>
#include <cuda_fp16.h>
#include <stdint.h>

#define NB 2
#define CD 256
#define LL 4096
#define NH 4
#define DKH 64

static constexpr float LOG2E = 1.4426950408889634f;

__device__ float  g_x  [NB * LL * CD];        // residual: [b][l][c] fp32
__device__ __half g_xh [NB * LL * CD];        // x hi (fp16)
__device__ __half g_xl [NB * LL * CD];        // x lo (fp16)
__device__ __half g_v  [NB * NH * LL * DKH];  // q/k/v heads (fp16)
__device__ __half g_ath[NB * LL * CD];        // attn out hi
__device__ __half g_atl[NB * LL * CD];        // attn out lo
__device__ float  g_y  [NB * LL * CD];        // fc+residual
__device__ __half g_wqh[CD * CD];             // w_qkv hi/lo
__device__ __half g_wql[CD * CD];
__device__ __half g_fwh[CD * CD];             // fc_w hi/lo
__device__ __half g_fwl[CD * CD];

// ------------------------- helpers -------------------------
__device__ __forceinline__ uint32_t smem_u32(const void* p) {
    uint32_t a;
    asm("{ .reg .u64 t; cvta.to.shared.u64 t, %1; cvt.u32.u64 %0, t; }"
        : "=r"(a) : "l"(p));
    return a;
}
__device__ __forceinline__ uint32_t SWZ(uint32_t o) {
    return o ^ ((o >> 3) & 0x70);
}
__device__ __forceinline__ void ldsm4(uint32_t* r, uint32_t a) {
    asm volatile("ldmatrix.sync.aligned.m8n8.x4.shared.b16 {%0,%1,%2,%3}, [%4];"
                 : "=r"(r[0]), "=r"(r[1]), "=r"(r[2]), "=r"(r[3]) : "r"(a));
}
__device__ __forceinline__ void ldsm4t(uint32_t* r, uint32_t a) {
    asm volatile("ldmatrix.sync.aligned.m8n8.x4.trans.shared.b16 {%0,%1,%2,%3}, [%4];"
                 : "=r"(r[0]), "=r"(r[1]), "=r"(r[2]), "=r"(r[3]) : "r"(a));
}
__device__ __forceinline__ void mma_f16(float* d, const uint32_t* a,
                                        uint32_t b0, uint32_t b1) {
    asm volatile(
        "mma.sync.aligned.m16n8k16.row.col.f32.f16.f16.f32 "
        "{%0,%1,%2,%3}, {%4,%5,%6,%7}, {%8,%9}, {%0,%1,%2,%3};"
        : "+f"(d[0]), "+f"(d[1]), "+f"(d[2]), "+f"(d[3])
        : "r"(a[0]), "r"(a[1]), "r"(a[2]), "r"(a[3]), "r"(b0), "r"(b1));
}
__device__ __forceinline__ void mma_f16s(float* d, uint32_t a0, uint32_t a1,
                                         uint32_t a2, uint32_t a3,
                                         uint32_t b0, uint32_t b1) {
    asm volatile(
        "mma.sync.aligned.m16n8k16.row.col.f32.f16.f16.f32 "
        "{%0,%1,%2,%3}, {%4,%5,%6,%7}, {%8,%9}, {%0,%1,%2,%3};"
        : "+f"(d[0]), "+f"(d[1]), "+f"(d[2]), "+f"(d[3])
        : "r"(a0), "r"(a1), "r"(a2), "r"(a3), "r"(b0), "r"(b1));
}
__device__ __forceinline__ float ex2f(float x) {
    float y;
    asm("ex2.approx.ftz.f32 %0, %1;" : "=f"(y) : "f"(x));
    return y;
}
__device__ __forceinline__ uint32_t pk_h2(float a, float b) {
    __half2 h = __floats2half2_rn(a, b);
    return *(uint32_t*)&h;
}
__device__ __forceinline__ void cpa16(uint32_t s, const void* g) {
    asm volatile("cp.async.cg.shared.global [%0], [%1], 16;" :: "r"(s), "l"(g));
}
__device__ __forceinline__ void cpa_commit() {
    asm volatile("cp.async.commit_group;" ::: "memory");
}
template <int N>
__device__ __forceinline__ void cpa_wait() {
    asm volatile("cp.async.wait_group %0;" :: "n"(N) : "memory");
}

// ---------------------------------------------------------------------------
// Kernel 0a: transpose input -> g_x (fp32) + g_xh/g_xl (fp16 hi/lo)
// ---------------------------------------------------------------------------
__global__ __launch_bounds__(256) void k_prep(const float* __restrict__ qin) {
    __shared__ float T[64][65];
    const int bt = blockIdx.z, c0 = blockIdx.y * 64, l0 = blockIdx.x * 64;
    const int tid = threadIdx.x;
    #pragma unroll
    for (int i = 0; i < 16; i++) {
        int idx = tid + i * 256;
        int ci = idx >> 6, lj = idx & 63;
        T[ci][lj] = qin[(size_t)bt * CD * LL + (size_t)(c0 + ci) * LL + l0 + lj];
    }
    __syncthreads();
    #pragma unroll
    for (int i = 0; i < 16; i++) {
        int idx = tid + i * 256;
        int li = idx >> 6, cj = idx & 63;
        float v = T[cj][li];
        size_t o = (size_t)(bt * LL + l0 + li) * CD + c0 + cj;
        g_x[o] = v;
        __half h = __float2half_rn(v);
        g_xh[o] = h;
        g_xl[o] = __float2half_rn(v - __half2float(h));
    }
}

// ---------------------------------------------------------------------------
// Kernel 0b: convert both weight matrices to fp16 hi/lo (one-time)
// ---------------------------------------------------------------------------
__global__ __launch_bounds__(256) void k_prep_w(const float* __restrict__ wq,
                                                const float* __restrict__ fw) {
    int idx = blockIdx.x * 256 + threadIdx.x;   // 65536 total
    float v = wq[idx];
    __half h = __float2half_rn(v);
    g_wqh[idx] = h;
    g_wql[idx] = __float2half_rn(v - __half2float(h));
    float u = fw[idx];
    __half g = __float2half_rn(u);
    g_fwh[idx] = g;
    g_fwl[idx] = __float2half_rn(u - __half2float(g));
}

// ---------------------------------------------------------------------------
// Shared GEMM mainloop: M=128 x N=64 x K=256, fp16 hi/lo 3-MMA, pure cp.async.
// 8 warps x m16. 2-stage smem (48KB each): Ahi 16K | Alo 16K | Bhi 8K | Blo 8K.
// A/B row stride in gmem = 512B (256 fp16).
// ---------------------------------------------------------------------------
__device__ __forceinline__ void gemm_ml(const char* gah, const char* gal,
                                        const char* gbh, const char* gbl,
                                        uint32_t base, int tid, int wid,
                                        uint32_t laneRow, uint32_t laneCol,
                                        float (&acc)[8][4]) {
    auto pref = [&](int kc) {
        uint32_t st = base + (uint32_t)(kc & 1) * 49152u;
        #pragma unroll
        for (int i = 0; i < 4; i++) {             // A: 1024 chunks
            int idx = tid + i * 256;
            int r = idx >> 3, c8 = idx & 7;
            uint32_t so = SWZ(r * 128 + c8 * 16);
            size_t go = (size_t)r * 512 + (size_t)kc * 128 + c8 * 16;
            cpa16(st + so, gah + go);
            cpa16(st + 16384 + so, gal + go);
        }
        #pragma unroll
        for (int i = 0; i < 2; i++) {             // B: 512 chunks
            int idx = tid + i * 256;
            int r = idx >> 3, c8 = idx & 7;
            uint32_t so = SWZ(r * 128 + c8 * 16);
            size_t go = (size_t)r * 512 + (size_t)kc * 128 + c8 * 16;
            cpa16(st + 32768 + so, gbh + go);
            cpa16(st + 40960 + so, gbl + go);
        }
    };
    pref(0); cpa_commit();
    pref(1); cpa_commit();
    #pragma unroll
    for (int kc = 0; kc < 4; kc++) {
        if (kc < 3) cpa_wait<1>(); else cpa_wait<0>();
        __syncthreads();
        uint32_t sb = base + (uint32_t)(kc & 1) * 49152u;
        #pragma unroll
        for (int s = 0; s < 4; s++) {
            uint32_t ah[4], al[4];
            uint32_t offA = SWZ((wid * 16 + laneRow) * 128 + s * 32 + laneCol);
            ldsm4(ah, sb + offA);
            ldsm4(al, sb + 16384 + offA);
            #pragma unroll
            for (int nf = 0; nf < 4; nf++) {
                uint32_t offB = SWZ((nf * 16 + laneRow) * 128 + s * 32 + laneCol);
                uint32_t b4[4], c4[4];
                ldsm4(b4, sb + 32768 + offB);
                ldsm4(c4, sb + 40960 + offB);
                mma_f16(acc[2 * nf],     ah, b4[0], b4[2]);
                mma_f16(acc[2 * nf],     al, b4[0], b4[2]);
                mma_f16(acc[2 * nf],     ah, c4[0], c4[2]);
                mma_f16(acc[2 * nf + 1], ah, b4[1], b4[3]);
                mma_f16(acc[2 * nf + 1], al, b4[1], b4[3]);
                mma_f16(acc[2 * nf + 1], ah, c4[1], c4[3]);
            }
        }
        __syncthreads();
        if (kc + 2 < 4) { pref(kc + 2); cpa_commit(); }
    }
}

// ---------------------------------------------------------------------------
// Kernel 1: QKV projection (HMMA) -> g_v fp16
// ---------------------------------------------------------------------------
__global__ __launch_bounds__(256, 2) void k_qkv_mma() {
    extern __shared__ char smg[];
    const uint32_t base = smem_u32(smg);
    const int tid = threadIdx.x, lane = tid & 31, wid = tid >> 5;
    const int m0 = blockIdx.x * 128;
    const int h = blockIdx.y, bt = blockIdx.z, bh = bt * NH + h;
    const uint32_t laneRow = lane & 15;
    const uint32_t laneCol = ((lane >> 4) & 1) * 16;

    float acc[8][4] = {};
    gemm_ml((const char*)(g_xh + (size_t)(bt * LL + m0) * CD),
            (const char*)(g_xl + (size_t)(bt * LL + m0) * CD),
            (const char*)(g_wqh + (size_t)h * 64 * CD),
            (const char*)(g_wql + (size_t)h * 64 * CD),
            base, tid, wid, laneRow, laneCol, acc);

    __half* gv = g_v + (size_t)bh * LL * DKH;
    const int r = m0 + wid * 16 + (lane >> 2);
    const int cb = (lane & 3) * 2;
    #pragma unroll
    for (int f = 0; f < 8; f++) {
        int c = f * 8 + cb;
        *(uint32_t*)&gv[(size_t)r * DKH + c] = pk_h2(acc[f][0], acc[f][1]);
        *(uint32_t*)&gv[(size_t)(r + 8) * DKH + c] = pk_h2(acc[f][2], acc[f][3]);
    }
}

// ---------------------------------------------------------------------------
// Kernel 3: fc GEMM (HMMA) + bias + residual -> g_y fp32
// ---------------------------------------------------------------------------
__global__ __launch_bounds__(256, 2) void k_fc_mma(const float* __restrict__ fb) {
    extern __shared__ char smg[];
    const uint32_t base = smem_u32(smg);
    const int tid = threadIdx.x, lane = tid & 31, wid = tid >> 5;
    const int m0 = blockIdx.x * 128;     // row in [0, B*L)
    const int o0 = blockIdx.y * 64;
    const uint32_t laneRow = lane & 15;
    const uint32_t laneCol = ((lane >> 4) & 1) * 16;

    float acc[8][4] = {};
    gemm_ml((const char*)(g_ath + (size_t)m0 * CD),
            (const char*)(g_atl + (size_t)m0 * CD),
            (const char*)(g_fwh + (size_t)o0 * CD),
            (const char*)(g_fwl + (size_t)o0 * CD),
            base, tid, wid, laneRow, laneCol, acc);

    const int r = m0 + wid * 16 + (lane >> 2);
    const int cb = (lane & 3) * 2;
    #pragma unroll
    for (int f = 0; f < 8; f++) {
        int c = o0 + f * 8 + cb;
        float b0 = fb[c], b1 = fb[c + 1];
        float2 res0 = *(const float2*)&g_x[(size_t)r * CD + c];
        float2 res1 = *(const float2*)&g_x[(size_t)(r + 8) * CD + c];
        *(float2*)&g_y[(size_t)r * CD + c] =
            make_float2(acc[f][0] + b0 + res0.x, acc[f][1] + b1 + res0.y);
        *(float2*)&g_y[(size_t)(r + 8) * CD + c] =
            make_float2(acc[f][2] + b0 + res1.x, acc[f][3] + b1 + res1.y);
    }
}

// ---------------------------------------------------------------------------
// Kernel 2: HMMA flash attention (epilogue -> fp16 hi/lo)
// ---------------------------------------------------------------------------
__device__ __forceinline__ void prefetch_kv(uint32_t buf, const char* g, int tid) {
    #pragma unroll
    for (int i = 0; i < 4; i++) {
        int c = tid + i * 256;
        int n = c >> 3, c8 = c & 7;
        uint32_t go = n * 128 + c8 * 16;
        cpa16(buf + SWZ(go), g + go);
    }
}

__global__ __launch_bounds__(256) void k_attn_mma() {
    extern __shared__ char sm[];
    const uint32_t base = smem_u32(sm);

    const int tid = threadIdx.x;
    const int lane = tid & 31;
    const int wid = tid >> 5;
    const int bh = blockIdx.y;
    const int m0 = blockIdx.x * 128;

    const char* gvb = (const char*)(g_v + (size_t)bh * LL * DKH);

    const uint32_t laneRow = lane & 15;
    const uint32_t laneCol = ((lane >> 4) & 1) * 16;

    const uint32_t Qb = base + 3 * 16384;

    #pragma unroll
    for (int i = 0; i < 4; i++) {
        int c = tid + i * 256;
        int n = c >> 3, c8 = c & 7;
        cpa16(Qb + SWZ(n * 128 + c8 * 16), gvb + (m0 + n) * 128 + c8 * 16);
    }
    cpa_commit();
    prefetch_kv(base, gvb, tid);
    cpa_commit();
    prefetch_kv(base + 16384, gvb + 16384, tid);
    cpa_commit();

    cpa_wait<2>();
    __syncthreads();

    uint32_t qh[4][4];
    {
        uint32_t rowb = (wid * 16 + laneRow) * 128;
        #pragma unroll
        for (int c = 0; c < 4; c++)
            ldsm4(qh[c], Qb + SWZ(rowb + c * 32 + laneCol));
    }

    float o[8][4] = {};
    float mr0 = -1e30f, mr1 = -1e30f, l0 = 0.f, l1 = 0.f;
    const float c1 = LOG2E * 0.125f;

    const int NT = LL / 128;
    for (int t = 0; t < NT; t++) {
        const uint32_t KVb = base + (uint32_t)(t % 3) * 16384;

        if (t + 1 < NT) cpa_wait<1>(); else cpa_wait<0>();
        __syncthreads();
        if (t + 2 < NT) {
            prefetch_kv(base + (uint32_t)((t + 2) % 3) * 16384,
                        gvb + (size_t)(t + 2) * 16384, tid);
            cpa_commit();
        }

        float s[16][4];
        #pragma unroll
        for (int j = 0; j < 16; j++)
            #pragma unroll
            for (int k = 0; k < 4; k++) s[j][k] = 0.f;

        #pragma unroll
        for (int jp = 0; jp < 8; jp++) {
            #pragma unroll
            for (int c = 0; c < 4; c++) {
                uint32_t off = SWZ((jp * 16 + laneRow) * 128 + c * 32 + laneCol);
                uint32_t bv[4];
                ldsm4(bv, KVb + off);
                mma_f16(s[2 * jp],     qh[c], bv[0], bv[2]);
                mma_f16(s[2 * jp + 1], qh[c], bv[1], bv[3]);
            }
        }

        float mt0 = -1e30f, mt1 = -1e30f;
        #pragma unroll
        for (int j = 0; j < 16; j++) {
            mt0 = fmaxf(mt0, fmaxf(s[j][0], s[j][1]));
            mt1 = fmaxf(mt1, fmaxf(s[j][2], s[j][3]));
        }
        mt0 = fmaxf(mt0, __shfl_xor_sync(0xffffffffu, mt0, 1));
        mt0 = fmaxf(mt0, __shfl_xor_sync(0xffffffffu, mt0, 2));
        mt1 = fmaxf(mt1, __shfl_xor_sync(0xffffffffu, mt1, 1));
        mt1 = fmaxf(mt1, __shfl_xor_sync(0xffffffffu, mt1, 2));
        float mn0 = fmaxf(mr0, mt0), mn1 = fmaxf(mr1, mt1);
        float cr0 = ex2f((mr0 - mn0) * c1), cr1 = ex2f((mr1 - mn1) * c1);
        mr0 = mn0; mr1 = mn1;
        l0 *= cr0; l1 *= cr1;
        #pragma unroll
        for (int vt = 0; vt < 8; vt++) {
            o[vt][0] *= cr0; o[vt][1] *= cr0;
            o[vt][2] *= cr1; o[vt][3] *= cr1;
        }
        const float mc0 = mn0 * c1, mc1 = mn1 * c1;
        uint32_t p[16][2];
        #pragma unroll
        for (int j = 0; j < 16; j++) {
            float e0 = ex2f(fmaf(s[j][0], c1, -mc0));
            float e1 = ex2f(fmaf(s[j][1], c1, -mc0));
            float e2 = ex2f(fmaf(s[j][2], c1, -mc1));
            float e3 = ex2f(fmaf(s[j][3], c1, -mc1));
            l0 += e0 + e1;
            l1 += e2 + e3;
            p[j][0] = pk_h2(e0, e1);
            p[j][1] = pk_h2(e2, e3);
        }

        #pragma unroll
        for (int c = 0; c < 8; c++) {
            uint32_t a0 = p[2 * c][0], a1 = p[2 * c][1];
            uint32_t a2 = p[2 * c + 1][0], a3 = p[2 * c + 1][1];
            #pragma unroll
            for (int vp = 0; vp < 4; vp++) {
                uint32_t off = SWZ((c * 16 + laneRow) * 128 + vp * 32 + laneCol);
                uint32_t bv[4];
                ldsm4t(bv, KVb + off);
                mma_f16s(o[2 * vp],     a0, a1, a2, a3, bv[0], bv[1]);
                mma_f16s(o[2 * vp + 1], a0, a1, a2, a3, bv[2], bv[3]);
            }
        }
        __syncthreads();
    }

    l0 += __shfl_xor_sync(0xffffffffu, l0, 1);
    l0 += __shfl_xor_sync(0xffffffffu, l0, 2);
    l1 += __shfl_xor_sync(0xffffffffu, l1, 1);
    l1 += __shfl_xor_sync(0xffffffffu, l1, 2);
    const float inv0 = 1.f / l0, inv1 = 1.f / l1;
    const int b = bh >> 2, h = bh & 3;
    const int r0 = m0 + wid * 16 + (lane >> 2);
    const int cb = (lane & 3) * 2;
    #pragma unroll
    for (int vt = 0; vt < 8; vt++) {
        size_t i0 = (size_t)(b * LL + r0) * CD + h * 64 + vt * 8 + cb;
        size_t i1 = (size_t)(b * LL + r0 + 8) * CD + h * 64 + vt * 8 + cb;
        float v00 = o[vt][0] * inv0, v01 = o[vt][1] * inv0;
        float v10 = o[vt][2] * inv1, v11 = o[vt][3] * inv1;
        __half h00 = __float2half_rn(v00), h01 = __float2half_rn(v01);
        __half h10 = __float2half_rn(v10), h11 = __float2half_rn(v11);
        __half2 hh0; hh0.x = h00; hh0.y = h01;
        __half2 hh1; hh1.x = h10; hh1.y = h11;
        *(uint32_t*)&g_ath[i0] = *(uint32_t*)&hh0;
        *(uint32_t*)&g_ath[i1] = *(uint32_t*)&hh1;
        *(uint32_t*)&g_atl[i0] =
            pk_h2(v00 - __half2float(h00), v01 - __half2float(h01));
        *(uint32_t*)&g_atl[i1] =
            pk_h2(v10 - __half2float(h10), v11 - __half2float(h11));
    }
}

// ---------------------------------------------------------------------------
// Kernel 4: LayerNorm over C=256
// ---------------------------------------------------------------------------
__global__ __launch_bounds__(256) void k_ln(const float* __restrict__ gam,
                                            const float* __restrict__ bet,
                                            float* __restrict__ out) {
    const int row = blockIdx.x * 8 + (threadIdx.x >> 5);
    const int lane = threadIdx.x & 31;
    const float* y = g_y + (size_t)row * CD;
    float v[8], s = 0.f, s2 = 0.f;
    #pragma unroll
    for (int k = 0; k < 8; k++) {
        v[k] = y[lane + 32 * k];
        s += v[k];
        s2 += v[k] * v[k];
    }
    #pragma unroll
    for (int off = 16; off; off >>= 1) {
        s  += __shfl_xor_sync(0xffffffffu, s, off);
        s2 += __shfl_xor_sync(0xffffffffu, s2, off);
    }
    const float mu = s * (1.f / CD);
    const float rstd = rsqrtf(s2 * (1.f / CD) - mu * mu + 1e-5f);
    #pragma unroll
    for (int k = 0; k < 8; k++) {
        int c = lane + 32 * k;
        out[(size_t)row * CD + c] = (v[k] - mu) * rstd * gam[c] + bet[c];
    }
}

// ---------------------------------------------------------------------------
extern "C" void kernel_launch(void* const* d_in, const int* in_sizes, int n_in,
                              void* d_out, int out_size) {
    const float* qin = (const float*)d_in[0];
    const float* wq  = (const float*)d_in[1];
    const float* fw  = (const float*)d_in[2];
    const float* fb  = (const float*)d_in[3];
    const float* lg  = (const float*)d_in[4];
    const float* lb  = (const float*)d_in[5];
    float* out = (float*)d_out;

    const int attn_smem = 65536;   // 3 x 16KB ring + 16KB Q
    const int gemm_smem = 98304;   // 2 x 48KB
    cudaFuncSetAttribute(k_attn_mma,
                         cudaFuncAttributeMaxDynamicSharedMemorySize, attn_smem);
    cudaFuncSetAttribute(k_qkv_mma,
                         cudaFuncAttributeMaxDynamicSharedMemorySize, gemm_smem);
    cudaFuncSetAttribute(k_fc_mma,
                         cudaFuncAttributeMaxDynamicSharedMemorySize, gemm_smem);

    k_prep<<<dim3(LL / 64, CD / 64, NB), 256>>>(qin);
    k_prep_w<<<CD * CD / 256, 256>>>(wq, fw);
    k_qkv_mma<<<dim3(LL / 128, NH, NB), 256, gemm_smem>>>();
    k_attn_mma<<<dim3(LL / 128, NB * NH), 256, attn_smem>>>();
    k_fc_mma<<<dim3(NB * LL / 128, CD / 64), 256, gemm_smem>>>(fb);
    k_ln<<<NB * LL / 8, 256>>>(lg, lb, out);
}

// round 10
// speedup vs baseline: 7.9325x; 1.0002x over previous
#include <cuda_runtime.h>
#include <cuda_fp16.h>
#include <stdint.h>

#define NB 2
#define CD 256
#define LL 4096
#define NH 4
#define DKH 64

static constexpr float LOG2E = 1.4426950408889634f;

__device__ float  g_x  [NB * LL * CD];        // residual: [b][l][c] fp32
__device__ __half g_xh [NB * LL * CD];        // x hi (fp16)
__device__ __half g_xl [NB * LL * CD];        // x lo (fp16)
__device__ __half g_v  [NB * NH * LL * DKH];  // q/k/v heads (fp16)
__device__ __half g_ath[NB * LL * CD];        // attn out hi
__device__ __half g_atl[NB * LL * CD];        // attn out lo
__device__ float  g_y  [NB * LL * CD];        // fc+residual
__device__ __half g_wqh[CD * CD];             // w_qkv hi/lo
__device__ __half g_wql[CD * CD];
__device__ __half g_fwh[CD * CD];             // fc_w hi/lo
__device__ __half g_fwl[CD * CD];

// ------------------------- helpers -------------------------
__device__ __forceinline__ uint32_t smem_u32(const void* p) {
    uint32_t a;
    asm("{ .reg .u64 t; cvta.to.shared.u64 t, %1; cvt.u32.u64 %0, t; }"
        : "=r"(a) : "l"(p));
    return a;
}
__device__ __forceinline__ uint32_t SWZ(uint32_t o) {
    return o ^ ((o >> 3) & 0x70);
}
__device__ __forceinline__ void ldsm4(uint32_t* r, uint32_t a) {
    asm volatile("ldmatrix.sync.aligned.m8n8.x4.shared.b16 {%0,%1,%2,%3}, [%4];"
                 : "=r"(r[0]), "=r"(r[1]), "=r"(r[2]), "=r"(r[3]) : "r"(a));
}
__device__ __forceinline__ void ldsm4t(uint32_t* r, uint32_t a) {
    asm volatile("ldmatrix.sync.aligned.m8n8.x4.trans.shared.b16 {%0,%1,%2,%3}, [%4];"
                 : "=r"(r[0]), "=r"(r[1]), "=r"(r[2]), "=r"(r[3]) : "r"(a));
}
__device__ __forceinline__ void mma_f16(float* d, const uint32_t* a,
                                        uint32_t b0, uint32_t b1) {
    asm volatile(
        "mma.sync.aligned.m16n8k16.row.col.f32.f16.f16.f32 "
        "{%0,%1,%2,%3}, {%4,%5,%6,%7}, {%8,%9}, {%0,%1,%2,%3};"
        : "+f"(d[0]), "+f"(d[1]), "+f"(d[2]), "+f"(d[3])
        : "r"(a[0]), "r"(a[1]), "r"(a[2]), "r"(a[3]), "r"(b0), "r"(b1));
}
__device__ __forceinline__ void mma_f16s(float* d, uint32_t a0, uint32_t a1,
                                         uint32_t a2, uint32_t a3,
                                         uint32_t b0, uint32_t b1) {
    asm volatile(
        "mma.sync.aligned.m16n8k16.row.col.f32.f16.f16.f32 "
        "{%0,%1,%2,%3}, {%4,%5,%6,%7}, {%8,%9}, {%0,%1,%2,%3};"
        : "+f"(d[0]), "+f"(d[1]), "+f"(d[2]), "+f"(d[3])
        : "r"(a0), "r"(a1), "r"(a2), "r"(a3), "r"(b0), "r"(b1));
}
__device__ __forceinline__ float ex2f(float x) {
    float y;
    asm("ex2.approx.ftz.f32 %0, %1;" : "=f"(y) : "f"(x));
    return y;
}
__device__ __forceinline__ uint32_t pk_h2(float a, float b) {
    __half2 h = __floats2half2_rn(a, b);
    return *(uint32_t*)&h;
}
__device__ __forceinline__ void cpa16(uint32_t s, const void* g) {
    asm volatile("cp.async.cg.shared.global [%0], [%1], 16;" :: "r"(s), "l"(g));
}
__device__ __forceinline__ void cpa_commit() {
    asm volatile("cp.async.commit_group;" ::: "memory");
}
template <int N>
__device__ __forceinline__ void cpa_wait() {
    asm volatile("cp.async.wait_group %0;" :: "n"(N) : "memory");
}

// ---------------------------------------------------------------------------
// Kernel 0a: transpose input -> g_x (fp32) + g_xh/g_xl (fp16 hi/lo)
// ---------------------------------------------------------------------------
__global__ __launch_bounds__(256) void k_prep(const float* __restrict__ qin) {
    __shared__ float T[64][65];
    const int bt = blockIdx.z, c0 = blockIdx.y * 64, l0 = blockIdx.x * 64;
    const int tid = threadIdx.x;
    #pragma unroll
    for (int i = 0; i < 16; i++) {
        int idx = tid + i * 256;
        int ci = idx >> 6, lj = idx & 63;
        T[ci][lj] = qin[(size_t)bt * CD * LL + (size_t)(c0 + ci) * LL + l0 + lj];
    }
    __syncthreads();
    #pragma unroll
    for (int i = 0; i < 16; i++) {
        int idx = tid + i * 256;
        int li = idx >> 6, cj = idx & 63;
        float v = T[cj][li];
        size_t o = (size_t)(bt * LL + l0 + li) * CD + c0 + cj;
        g_x[o] = v;
        __half h = __float2half_rn(v);
        g_xh[o] = h;
        g_xl[o] = __float2half_rn(v - __half2float(h));
    }
}

// ---------------------------------------------------------------------------
// Kernel 0b: convert both weight matrices to fp16 hi/lo (one-time)
// ---------------------------------------------------------------------------
__global__ __launch_bounds__(256) void k_prep_w(const float* __restrict__ wq,
                                                const float* __restrict__ fw) {
    int idx = blockIdx.x * 256 + threadIdx.x;   // 65536 total
    float v = wq[idx];
    __half h = __float2half_rn(v);
    g_wqh[idx] = h;
    g_wql[idx] = __float2half_rn(v - __half2float(h));
    float u = fw[idx];
    __half g = __float2half_rn(u);
    g_fwh[idx] = g;
    g_fwl[idx] = __float2half_rn(u - __half2float(g));
}

// ---------------------------------------------------------------------------
// Shared GEMM mainloop: M=128 x N=64 x K=256, fp16 hi/lo 3-MMA, pure cp.async.
// ---------------------------------------------------------------------------
__device__ __forceinline__ void gemm_ml(const char* gah, const char* gal,
                                        const char* gbh, const char* gbl,
                                        uint32_t base, int tid, int wid,
                                        uint32_t laneRow, uint32_t laneCol,
                                        float (&acc)[8][4]) {
    auto pref = [&](int kc) {
        uint32_t st = base + (uint32_t)(kc & 1) * 49152u;
        #pragma unroll
        for (int i = 0; i < 4; i++) {             // A: 1024 chunks
            int idx = tid + i * 256;
            int r = idx >> 3, c8 = idx & 7;
            uint32_t so = SWZ(r * 128 + c8 * 16);
            size_t go = (size_t)r * 512 + (size_t)kc * 128 + c8 * 16;
            cpa16(st + so, gah + go);
            cpa16(st + 16384 + so, gal + go);
        }
        #pragma unroll
        for (int i = 0; i < 2; i++) {             // B: 512 chunks
            int idx = tid + i * 256;
            int r = idx >> 3, c8 = idx & 7;
            uint32_t so = SWZ(r * 128 + c8 * 16);
            size_t go = (size_t)r * 512 + (size_t)kc * 128 + c8 * 16;
            cpa16(st + 32768 + so, gbh + go);
            cpa16(st + 40960 + so, gbl + go);
        }
    };
    pref(0); cpa_commit();
    pref(1); cpa_commit();
    #pragma unroll
    for (int kc = 0; kc < 4; kc++) {
        if (kc < 3) cpa_wait<1>(); else cpa_wait<0>();
        __syncthreads();
        uint32_t sb = base + (uint32_t)(kc & 1) * 49152u;
        #pragma unroll
        for (int s = 0; s < 4; s++) {
            uint32_t ah[4], al[4];
            uint32_t offA = SWZ((wid * 16 + laneRow) * 128 + s * 32 + laneCol);
            ldsm4(ah, sb + offA);
            ldsm4(al, sb + 16384 + offA);
            #pragma unroll
            for (int nf = 0; nf < 4; nf++) {
                uint32_t offB = SWZ((nf * 16 + laneRow) * 128 + s * 32 + laneCol);
                uint32_t b4[4], c4[4];
                ldsm4(b4, sb + 32768 + offB);
                ldsm4(c4, sb + 40960 + offB);
                mma_f16(acc[2 * nf],     ah, b4[0], b4[2]);
                mma_f16(acc[2 * nf],     al, b4[0], b4[2]);
                mma_f16(acc[2 * nf],     ah, c4[0], c4[2]);
                mma_f16(acc[2 * nf + 1], ah, b4[1], b4[3]);
                mma_f16(acc[2 * nf + 1], al, b4[1], b4[3]);
                mma_f16(acc[2 * nf + 1], ah, c4[1], c4[3]);
            }
        }
        __syncthreads();
        if (kc + 2 < 4) { pref(kc + 2); cpa_commit(); }
    }
}

// ---------------------------------------------------------------------------
// Kernel 1: QKV projection (HMMA) -> g_v fp16
// ---------------------------------------------------------------------------
__global__ __launch_bounds__(256, 2) void k_qkv_mma() {
    extern __shared__ char smg[];
    const uint32_t base = smem_u32(smg);
    const int tid = threadIdx.x, lane = tid & 31, wid = tid >> 5;
    const int m0 = blockIdx.x * 128;
    const int h = blockIdx.y, bt = blockIdx.z, bh = bt * NH + h;
    const uint32_t laneRow = lane & 15;
    const uint32_t laneCol = ((lane >> 4) & 1) * 16;

    float acc[8][4] = {};
    gemm_ml((const char*)(g_xh + (size_t)(bt * LL + m0) * CD),
            (const char*)(g_xl + (size_t)(bt * LL + m0) * CD),
            (const char*)(g_wqh + (size_t)h * 64 * CD),
            (const char*)(g_wql + (size_t)h * 64 * CD),
            base, tid, wid, laneRow, laneCol, acc);

    __half* gv = g_v + (size_t)bh * LL * DKH;
    const int r = m0 + wid * 16 + (lane >> 2);
    const int cb = (lane & 3) * 2;
    #pragma unroll
    for (int f = 0; f < 8; f++) {
        int c = f * 8 + cb;
        *(uint32_t*)&gv[(size_t)r * DKH + c] = pk_h2(acc[f][0], acc[f][1]);
        *(uint32_t*)&gv[(size_t)(r + 8) * DKH + c] = pk_h2(acc[f][2], acc[f][3]);
    }
}

// ---------------------------------------------------------------------------
// Kernel 3: fc GEMM (HMMA) + bias + residual -> g_y fp32
// ---------------------------------------------------------------------------
__global__ __launch_bounds__(256, 2) void k_fc_mma(const float* __restrict__ fb) {
    extern __shared__ char smg[];
    const uint32_t base = smem_u32(smg);
    const int tid = threadIdx.x, lane = tid & 31, wid = tid >> 5;
    const int m0 = blockIdx.x * 128;     // row in [0, B*L)
    const int o0 = blockIdx.y * 64;
    const uint32_t laneRow = lane & 15;
    const uint32_t laneCol = ((lane >> 4) & 1) * 16;

    float acc[8][4] = {};
    gemm_ml((const char*)(g_ath + (size_t)m0 * CD),
            (const char*)(g_atl + (size_t)m0 * CD),
            (const char*)(g_fwh + (size_t)o0 * CD),
            (const char*)(g_fwl + (size_t)o0 * CD),
            base, tid, wid, laneRow, laneCol, acc);

    const int r = m0 + wid * 16 + (lane >> 2);
    const int cb = (lane & 3) * 2;
    #pragma unroll
    for (int f = 0; f < 8; f++) {
        int c = o0 + f * 8 + cb;
        float b0 = fb[c], b1 = fb[c + 1];
        float2 res0 = *(const float2*)&g_x[(size_t)r * CD + c];
        float2 res1 = *(const float2*)&g_x[(size_t)(r + 8) * CD + c];
        *(float2*)&g_y[(size_t)r * CD + c] =
            make_float2(acc[f][0] + b0 + res0.x, acc[f][1] + b1 + res0.y);
        *(float2*)&g_y[(size_t)(r + 8) * CD + c] =
            make_float2(acc[f][2] + b0 + res1.x, acc[f][3] + b1 + res1.y);
    }
}

// ---------------------------------------------------------------------------
// Kernel 2: HMMA flash attention. 256 threads / 8 warps, 128 q-rows per CTA.
// Key tile of 128 processed in two 64-column halves to cap registers at 128
// -> 2 CTAs/SM. 3-stage cp.async ring + Q staging = 64KB smem.
// ---------------------------------------------------------------------------
__device__ __forceinline__ void prefetch_kv(uint32_t buf, const char* g, int tid) {
    #pragma unroll
    for (int i = 0; i < 4; i++) {
        int c = tid + i * 256;
        int n = c >> 3, c8 = c & 7;
        uint32_t go = n * 128 + c8 * 16;
        cpa16(buf + SWZ(go), g + go);
    }
}

__global__ __launch_bounds__(256, 2) void k_attn_mma() {
    extern __shared__ char sm[];
    const uint32_t base = smem_u32(sm);

    const int tid = threadIdx.x;
    const int lane = tid & 31;
    const int wid = tid >> 5;
    const int bh = blockIdx.y;
    const int m0 = blockIdx.x * 128;

    const char* gvb = (const char*)(g_v + (size_t)bh * LL * DKH);

    const uint32_t laneRow = lane & 15;
    const uint32_t laneCol = ((lane >> 4) & 1) * 16;

    const uint32_t Qb = base + 3 * 16384;

    #pragma unroll
    for (int i = 0; i < 4; i++) {
        int c = tid + i * 256;
        int n = c >> 3, c8 = c & 7;
        cpa16(Qb + SWZ(n * 128 + c8 * 16), gvb + (m0 + n) * 128 + c8 * 16);
    }
    cpa_commit();
    prefetch_kv(base, gvb, tid);
    cpa_commit();
    prefetch_kv(base + 16384, gvb + 16384, tid);
    cpa_commit();

    cpa_wait<2>();
    __syncthreads();

    uint32_t qh[4][4];
    {
        uint32_t rowb = (wid * 16 + laneRow) * 128;
        #pragma unroll
        for (int c = 0; c < 4; c++)
            ldsm4(qh[c], Qb + SWZ(rowb + c * 32 + laneCol));
    }

    float o[8][4] = {};
    float mr0 = -1e30f, mr1 = -1e30f, l0 = 0.f, l1 = 0.f;
    const float c1 = LOG2E * 0.125f;

    const int NT = LL / 128;
    for (int t = 0; t < NT; t++) {
        const uint32_t KVb = base + (uint32_t)(t % 3) * 16384;

        if (t + 1 < NT) cpa_wait<1>(); else cpa_wait<0>();
        __syncthreads();
        if (t + 2 < NT) {
            prefetch_kv(base + (uint32_t)((t + 2) % 3) * 16384,
                        gvb + (size_t)(t + 2) * 16384, tid);
            cpa_commit();
        }

        #pragma unroll
        for (int hf = 0; hf < 2; hf++) {
            const int nb = hf * 64;

            // ---- S = Q K^T over this 64-col half ----
            float s[8][4];
            #pragma unroll
            for (int j = 0; j < 8; j++)
                #pragma unroll
                for (int k = 0; k < 4; k++) s[j][k] = 0.f;

            #pragma unroll
            for (int jp = 0; jp < 4; jp++) {
                #pragma unroll
                for (int c = 0; c < 4; c++) {
                    uint32_t off = SWZ((nb + jp * 16 + laneRow) * 128 +
                                       c * 32 + laneCol);
                    uint32_t bv[4];
                    ldsm4(bv, KVb + off);
                    mma_f16(s[2 * jp],     qh[c], bv[0], bv[2]);
                    mma_f16(s[2 * jp + 1], qh[c], bv[1], bv[3]);
                }
            }

            // ---- online softmax (half-tile) ----
            float mt0 = -1e30f, mt1 = -1e30f;
            #pragma unroll
            for (int j = 0; j < 8; j++) {
                mt0 = fmaxf(mt0, fmaxf(s[j][0], s[j][1]));
                mt1 = fmaxf(mt1, fmaxf(s[j][2], s[j][3]));
            }
            mt0 = fmaxf(mt0, __shfl_xor_sync(0xffffffffu, mt0, 1));
            mt0 = fmaxf(mt0, __shfl_xor_sync(0xffffffffu, mt0, 2));
            mt1 = fmaxf(mt1, __shfl_xor_sync(0xffffffffu, mt1, 1));
            mt1 = fmaxf(mt1, __shfl_xor_sync(0xffffffffu, mt1, 2));
            float mn0 = fmaxf(mr0, mt0), mn1 = fmaxf(mr1, mt1);
            float cr0 = ex2f((mr0 - mn0) * c1), cr1 = ex2f((mr1 - mn1) * c1);
            mr0 = mn0; mr1 = mn1;
            l0 *= cr0; l1 *= cr1;
            #pragma unroll
            for (int vt = 0; vt < 8; vt++) {
                o[vt][0] *= cr0; o[vt][1] *= cr0;
                o[vt][2] *= cr1; o[vt][3] *= cr1;
            }
            const float mc0 = mn0 * c1, mc1 = mn1 * c1;
            uint32_t p[8][2];
            #pragma unroll
            for (int j = 0; j < 8; j++) {
                float e0 = ex2f(fmaf(s[j][0], c1, -mc0));
                float e1 = ex2f(fmaf(s[j][1], c1, -mc0));
                float e2 = ex2f(fmaf(s[j][2], c1, -mc1));
                float e3 = ex2f(fmaf(s[j][3], c1, -mc1));
                l0 += e0 + e1;
                l1 += e2 + e3;
                p[j][0] = pk_h2(e0, e1);
                p[j][1] = pk_h2(e2, e3);
            }

            // ---- O += P @ V (this half's 64 key rows) ----
            #pragma unroll
            for (int c = 0; c < 4; c++) {
                uint32_t a0 = p[2 * c][0], a1 = p[2 * c][1];
                uint32_t a2 = p[2 * c + 1][0], a3 = p[2 * c + 1][1];
                #pragma unroll
                for (int vp = 0; vp < 4; vp++) {
                    uint32_t off = SWZ((nb + c * 16 + laneRow) * 128 +
                                       vp * 32 + laneCol);
                    uint32_t bv[4];
                    ldsm4t(bv, KVb + off);
                    mma_f16s(o[2 * vp],     a0, a1, a2, a3, bv[0], bv[1]);
                    mma_f16s(o[2 * vp + 1], a0, a1, a2, a3, bv[2], bv[3]);
                }
            }
        }
        __syncthreads();
    }

    l0 += __shfl_xor_sync(0xffffffffu, l0, 1);
    l0 += __shfl_xor_sync(0xffffffffu, l0, 2);
    l1 += __shfl_xor_sync(0xffffffffu, l1, 1);
    l1 += __shfl_xor_sync(0xffffffffu, l1, 2);
    const float inv0 = 1.f / l0, inv1 = 1.f / l1;
    const int b = bh >> 2, h = bh & 3;
    const int r0 = m0 + wid * 16 + (lane >> 2);
    const int cb = (lane & 3) * 2;
    #pragma unroll
    for (int vt = 0; vt < 8; vt++) {
        size_t i0 = (size_t)(b * LL + r0) * CD + h * 64 + vt * 8 + cb;
        size_t i1 = (size_t)(b * LL + r0 + 8) * CD + h * 64 + vt * 8 + cb;
        float v00 = o[vt][0] * inv0, v01 = o[vt][1] * inv0;
        float v10 = o[vt][2] * inv1, v11 = o[vt][3] * inv1;
        __half h00 = __float2half_rn(v00), h01 = __float2half_rn(v01);
        __half h10 = __float2half_rn(v10), h11 = __float2half_rn(v11);
        __half2 hh0; hh0.x = h00; hh0.y = h01;
        __half2 hh1; hh1.x = h10; hh1.y = h11;
        *(uint32_t*)&g_ath[i0] = *(uint32_t*)&hh0;
        *(uint32_t*)&g_ath[i1] = *(uint32_t*)&hh1;
        *(uint32_t*)&g_atl[i0] =
            pk_h2(v00 - __half2float(h00), v01 - __half2float(h01));
        *(uint32_t*)&g_atl[i1] =
            pk_h2(v10 - __half2float(h10), v11 - __half2float(h11));
    }
}

// ---------------------------------------------------------------------------
// Kernel 4: LayerNorm over C=256
// ---------------------------------------------------------------------------
__global__ __launch_bounds__(256) void k_ln(const float* __restrict__ gam,
                                            const float* __restrict__ bet,
                                            float* __restrict__ out) {
    const int row = blockIdx.x * 8 + (threadIdx.x >> 5);
    const int lane = threadIdx.x & 31;
    const float* y = g_y + (size_t)row * CD;
    float v[8], s = 0.f, s2 = 0.f;
    #pragma unroll
    for (int k = 0; k < 8; k++) {
        v[k] = y[lane + 32 * k];
        s += v[k];
        s2 += v[k] * v[k];
    }
    #pragma unroll
    for (int off = 16; off; off >>= 1) {
        s  += __shfl_xor_sync(0xffffffffu, s, off);
        s2 += __shfl_xor_sync(0xffffffffu, s2, off);
    }
    const float mu = s * (1.f / CD);
    const float rstd = rsqrtf(s2 * (1.f / CD) - mu * mu + 1e-5f);
    #pragma unroll
    for (int k = 0; k < 8; k++) {
        int c = lane + 32 * k;
        out[(size_t)row * CD + c] = (v[k] - mu) * rstd * gam[c] + bet[c];
    }
}

// ---------------------------------------------------------------------------
extern "C" void kernel_launch(void* const* d_in, const int* in_sizes, int n_in,
                              void* d_out, int out_size) {
    const float* qin = (const float*)d_in[0];
    const float* wq  = (const float*)d_in[1];
    const float* fw  = (const float*)d_in[2];
    const float* fb  = (const float*)d_in[3];
    const float* lg  = (const float*)d_in[4];
    const float* lb  = (const float*)d_in[5];
    float* out = (float*)d_out;

    const int attn_smem = 65536;   // 3 x 16KB ring + 16KB Q
    const int gemm_smem = 98304;   // 2 x 48KB
    cudaFuncSetAttribute(k_attn_mma,
                         cudaFuncAttributeMaxDynamicSharedMemorySize, attn_smem);
    cudaFuncSetAttribute(k_qkv_mma,
                         cudaFuncAttributeMaxDynamicSharedMemorySize, gemm_smem);
    cudaFuncSetAttribute(k_fc_mma,
                         cudaFuncAttributeMaxDynamicSharedMemorySize, gemm_smem);

    k_prep<<<dim3(LL / 64, CD / 64, NB), 256>>>(qin);
    k_prep_w<<<CD * CD / 256, 256>>>(wq, fw);
    k_qkv_mma<<<dim3(LL / 128, NH, NB), 256, gemm_smem>>>();
    k_attn_mma<<<dim3(LL / 128, NB * NH), 256, attn_smem>>>();
    k_fc_mma<<<dim3(NB * LL / 128, CD / 64), 256, gemm_smem>>>(fb);
    k_ln<<<NB * LL / 8, 256>>>(lg, lb, out);
}

// round 11
// speedup vs baseline: 8.5486x; 1.0777x over previous
#include <cuda_runtime.h>
#include <cuda_fp16.h>
#include <stdint.h>

#define NB 2
#define CD 256
#define LL 4096
#define NH 4
#define DKH 64

static constexpr float LOG2E = 1.4426950408889634f;

__device__ float  g_x  [NB * LL * CD];        // residual: [b][l][c] fp32
__device__ __half g_xh [NB * LL * CD];        // x hi (fp16)
__device__ __half g_xl [NB * LL * CD];        // x lo (fp16)
__device__ __half g_v  [NB * NH * LL * DKH];  // q/k/v heads (fp16)
__device__ __half g_ath[NB * LL * CD];        // attn out hi
__device__ __half g_atl[NB * LL * CD];        // attn out lo
__device__ float  g_y  [NB * LL * CD];        // fc+residual
__device__ __half g_wqh[CD * CD];             // w_qkv hi/lo
__device__ __half g_wql[CD * CD];
__device__ __half g_fwh[CD * CD];             // fc_w hi/lo
__device__ __half g_fwl[CD * CD];
__device__ float  g_norm[NB * NH * LL];       // per-row |q|
__device__ int    g_gmax[NB * NH];            // per-(b,h) max |q| (as int bits)

// ------------------------- helpers -------------------------
__device__ __forceinline__ uint32_t smem_u32(const void* p) {
    uint32_t a;
    asm("{ .reg .u64 t; cvta.to.shared.u64 t, %1; cvt.u32.u64 %0, t; }"
        : "=r"(a) : "l"(p));
    return a;
}
__device__ __forceinline__ uint32_t SWZ(uint32_t o) {
    return o ^ ((o >> 3) & 0x70);
}
__device__ __forceinline__ void ldsm4(uint32_t* r, uint32_t a) {
    asm volatile("ldmatrix.sync.aligned.m8n8.x4.shared.b16 {%0,%1,%2,%3}, [%4];"
                 : "=r"(r[0]), "=r"(r[1]), "=r"(r[2]), "=r"(r[3]) : "r"(a));
}
__device__ __forceinline__ void ldsm4t(uint32_t* r, uint32_t a) {
    asm volatile("ldmatrix.sync.aligned.m8n8.x4.trans.shared.b16 {%0,%1,%2,%3}, [%4];"
                 : "=r"(r[0]), "=r"(r[1]), "=r"(r[2]), "=r"(r[3]) : "r"(a));
}
__device__ __forceinline__ void mma_f16(float* d, const uint32_t* a,
                                        uint32_t b0, uint32_t b1) {
    asm volatile(
        "mma.sync.aligned.m16n8k16.row.col.f32.f16.f16.f32 "
        "{%0,%1,%2,%3}, {%4,%5,%6,%7}, {%8,%9}, {%0,%1,%2,%3};"
        : "+f"(d[0]), "+f"(d[1]), "+f"(d[2]), "+f"(d[3])
        : "r"(a[0]), "r"(a[1]), "r"(a[2]), "r"(a[3]), "r"(b0), "r"(b1));
}
__device__ __forceinline__ void mma_f16s(float* d, uint32_t a0, uint32_t a1,
                                         uint32_t a2, uint32_t a3,
                                         uint32_t b0, uint32_t b1) {
    asm volatile(
        "mma.sync.aligned.m16n8k16.row.col.f32.f16.f16.f32 "
        "{%0,%1,%2,%3}, {%4,%5,%6,%7}, {%8,%9}, {%0,%1,%2,%3};"
        : "+f"(d[0]), "+f"(d[1]), "+f"(d[2]), "+f"(d[3])
        : "r"(a0), "r"(a1), "r"(a2), "r"(a3), "r"(b0), "r"(b1));
}
__device__ __forceinline__ float ex2f(float x) {
    float y;
    asm("ex2.approx.ftz.f32 %0, %1;" : "=f"(y) : "f"(x));
    return y;
}
__device__ __forceinline__ uint32_t pk_h2(float a, float b) {
    __half2 h = __floats2half2_rn(a, b);
    return *(uint32_t*)&h;
}
__device__ __forceinline__ void cpa16(uint32_t s, const void* g) {
    asm volatile("cp.async.cg.shared.global [%0], [%1], 16;" :: "r"(s), "l"(g));
}
__device__ __forceinline__ void cpa_commit() {
    asm volatile("cp.async.commit_group;" ::: "memory");
}
template <int N>
__device__ __forceinline__ void cpa_wait() {
    asm volatile("cp.async.wait_group %0;" :: "n"(N) : "memory");
}

// ---------------------------------------------------------------------------
// Kernel 0a: transpose input -> g_x (fp32) + g_xh/g_xl (fp16 hi/lo)
// ---------------------------------------------------------------------------
__global__ __launch_bounds__(256) void k_prep(const float* __restrict__ qin) {
    __shared__ float T[64][65];
    const int bt = blockIdx.z, c0 = blockIdx.y * 64, l0 = blockIdx.x * 64;
    const int tid = threadIdx.x;
    #pragma unroll
    for (int i = 0; i < 16; i++) {
        int idx = tid + i * 256;
        int ci = idx >> 6, lj = idx & 63;
        T[ci][lj] = qin[(size_t)bt * CD * LL + (size_t)(c0 + ci) * LL + l0 + lj];
    }
    __syncthreads();
    #pragma unroll
    for (int i = 0; i < 16; i++) {
        int idx = tid + i * 256;
        int li = idx >> 6, cj = idx & 63;
        float v = T[cj][li];
        size_t o = (size_t)(bt * LL + l0 + li) * CD + c0 + cj;
        g_x[o] = v;
        __half h = __float2half_rn(v);
        g_xh[o] = h;
        g_xl[o] = __float2half_rn(v - __half2float(h));
    }
}

// ---------------------------------------------------------------------------
// Kernel 0b: convert weights to fp16 hi/lo + reset gmax (one-time per launch)
// ---------------------------------------------------------------------------
__global__ __launch_bounds__(256) void k_prep_w(const float* __restrict__ wq,
                                                const float* __restrict__ fw) {
    int idx = blockIdx.x * 256 + threadIdx.x;   // 65536 total
    if (idx < NB * NH) g_gmax[idx] = 0;
    float v = wq[idx];
    __half h = __float2half_rn(v);
    g_wqh[idx] = h;
    g_wql[idx] = __float2half_rn(v - __half2float(h));
    float u = fw[idx];
    __half g = __float2half_rn(u);
    g_fwh[idx] = g;
    g_fwl[idx] = __float2half_rn(u - __half2float(g));
}

// ---------------------------------------------------------------------------
// Shared GEMM mainloop: M=128 x N=64 x K=256, fp16 hi/lo 3-MMA, pure cp.async.
// ---------------------------------------------------------------------------
__device__ __forceinline__ void gemm_ml(const char* gah, const char* gal,
                                        const char* gbh, const char* gbl,
                                        uint32_t base, int tid, int wid,
                                        uint32_t laneRow, uint32_t laneCol,
                                        float (&acc)[8][4]) {
    auto pref = [&](int kc) {
        uint32_t st = base + (uint32_t)(kc & 1) * 49152u;
        #pragma unroll
        for (int i = 0; i < 4; i++) {             // A: 1024 chunks
            int idx = tid + i * 256;
            int r = idx >> 3, c8 = idx & 7;
            uint32_t so = SWZ(r * 128 + c8 * 16);
            size_t go = (size_t)r * 512 + (size_t)kc * 128 + c8 * 16;
            cpa16(st + so, gah + go);
            cpa16(st + 16384 + so, gal + go);
        }
        #pragma unroll
        for (int i = 0; i < 2; i++) {             // B: 512 chunks
            int idx = tid + i * 256;
            int r = idx >> 3, c8 = idx & 7;
            uint32_t so = SWZ(r * 128 + c8 * 16);
            size_t go = (size_t)r * 512 + (size_t)kc * 128 + c8 * 16;
            cpa16(st + 32768 + so, gbh + go);
            cpa16(st + 40960 + so, gbl + go);
        }
    };
    pref(0); cpa_commit();
    pref(1); cpa_commit();
    #pragma unroll
    for (int kc = 0; kc < 4; kc++) {
        if (kc < 3) cpa_wait<1>(); else cpa_wait<0>();
        __syncthreads();
        uint32_t sb = base + (uint32_t)(kc & 1) * 49152u;
        #pragma unroll
        for (int s = 0; s < 4; s++) {
            uint32_t ah[4], al[4];
            uint32_t offA = SWZ((wid * 16 + laneRow) * 128 + s * 32 + laneCol);
            ldsm4(ah, sb + offA);
            ldsm4(al, sb + 16384 + offA);
            #pragma unroll
            for (int nf = 0; nf < 4; nf++) {
                uint32_t offB = SWZ((nf * 16 + laneRow) * 128 + s * 32 + laneCol);
                uint32_t b4[4], c4[4];
                ldsm4(b4, sb + 32768 + offB);
                ldsm4(c4, sb + 40960 + offB);
                mma_f16(acc[2 * nf],     ah, b4[0], b4[2]);
                mma_f16(acc[2 * nf],     al, b4[0], b4[2]);
                mma_f16(acc[2 * nf],     ah, c4[0], c4[2]);
                mma_f16(acc[2 * nf + 1], ah, b4[1], b4[3]);
                mma_f16(acc[2 * nf + 1], al, b4[1], b4[3]);
                mma_f16(acc[2 * nf + 1], ah, c4[1], c4[3]);
            }
        }
        __syncthreads();
        if (kc + 2 < 4) { pref(kc + 2); cpa_commit(); }
    }
}

// ---------------------------------------------------------------------------
// Kernel 1: QKV projection (HMMA) -> g_v fp16 + row norms + per-(b,h) max
// ---------------------------------------------------------------------------
__global__ __launch_bounds__(256, 2) void k_qkv_mma() {
    extern __shared__ char smg[];
    const uint32_t base = smem_u32(smg);
    const int tid = threadIdx.x, lane = tid & 31, wid = tid >> 5;
    const int m0 = blockIdx.x * 128;
    const int h = blockIdx.y, bt = blockIdx.z, bh = bt * NH + h;
    const uint32_t laneRow = lane & 15;
    const uint32_t laneCol = ((lane >> 4) & 1) * 16;

    float acc[8][4] = {};
    gemm_ml((const char*)(g_xh + (size_t)(bt * LL + m0) * CD),
            (const char*)(g_xl + (size_t)(bt * LL + m0) * CD),
            (const char*)(g_wqh + (size_t)h * 64 * CD),
            (const char*)(g_wql + (size_t)h * 64 * CD),
            base, tid, wid, laneRow, laneCol, acc);

    __half* gv = g_v + (size_t)bh * LL * DKH;
    const int r = m0 + wid * 16 + (lane >> 2);
    const int cb = (lane & 3) * 2;
    float s0 = 0.f, s1 = 0.f;
    #pragma unroll
    for (int f = 0; f < 8; f++) {
        int c = f * 8 + cb;
        *(uint32_t*)&gv[(size_t)r * DKH + c] = pk_h2(acc[f][0], acc[f][1]);
        *(uint32_t*)&gv[(size_t)(r + 8) * DKH + c] = pk_h2(acc[f][2], acc[f][3]);
        s0 += acc[f][0] * acc[f][0] + acc[f][1] * acc[f][1];
        s1 += acc[f][2] * acc[f][2] + acc[f][3] * acc[f][3];
    }
    s0 += __shfl_xor_sync(0xffffffffu, s0, 1);
    s0 += __shfl_xor_sync(0xffffffffu, s0, 2);
    s1 += __shfl_xor_sync(0xffffffffu, s1, 1);
    s1 += __shfl_xor_sync(0xffffffffu, s1, 2);
    if ((lane & 3) == 0) {
        float n0 = sqrtf(s0), n1 = sqrtf(s1);
        g_norm[(size_t)bh * LL + r] = n0;
        g_norm[(size_t)bh * LL + r + 8] = n1;
        atomicMax(&g_gmax[bh], __float_as_int(fmaxf(n0, n1)));
    }
}

// ---------------------------------------------------------------------------
// Kernel 3: fc GEMM (HMMA) + bias + residual -> g_y fp32
// ---------------------------------------------------------------------------
__global__ __launch_bounds__(256, 2) void k_fc_mma(const float* __restrict__ fb) {
    extern __shared__ char smg[];
    const uint32_t base = smem_u32(smg);
    const int tid = threadIdx.x, lane = tid & 31, wid = tid >> 5;
    const int m0 = blockIdx.x * 128;     // row in [0, B*L)
    const int o0 = blockIdx.y * 64;
    const uint32_t laneRow = lane & 15;
    const uint32_t laneCol = ((lane >> 4) & 1) * 16;

    float acc[8][4] = {};
    gemm_ml((const char*)(g_ath + (size_t)m0 * CD),
            (const char*)(g_atl + (size_t)m0 * CD),
            (const char*)(g_fwh + (size_t)o0 * CD),
            (const char*)(g_fwl + (size_t)o0 * CD),
            base, tid, wid, laneRow, laneCol, acc);

    const int r = m0 + wid * 16 + (lane >> 2);
    const int cb = (lane & 3) * 2;
    #pragma unroll
    for (int f = 0; f < 8; f++) {
        int c = o0 + f * 8 + cb;
        float b0 = fb[c], b1 = fb[c + 1];
        float2 res0 = *(const float2*)&g_x[(size_t)r * CD + c];
        float2 res1 = *(const float2*)&g_x[(size_t)(r + 8) * CD + c];
        *(float2*)&g_y[(size_t)r * CD + c] =
            make_float2(acc[f][0] + b0 + res0.x, acc[f][1] + b1 + res0.y);
        *(float2*)&g_y[(size_t)(r + 8) * CD + c] =
            make_float2(acc[f][2] + b0 + res1.x, acc[f][3] + b1 + res1.y);
    }
}

// ---------------------------------------------------------------------------
// Kernel 2: HMMA flash attention with FIXED per-row exp shift (Q==K =>
// Cauchy-Schwarz bound M_i = |q_i|*gmax/8 >= rowmax(S)). No online softmax:
// no max reductions, no shuffles, no O-rescale. p = exp(S - M_i) in (0,1].
// ---------------------------------------------------------------------------
__device__ __forceinline__ void prefetch_kv(uint32_t buf, const char* g, int tid) {
    #pragma unroll
    for (int i = 0; i < 4; i++) {
        int c = tid + i * 256;
        int n = c >> 3, c8 = c & 7;
        uint32_t go = n * 128 + c8 * 16;
        cpa16(buf + SWZ(go), g + go);
    }
}

__global__ __launch_bounds__(256, 2) void k_attn_mma() {
    extern __shared__ char sm[];
    const uint32_t base = smem_u32(sm);

    const int tid = threadIdx.x;
    const int lane = tid & 31;
    const int wid = tid >> 5;
    const int bh = blockIdx.y;
    const int m0 = blockIdx.x * 128;

    const char* gvb = (const char*)(g_v + (size_t)bh * LL * DKH);

    const uint32_t laneRow = lane & 15;
    const uint32_t laneCol = ((lane >> 4) & 1) * 16;

    const uint32_t Qb = base + 3 * 16384;

    #pragma unroll
    for (int i = 0; i < 4; i++) {
        int c = tid + i * 256;
        int n = c >> 3, c8 = c & 7;
        cpa16(Qb + SWZ(n * 128 + c8 * 16), gvb + (m0 + n) * 128 + c8 * 16);
    }
    cpa_commit();
    prefetch_kv(base, gvb, tid);
    cpa_commit();
    prefetch_kv(base + 16384, gvb + 16384, tid);
    cpa_commit();

    cpa_wait<2>();
    __syncthreads();

    uint32_t qh[4][4];
    {
        uint32_t rowb = (wid * 16 + laneRow) * 128;
        #pragma unroll
        for (int c = 0; c < 4; c++)
            ldsm4(qh[c], Qb + SWZ(rowb + c * 32 + laneCol));
    }

    const float c1 = LOG2E * 0.125f;
    // per-thread fixed exp shifts for rows r0 and r0+8
    const int r0 = m0 + wid * 16 + (lane >> 2);
    const float gmax = __int_as_float(g_gmax[bh]);
    const float mc0 = g_norm[(size_t)bh * LL + r0] * gmax * c1;
    const float mc1 = g_norm[(size_t)bh * LL + r0 + 8] * gmax * c1;

    float o[8][4] = {};
    float l0 = 0.f, l1 = 0.f;

    const int NT = LL / 128;
    for (int t = 0; t < NT; t++) {
        const uint32_t KVb = base + (uint32_t)(t % 3) * 16384;

        if (t + 1 < NT) cpa_wait<1>(); else cpa_wait<0>();
        __syncthreads();
        if (t + 2 < NT) {
            prefetch_kv(base + (uint32_t)((t + 2) % 3) * 16384,
                        gvb + (size_t)(t + 2) * 16384, tid);
            cpa_commit();
        }

        #pragma unroll
        for (int hf = 0; hf < 2; hf++) {
            const int nb = hf * 64;

            // ---- S = Q K^T over this 64-col half ----
            float s[8][4];
            #pragma unroll
            for (int j = 0; j < 8; j++)
                #pragma unroll
                for (int k = 0; k < 4; k++) s[j][k] = 0.f;

            #pragma unroll
            for (int jp = 0; jp < 4; jp++) {
                #pragma unroll
                for (int c = 0; c < 4; c++) {
                    uint32_t off = SWZ((nb + jp * 16 + laneRow) * 128 +
                                       c * 32 + laneCol);
                    uint32_t bv[4];
                    ldsm4(bv, KVb + off);
                    mma_f16(s[2 * jp],     qh[c], bv[0], bv[2]);
                    mma_f16(s[2 * jp + 1], qh[c], bv[1], bv[3]);
                }
            }

            // ---- p = exp(S*c1 - mc): no reductions, no rescale ----
            uint32_t p[8][2];
            #pragma unroll
            for (int j = 0; j < 8; j++) {
                float e0 = ex2f(fmaf(s[j][0], c1, -mc0));
                float e1 = ex2f(fmaf(s[j][1], c1, -mc0));
                float e2 = ex2f(fmaf(s[j][2], c1, -mc1));
                float e3 = ex2f(fmaf(s[j][3], c1, -mc1));
                l0 += e0 + e1;
                l1 += e2 + e3;
                p[j][0] = pk_h2(e0, e1);
                p[j][1] = pk_h2(e2, e3);
            }

            // ---- O += P @ V ----
            #pragma unroll
            for (int c = 0; c < 4; c++) {
                uint32_t a0 = p[2 * c][0], a1 = p[2 * c][1];
                uint32_t a2 = p[2 * c + 1][0], a3 = p[2 * c + 1][1];
                #pragma unroll
                for (int vp = 0; vp < 4; vp++) {
                    uint32_t off = SWZ((nb + c * 16 + laneRow) * 128 +
                                       vp * 32 + laneCol);
                    uint32_t bv[4];
                    ldsm4t(bv, KVb + off);
                    mma_f16s(o[2 * vp],     a0, a1, a2, a3, bv[0], bv[1]);
                    mma_f16s(o[2 * vp + 1], a0, a1, a2, a3, bv[2], bv[3]);
                }
            }
        }
        __syncthreads();
    }

    l0 += __shfl_xor_sync(0xffffffffu, l0, 1);
    l0 += __shfl_xor_sync(0xffffffffu, l0, 2);
    l1 += __shfl_xor_sync(0xffffffffu, l1, 1);
    l1 += __shfl_xor_sync(0xffffffffu, l1, 2);
    const float inv0 = 1.f / l0, inv1 = 1.f / l1;
    const int b = bh >> 2, h = bh & 3;
    const int cb = (lane & 3) * 2;
    #pragma unroll
    for (int vt = 0; vt < 8; vt++) {
        size_t i0 = (size_t)(b * LL + r0) * CD + h * 64 + vt * 8 + cb;
        size_t i1 = (size_t)(b * LL + r0 + 8) * CD + h * 64 + vt * 8 + cb;
        float v00 = o[vt][0] * inv0, v01 = o[vt][1] * inv0;
        float v10 = o[vt][2] * inv1, v11 = o[vt][3] * inv1;
        __half h00 = __float2half_rn(v00), h01 = __float2half_rn(v01);
        __half h10 = __float2half_rn(v10), h11 = __float2half_rn(v11);
        __half2 hh0; hh0.x = h00; hh0.y = h01;
        __half2 hh1; hh1.x = h10; hh1.y = h11;
        *(uint32_t*)&g_ath[i0] = *(uint32_t*)&hh0;
        *(uint32_t*)&g_ath[i1] = *(uint32_t*)&hh1;
        *(uint32_t*)&g_atl[i0] =
            pk_h2(v00 - __half2float(h00), v01 - __half2float(h01));
        *(uint32_t*)&g_atl[i1] =
            pk_h2(v10 - __half2float(h10), v11 - __half2float(h11));
    }
}

// ---------------------------------------------------------------------------
// Kernel 4: LayerNorm over C=256
// ---------------------------------------------------------------------------
__global__ __launch_bounds__(256) void k_ln(const float* __restrict__ gam,
                                            const float* __restrict__ bet,
                                            float* __restrict__ out) {
    const int row = blockIdx.x * 8 + (threadIdx.x >> 5);
    const int lane = threadIdx.x & 31;
    const float* y = g_y + (size_t)row * CD;
    float v[8], s = 0.f, s2 = 0.f;
    #pragma unroll
    for (int k = 0; k < 8; k++) {
        v[k] = y[lane + 32 * k];
        s += v[k];
        s2 += v[k] * v[k];
    }
    #pragma unroll
    for (int off = 16; off; off >>= 1) {
        s  += __shfl_xor_sync(0xffffffffu, s, off);
        s2 += __shfl_xor_sync(0xffffffffu, s2, off);
    }
    const float mu = s * (1.f / CD);
    const float rstd = rsqrtf(s2 * (1.f / CD) - mu * mu + 1e-5f);
    #pragma unroll
    for (int k = 0; k < 8; k++) {
        int c = lane + 32 * k;
        out[(size_t)row * CD + c] = (v[k] - mu) * rstd * gam[c] + bet[c];
    }
}

// ---------------------------------------------------------------------------
extern "C" void kernel_launch(void* const* d_in, const int* in_sizes, int n_in,
                              void* d_out, int out_size) {
    const float* qin = (const float*)d_in[0];
    const float* wq  = (const float*)d_in[1];
    const float* fw  = (const float*)d_in[2];
    const float* fb  = (const float*)d_in[3];
    const float* lg  = (const float*)d_in[4];
    const float* lb  = (const float*)d_in[5];
    float* out = (float*)d_out;

    const int attn_smem = 65536;   // 3 x 16KB ring + 16KB Q
    const int gemm_smem = 98304;   // 2 x 48KB
    cudaFuncSetAttribute(k_attn_mma,
                         cudaFuncAttributeMaxDynamicSharedMemorySize, attn_smem);
    cudaFuncSetAttribute(k_qkv_mma,
                         cudaFuncAttributeMaxDynamicSharedMemorySize, gemm_smem);
    cudaFuncSetAttribute(k_fc_mma,
                         cudaFuncAttributeMaxDynamicSharedMemorySize, gemm_smem);

    k_prep<<<dim3(LL / 64, CD / 64, NB), 256>>>(qin);
    k_prep_w<<<CD * CD / 256, 256>>>(wq, fw);
    k_qkv_mma<<<dim3(LL / 128, NH, NB), 256, gemm_smem>>>();
    k_attn_mma<<<dim3(LL / 128, NB * NH), 256, attn_smem>>>();
    k_fc_mma<<<dim3(NB * LL / 128, CD / 64), 256, gemm_smem>>>(fb);
    k_ln<<<NB * LL / 8, 256>>>(lg, lb, out);
}

// round 12
// speedup vs baseline: 8.6866x; 1.0161x over previous
#include <cuda_runtime.h>
#include <cuda_fp16.h>
#include <stdint.h>

#define NB 2
#define CD 256
#define LL 4096
#define NH 4
#define DKH 64

static constexpr float LOG2E = 1.4426950408889634f;

__device__ float  g_x  [NB * LL * CD];        // residual: [b][l][c] fp32
__device__ __half g_xh [NB * LL * CD];        // x hi (fp16)
__device__ __half g_xl [NB * LL * CD];        // x lo (fp16)
__device__ __half g_v  [NB * NH * LL * DKH];  // q/k/v heads (fp16)
__device__ __half g_ath[NB * LL * CD];        // attn out hi
__device__ __half g_atl[NB * LL * CD];        // attn out lo
__device__ float  g_y  [NB * LL * CD];        // fc+residual
__device__ __half g_wqh[CD * CD];             // w_qkv hi/lo
__device__ __half g_wql[CD * CD];
__device__ __half g_fwh[CD * CD];             // fc_w hi/lo
__device__ __half g_fwl[CD * CD];
__device__ float  g_norm[NB * NH * LL];       // per-row |q|
__device__ int    g_gmax[NB * NH];            // per-(b,h) max |q| (int bits)

// ------------------------- helpers -------------------------
__device__ __forceinline__ uint32_t smem_u32(const void* p) {
    uint32_t a;
    asm("{ .reg .u64 t; cvta.to.shared.u64 t, %1; cvt.u32.u64 %0, t; }"
        : "=r"(a) : "l"(p));
    return a;
}
__device__ __forceinline__ uint32_t SWZ(uint32_t o) {
    return o ^ ((o >> 3) & 0x70);
}
__device__ __forceinline__ void ldsm4(uint32_t* r, uint32_t a) {
    asm volatile("ldmatrix.sync.aligned.m8n8.x4.shared.b16 {%0,%1,%2,%3}, [%4];"
                 : "=r"(r[0]), "=r"(r[1]), "=r"(r[2]), "=r"(r[3]) : "r"(a));
}
__device__ __forceinline__ void ldsm4t(uint32_t* r, uint32_t a) {
    asm volatile("ldmatrix.sync.aligned.m8n8.x4.trans.shared.b16 {%0,%1,%2,%3}, [%4];"
                 : "=r"(r[0]), "=r"(r[1]), "=r"(r[2]), "=r"(r[3]) : "r"(a));
}
__device__ __forceinline__ void mma_f16(float* d, const uint32_t* a,
                                        uint32_t b0, uint32_t b1) {
    asm volatile(
        "mma.sync.aligned.m16n8k16.row.col.f32.f16.f16.f32 "
        "{%0,%1,%2,%3}, {%4,%5,%6,%7}, {%8,%9}, {%0,%1,%2,%3};"
        : "+f"(d[0]), "+f"(d[1]), "+f"(d[2]), "+f"(d[3])
        : "r"(a[0]), "r"(a[1]), "r"(a[2]), "r"(a[3]), "r"(b0), "r"(b1));
}
__device__ __forceinline__ void mma_f16s(float* d, uint32_t a0, uint32_t a1,
                                         uint32_t a2, uint32_t a3,
                                         uint32_t b0, uint32_t b1) {
    asm volatile(
        "mma.sync.aligned.m16n8k16.row.col.f32.f16.f16.f32 "
        "{%0,%1,%2,%3}, {%4,%5,%6,%7}, {%8,%9}, {%0,%1,%2,%3};"
        : "+f"(d[0]), "+f"(d[1]), "+f"(d[2]), "+f"(d[3])
        : "r"(a0), "r"(a1), "r"(a2), "r"(a3), "r"(b0), "r"(b1));
}
__device__ __forceinline__ float ex2f(float x) {
    float y;
    asm("ex2.approx.ftz.f32 %0, %1;" : "=f"(y) : "f"(x));
    return y;
}
__device__ __forceinline__ uint32_t pk_h2(float a, float b) {
    __half2 h = __floats2half2_rn(a, b);
    return *(uint32_t*)&h;
}
__device__ __forceinline__ void cpa16(uint32_t s, const void* g) {
    asm volatile("cp.async.cg.shared.global [%0], [%1], 16;" :: "r"(s), "l"(g));
}
__device__ __forceinline__ void cpa_commit() {
    asm volatile("cp.async.commit_group;" ::: "memory");
}
template <int N>
__device__ __forceinline__ void cpa_wait() {
    asm volatile("cp.async.wait_group %0;" :: "n"(N) : "memory");
}

// ---------------------------------------------------------------------------
// Kernel 0a: transpose input -> g_x (fp32) + g_xh/g_xl (fp16 hi/lo)
// ---------------------------------------------------------------------------
__global__ __launch_bounds__(256) void k_prep(const float* __restrict__ qin) {
    __shared__ float T[64][65];
    const int bt = blockIdx.z, c0 = blockIdx.y * 64, l0 = blockIdx.x * 64;
    const int tid = threadIdx.x;
    #pragma unroll
    for (int i = 0; i < 16; i++) {
        int idx = tid + i * 256;
        int ci = idx >> 6, lj = idx & 63;
        T[ci][lj] = qin[(size_t)bt * CD * LL + (size_t)(c0 + ci) * LL + l0 + lj];
    }
    __syncthreads();
    #pragma unroll
    for (int i = 0; i < 16; i++) {
        int idx = tid + i * 256;
        int li = idx >> 6, cj = idx & 63;
        float v = T[cj][li];
        size_t o = (size_t)(bt * LL + l0 + li) * CD + c0 + cj;
        g_x[o] = v;
        __half h = __float2half_rn(v);
        g_xh[o] = h;
        g_xl[o] = __float2half_rn(v - __half2float(h));
    }
}

// ---------------------------------------------------------------------------
// Kernel 0b: convert weights to fp16 hi/lo + reset gmax
// ---------------------------------------------------------------------------
__global__ __launch_bounds__(256) void k_prep_w(const float* __restrict__ wq,
                                                const float* __restrict__ fw) {
    int idx = blockIdx.x * 256 + threadIdx.x;   // 65536 total
    if (idx < NB * NH) g_gmax[idx] = 0;
    float v = wq[idx];
    __half h = __float2half_rn(v);
    g_wqh[idx] = h;
    g_wql[idx] = __float2half_rn(v - __half2float(h));
    float u = fw[idx];
    __half g = __float2half_rn(u);
    g_fwh[idx] = g;
    g_fwl[idx] = __float2half_rn(u - __half2float(g));
}

// ---------------------------------------------------------------------------
// Shared GEMM mainloop: M=128 x N=64 x K=256, fp16 hi/lo 3-MMA, pure cp.async.
// ---------------------------------------------------------------------------
__device__ __forceinline__ void gemm_ml(const char* gah, const char* gal,
                                        const char* gbh, const char* gbl,
                                        uint32_t base, int tid, int wid,
                                        uint32_t laneRow, uint32_t laneCol,
                                        float (&acc)[8][4]) {
    auto pref = [&](int kc) {
        uint32_t st = base + (uint32_t)(kc & 1) * 49152u;
        #pragma unroll
        for (int i = 0; i < 4; i++) {             // A: 1024 chunks
            int idx = tid + i * 256;
            int r = idx >> 3, c8 = idx & 7;
            uint32_t so = SWZ(r * 128 + c8 * 16);
            size_t go = (size_t)r * 512 + (size_t)kc * 128 + c8 * 16;
            cpa16(st + so, gah + go);
            cpa16(st + 16384 + so, gal + go);
        }
        #pragma unroll
        for (int i = 0; i < 2; i++) {             // B: 512 chunks
            int idx = tid + i * 256;
            int r = idx >> 3, c8 = idx & 7;
            uint32_t so = SWZ(r * 128 + c8 * 16);
            size_t go = (size_t)r * 512 + (size_t)kc * 128 + c8 * 16;
            cpa16(st + 32768 + so, gbh + go);
            cpa16(st + 40960 + so, gbl + go);
        }
    };
    pref(0); cpa_commit();
    pref(1); cpa_commit();
    #pragma unroll
    for (int kc = 0; kc < 4; kc++) {
        if (kc < 3) cpa_wait<1>(); else cpa_wait<0>();
        __syncthreads();
        uint32_t sb = base + (uint32_t)(kc & 1) * 49152u;
        #pragma unroll
        for (int s = 0; s < 4; s++) {
            uint32_t ah[4], al[4];
            uint32_t offA = SWZ((wid * 16 + laneRow) * 128 + s * 32 + laneCol);
            ldsm4(ah, sb + offA);
            ldsm4(al, sb + 16384 + offA);
            #pragma unroll
            for (int nf = 0; nf < 4; nf++) {
                uint32_t offB = SWZ((nf * 16 + laneRow) * 128 + s * 32 + laneCol);
                uint32_t b4[4], c4[4];
                ldsm4(b4, sb + 32768 + offB);
                ldsm4(c4, sb + 40960 + offB);
                mma_f16(acc[2 * nf],     ah, b4[0], b4[2]);
                mma_f16(acc[2 * nf],     al, b4[0], b4[2]);
                mma_f16(acc[2 * nf],     ah, c4[0], c4[2]);
                mma_f16(acc[2 * nf + 1], ah, b4[1], b4[3]);
                mma_f16(acc[2 * nf + 1], al, b4[1], b4[3]);
                mma_f16(acc[2 * nf + 1], ah, c4[1], c4[3]);
            }
        }
        __syncthreads();
        if (kc + 2 < 4) { pref(kc + 2); cpa_commit(); }
    }
}

// ---------------------------------------------------------------------------
// Kernel 1: QKV projection (HMMA) -> g_v fp16 + row norms + per-(b,h) max
// ---------------------------------------------------------------------------
__global__ __launch_bounds__(256, 2) void k_qkv_mma() {
    extern __shared__ char smg[];
    const uint32_t base = smem_u32(smg);
    const int tid = threadIdx.x, lane = tid & 31, wid = tid >> 5;
    const int m0 = blockIdx.x * 128;
    const int h = blockIdx.y, bt = blockIdx.z, bh = bt * NH + h;
    const uint32_t laneRow = lane & 15;
    const uint32_t laneCol = ((lane >> 4) & 1) * 16;

    float acc[8][4] = {};
    gemm_ml((const char*)(g_xh + (size_t)(bt * LL + m0) * CD),
            (const char*)(g_xl + (size_t)(bt * LL + m0) * CD),
            (const char*)(g_wqh + (size_t)h * 64 * CD),
            (const char*)(g_wql + (size_t)h * 64 * CD),
            base, tid, wid, laneRow, laneCol, acc);

    __half* gv = g_v + (size_t)bh * LL * DKH;
    const int r = m0 + wid * 16 + (lane >> 2);
    const int cb = (lane & 3) * 2;
    float s0 = 0.f, s1 = 0.f;
    #pragma unroll
    for (int f = 0; f < 8; f++) {
        int c = f * 8 + cb;
        *(uint32_t*)&gv[(size_t)r * DKH + c] = pk_h2(acc[f][0], acc[f][1]);
        *(uint32_t*)&gv[(size_t)(r + 8) * DKH + c] = pk_h2(acc[f][2], acc[f][3]);
        s0 += acc[f][0] * acc[f][0] + acc[f][1] * acc[f][1];
        s1 += acc[f][2] * acc[f][2] + acc[f][3] * acc[f][3];
    }
    s0 += __shfl_xor_sync(0xffffffffu, s0, 1);
    s0 += __shfl_xor_sync(0xffffffffu, s0, 2);
    s1 += __shfl_xor_sync(0xffffffffu, s1, 1);
    s1 += __shfl_xor_sync(0xffffffffu, s1, 2);
    if ((lane & 3) == 0) {
        float n0 = sqrtf(s0), n1 = sqrtf(s1);
        g_norm[(size_t)bh * LL + r] = n0;
        g_norm[(size_t)bh * LL + r + 8] = n1;
        atomicMax(&g_gmax[bh], __float_as_int(fmaxf(n0, n1)));
    }
}

// ---------------------------------------------------------------------------
// Kernel 3: fc GEMM (HMMA) + bias + residual -> g_y fp32
// ---------------------------------------------------------------------------
__global__ __launch_bounds__(256, 2) void k_fc_mma(const float* __restrict__ fb) {
    extern __shared__ char smg[];
    const uint32_t base = smem_u32(smg);
    const int tid = threadIdx.x, lane = tid & 31, wid = tid >> 5;
    const int m0 = blockIdx.x * 128;     // row in [0, B*L)
    const int o0 = blockIdx.y * 64;
    const uint32_t laneRow = lane & 15;
    const uint32_t laneCol = ((lane >> 4) & 1) * 16;

    float acc[8][4] = {};
    gemm_ml((const char*)(g_ath + (size_t)m0 * CD),
            (const char*)(g_atl + (size_t)m0 * CD),
            (const char*)(g_fwh + (size_t)o0 * CD),
            (const char*)(g_fwl + (size_t)o0 * CD),
            base, tid, wid, laneRow, laneCol, acc);

    const int r = m0 + wid * 16 + (lane >> 2);
    const int cb = (lane & 3) * 2;
    #pragma unroll
    for (int f = 0; f < 8; f++) {
        int c = o0 + f * 8 + cb;
        float b0 = fb[c], b1 = fb[c + 1];
        float2 res0 = *(const float2*)&g_x[(size_t)r * CD + c];
        float2 res1 = *(const float2*)&g_x[(size_t)(r + 8) * CD + c];
        *(float2*)&g_y[(size_t)r * CD + c] =
            make_float2(acc[f][0] + b0 + res0.x, acc[f][1] + b1 + res0.y);
        *(float2*)&g_y[(size_t)(r + 8) * CD + c] =
            make_float2(acc[f][2] + b0 + res1.x, acc[f][3] + b1 + res1.y);
    }
}

// ---------------------------------------------------------------------------
// Kernel 2: HMMA flash attention, fixed per-row exp shift (Q==K Cauchy-Schwarz).
// 256 threads / 8 warps; each warp owns 32 q-rows (2 m-frags); CTA = 256 rows.
// Every B-fragment ldsm now feeds 4 MMAs (2 m-frags) - halves LDSM traffic.
// 3-stage KV ring (48KB) + 32KB Q staging = 80KB smem, occ 1.
// ---------------------------------------------------------------------------
__device__ __forceinline__ void prefetch_kv(uint32_t buf, const char* g, int tid) {
    #pragma unroll
    for (int i = 0; i < 4; i++) {
        int c = tid + i * 256;
        int n = c >> 3, c8 = c & 7;
        uint32_t go = n * 128 + c8 * 16;
        cpa16(buf + SWZ(go), g + go);
    }
}

__global__ __launch_bounds__(256) void k_attn_mma() {
    extern __shared__ char sm[];
    const uint32_t base = smem_u32(sm);

    const int tid = threadIdx.x;
    const int lane = tid & 31;
    const int wid = tid >> 5;
    const int bh = blockIdx.y;
    const int m0 = blockIdx.x * 256;

    const char* gvb = (const char*)(g_v + (size_t)bh * LL * DKH);

    const uint32_t laneRow = lane & 15;
    const uint32_t laneCol = ((lane >> 4) & 1) * 16;

    const uint32_t Qb = base + 49152;   // 32KB Q staging after 3x16KB ring

    // ---- stage Q (256 rows) ----
    #pragma unroll
    for (int i = 0; i < 8; i++) {
        int c = tid + i * 256;
        int n = c >> 3, c8 = c & 7;
        cpa16(Qb + SWZ(n * 128 + c8 * 16), gvb + (m0 + n) * 128 + c8 * 16);
    }
    cpa_commit();
    prefetch_kv(base, gvb, tid);
    cpa_commit();
    prefetch_kv(base + 16384, gvb + 16384, tid);
    cpa_commit();

    cpa_wait<2>();
    __syncthreads();

    // ---- Q fragments: 2 m-frags per warp ----
    uint32_t qh[2][4][4];
    #pragma unroll
    for (int mi = 0; mi < 2; mi++) {
        uint32_t rowb = (wid * 32 + mi * 16 + laneRow) * 128;
        #pragma unroll
        for (int c = 0; c < 4; c++)
            ldsm4(qh[mi][c], Qb + SWZ(rowb + c * 32 + laneCol));
    }

    const float c1 = LOG2E * 0.125f;
    const int rbase = m0 + wid * 32 + (lane >> 2);
    const float gmax = __int_as_float(g_gmax[bh]);
    float mc[2][2];
    #pragma unroll
    for (int mi = 0; mi < 2; mi++) {
        mc[mi][0] = g_norm[(size_t)bh * LL + rbase + mi * 16] * gmax * c1;
        mc[mi][1] = g_norm[(size_t)bh * LL + rbase + mi * 16 + 8] * gmax * c1;
    }

    float o[2][8][4] = {};
    float l[2][2] = {};

    const int NT = LL / 128;
    for (int t = 0; t < NT; t++) {
        const uint32_t KVb = base + (uint32_t)(t % 3) * 16384;

        if (t + 1 < NT) cpa_wait<1>(); else cpa_wait<0>();
        __syncthreads();
        if (t + 2 < NT) {
            prefetch_kv(base + (uint32_t)((t + 2) % 3) * 16384,
                        gvb + (size_t)(t + 2) * 16384, tid);
            cpa_commit();
        }

        #pragma unroll
        for (int hf = 0; hf < 2; hf++) {
            const int nb = hf * 64;

            // ---- S = Q K^T, both m-frags share each B ldsm ----
            float s[2][8][4];
            #pragma unroll
            for (int mi = 0; mi < 2; mi++)
                #pragma unroll
                for (int j = 0; j < 8; j++)
                    #pragma unroll
                    for (int k = 0; k < 4; k++) s[mi][j][k] = 0.f;

            #pragma unroll
            for (int jp = 0; jp < 4; jp++) {
                #pragma unroll
                for (int c = 0; c < 4; c++) {
                    uint32_t off = SWZ((nb + jp * 16 + laneRow) * 128 +
                                       c * 32 + laneCol);
                    uint32_t bv[4];
                    ldsm4(bv, KVb + off);
                    mma_f16(s[0][2 * jp],     qh[0][c], bv[0], bv[2]);
                    mma_f16(s[0][2 * jp + 1], qh[0][c], bv[1], bv[3]);
                    mma_f16(s[1][2 * jp],     qh[1][c], bv[0], bv[2]);
                    mma_f16(s[1][2 * jp + 1], qh[1][c], bv[1], bv[3]);
                }
            }

            // ---- p = exp(S*c1 - mc) ----
            uint32_t p[2][8][2];
            #pragma unroll
            for (int mi = 0; mi < 2; mi++) {
                #pragma unroll
                for (int j = 0; j < 8; j++) {
                    float e0 = ex2f(fmaf(s[mi][j][0], c1, -mc[mi][0]));
                    float e1 = ex2f(fmaf(s[mi][j][1], c1, -mc[mi][0]));
                    float e2 = ex2f(fmaf(s[mi][j][2], c1, -mc[mi][1]));
                    float e3 = ex2f(fmaf(s[mi][j][3], c1, -mc[mi][1]));
                    l[mi][0] += e0 + e1;
                    l[mi][1] += e2 + e3;
                    p[mi][j][0] = pk_h2(e0, e1);
                    p[mi][j][1] = pk_h2(e2, e3);
                }
            }

            // ---- O += P @ V, both m-frags share each V ldsm ----
            #pragma unroll
            for (int c = 0; c < 4; c++) {
                #pragma unroll
                for (int vp = 0; vp < 4; vp++) {
                    uint32_t off = SWZ((nb + c * 16 + laneRow) * 128 +
                                       vp * 32 + laneCol);
                    uint32_t bv[4];
                    ldsm4t(bv, KVb + off);
                    mma_f16s(o[0][2 * vp], p[0][2 * c][0], p[0][2 * c][1],
                             p[0][2 * c + 1][0], p[0][2 * c + 1][1],
                             bv[0], bv[1]);
                    mma_f16s(o[0][2 * vp + 1], p[0][2 * c][0], p[0][2 * c][1],
                             p[0][2 * c + 1][0], p[0][2 * c + 1][1],
                             bv[2], bv[3]);
                    mma_f16s(o[1][2 * vp], p[1][2 * c][0], p[1][2 * c][1],
                             p[1][2 * c + 1][0], p[1][2 * c + 1][1],
                             bv[0], bv[1]);
                    mma_f16s(o[1][2 * vp + 1], p[1][2 * c][0], p[1][2 * c][1],
                             p[1][2 * c + 1][0], p[1][2 * c + 1][1],
                             bv[2], bv[3]);
                }
            }
        }
        __syncthreads();
    }

    // ---- epilogue ----
    #pragma unroll
    for (int mi = 0; mi < 2; mi++) {
        #pragma unroll
        for (int hsel = 0; hsel < 2; hsel++) {
            l[mi][hsel] += __shfl_xor_sync(0xffffffffu, l[mi][hsel], 1);
            l[mi][hsel] += __shfl_xor_sync(0xffffffffu, l[mi][hsel], 2);
        }
    }
    const int b = bh >> 2, hd = bh & 3;
    const int cb = (lane & 3) * 2;
    #pragma unroll
    for (int mi = 0; mi < 2; mi++) {
        const float inv0 = 1.f / l[mi][0], inv1 = 1.f / l[mi][1];
        const int r0 = rbase + mi * 16;
        #pragma unroll
        for (int vt = 0; vt < 8; vt++) {
            size_t i0 = (size_t)(b * LL + r0) * CD + hd * 64 + vt * 8 + cb;
            size_t i1 = (size_t)(b * LL + r0 + 8) * CD + hd * 64 + vt * 8 + cb;
            float v00 = o[mi][vt][0] * inv0, v01 = o[mi][vt][1] * inv0;
            float v10 = o[mi][vt][2] * inv1, v11 = o[mi][vt][3] * inv1;
            __half h00 = __float2half_rn(v00), h01 = __float2half_rn(v01);
            __half h10 = __float2half_rn(v10), h11 = __float2half_rn(v11);
            __half2 hh0; hh0.x = h00; hh0.y = h01;
            __half2 hh1; hh1.x = h10; hh1.y = h11;
            *(uint32_t*)&g_ath[i0] = *(uint32_t*)&hh0;
            *(uint32_t*)&g_ath[i1] = *(uint32_t*)&hh1;
            *(uint32_t*)&g_atl[i0] =
                pk_h2(v00 - __half2float(h00), v01 - __half2float(h01));
            *(uint32_t*)&g_atl[i1] =
                pk_h2(v10 - __half2float(h10), v11 - __half2float(h11));
        }
    }
}

// ---------------------------------------------------------------------------
// Kernel 4: LayerNorm over C=256
// ---------------------------------------------------------------------------
__global__ __launch_bounds__(256) void k_ln(const float* __restrict__ gam,
                                            const float* __restrict__ bet,
                                            float* __restrict__ out) {
    const int row = blockIdx.x * 8 + (threadIdx.x >> 5);
    const int lane = threadIdx.x & 31;
    const float* y = g_y + (size_t)row * CD;
    float v[8], s = 0.f, s2 = 0.f;
    #pragma unroll
    for (int k = 0; k < 8; k++) {
        v[k] = y[lane + 32 * k];
        s += v[k];
        s2 += v[k] * v[k];
    }
    #pragma unroll
    for (int off = 16; off; off >>= 1) {
        s  += __shfl_xor_sync(0xffffffffu, s, off);
        s2 += __shfl_xor_sync(0xffffffffu, s2, off);
    }
    const float mu = s * (1.f / CD);
    const float rstd = rsqrtf(s2 * (1.f / CD) - mu * mu + 1e-5f);
    #pragma unroll
    for (int k = 0; k < 8; k++) {
        int c = lane + 32 * k;
        out[(size_t)row * CD + c] = (v[k] - mu) * rstd * gam[c] + bet[c];
    }
}

// ---------------------------------------------------------------------------
extern "C" void kernel_launch(void* const* d_in, const int* in_sizes, int n_in,
                              void* d_out, int out_size) {
    const float* qin = (const float*)d_in[0];
    const float* wq  = (const float*)d_in[1];
    const float* fw  = (const float*)d_in[2];
    const float* fb  = (const float*)d_in[3];
    const float* lg  = (const float*)d_in[4];
    const float* lb  = (const float*)d_in[5];
    float* out = (float*)d_out;

    const int attn_smem = 81920;   // 3 x 16KB ring + 32KB Q
    const int gemm_smem = 98304;   // 2 x 48KB
    cudaFuncSetAttribute(k_attn_mma,
                         cudaFuncAttributeMaxDynamicSharedMemorySize, attn_smem);
    cudaFuncSetAttribute(k_qkv_mma,
                         cudaFuncAttributeMaxDynamicSharedMemorySize, gemm_smem);
    cudaFuncSetAttribute(k_fc_mma,
                         cudaFuncAttributeMaxDynamicSharedMemorySize, gemm_smem);

    k_prep<<<dim3(LL / 64, CD / 64, NB), 256>>>(qin);
    k_prep_w<<<CD * CD / 256, 256>>>(wq, fw);
    k_qkv_mma<<<dim3(LL / 128, NH, NB), 256, gemm_smem>>>();
    k_attn_mma<<<dim3(LL / 256, NB * NH), 256, attn_smem>>>();
    k_fc_mma<<<dim3(NB * LL / 128, CD / 64), 256, gemm_smem>>>(fb);
    k_ln<<<NB * LL / 8, 256>>>(lg, lb, out);
}

// round 13
// speedup vs baseline: 8.7463x; 1.0069x over previous
#include <cuda_runtime.h>
#include <cuda_fp16.h>
#include <stdint.h>

#define NB 2
#define CD 256
#define LL 4096
#define NH 4
#define DKH 64

static constexpr float LOG2E = 1.4426950408889634f;

__device__ float  g_x  [NB * LL * CD];        // residual: [b][l][c] fp32
__device__ __half g_xh [NB * LL * CD];        // x hi (fp16)
__device__ __half g_xl [NB * LL * CD];        // x lo (fp16)
__device__ __half g_v  [NB * NH * LL * DKH];  // q/k/v heads (fp16)
__device__ __half g_ath[NB * LL * CD];        // attn out hi
__device__ __half g_atl[NB * LL * CD];        // attn out lo
__device__ float  g_y  [NB * LL * CD];        // fc+residual
__device__ __half g_wqh[CD * CD];             // w_qkv hi/lo
__device__ __half g_wql[CD * CD];
__device__ __half g_fwh[CD * CD];             // fc_w hi/lo
__device__ __half g_fwl[CD * CD];
__device__ float  g_norm[NB * NH * LL];       // per-row |q|
__device__ int    g_gmax[NB * NH];            // per-(b,h) max |q| (int bits)

// ------------------------- helpers -------------------------
__device__ __forceinline__ uint32_t smem_u32(const void* p) {
    uint32_t a;
    asm("{ .reg .u64 t; cvta.to.shared.u64 t, %1; cvt.u32.u64 %0, t; }"
        : "=r"(a) : "l"(p));
    return a;
}
__device__ __forceinline__ uint32_t SWZ(uint32_t o) {
    return o ^ ((o >> 3) & 0x70);
}
__device__ __forceinline__ void ldsm4(uint32_t* r, uint32_t a) {
    asm volatile("ldmatrix.sync.aligned.m8n8.x4.shared.b16 {%0,%1,%2,%3}, [%4];"
                 : "=r"(r[0]), "=r"(r[1]), "=r"(r[2]), "=r"(r[3]) : "r"(a));
}
__device__ __forceinline__ void ldsm4t(uint32_t* r, uint32_t a) {
    asm volatile("ldmatrix.sync.aligned.m8n8.x4.trans.shared.b16 {%0,%1,%2,%3}, [%4];"
                 : "=r"(r[0]), "=r"(r[1]), "=r"(r[2]), "=r"(r[3]) : "r"(a));
}
__device__ __forceinline__ void mma_f16(float* d, const uint32_t* a,
                                        uint32_t b0, uint32_t b1) {
    asm volatile(
        "mma.sync.aligned.m16n8k16.row.col.f32.f16.f16.f32 "
        "{%0,%1,%2,%3}, {%4,%5,%6,%7}, {%8,%9}, {%0,%1,%2,%3};"
        : "+f"(d[0]), "+f"(d[1]), "+f"(d[2]), "+f"(d[3])
        : "r"(a[0]), "r"(a[1]), "r"(a[2]), "r"(a[3]), "r"(b0), "r"(b1));
}
__device__ __forceinline__ void mma_f16s(float* d, uint32_t a0, uint32_t a1,
                                         uint32_t a2, uint32_t a3,
                                         uint32_t b0, uint32_t b1) {
    asm volatile(
        "mma.sync.aligned.m16n8k16.row.col.f32.f16.f16.f32 "
        "{%0,%1,%2,%3}, {%4,%5,%6,%7}, {%8,%9}, {%0,%1,%2,%3};"
        : "+f"(d[0]), "+f"(d[1]), "+f"(d[2]), "+f"(d[3])
        : "r"(a0), "r"(a1), "r"(a2), "r"(a3), "r"(b0), "r"(b1));
}
__device__ __forceinline__ float ex2f(float x) {
    float y;
    asm("ex2.approx.ftz.f32 %0, %1;" : "=f"(y) : "f"(x));
    return y;
}
__device__ __forceinline__ uint32_t pk_h2(float a, float b) {
    __half2 h = __floats2half2_rn(a, b);
    return *(uint32_t*)&h;
}
__device__ __forceinline__ void cpa16(uint32_t s, const void* g) {
    asm volatile("cp.async.cg.shared.global [%0], [%1], 16;" :: "r"(s), "l"(g));
}
__device__ __forceinline__ void cpa_commit() {
    asm volatile("cp.async.commit_group;" ::: "memory");
}
template <int N>
__device__ __forceinline__ void cpa_wait() {
    asm volatile("cp.async.wait_group %0;" :: "n"(N) : "memory");
}

// ---------------------------------------------------------------------------
// Kernel 0a: transpose input -> g_x (fp32) + g_xh/g_xl (fp16 hi/lo)
// ---------------------------------------------------------------------------
__global__ __launch_bounds__(256) void k_prep(const float* __restrict__ qin) {
    __shared__ float T[64][65];
    const int bt = blockIdx.z, c0 = blockIdx.y * 64, l0 = blockIdx.x * 64;
    const int tid = threadIdx.x;
    #pragma unroll
    for (int i = 0; i < 16; i++) {
        int idx = tid + i * 256;
        int ci = idx >> 6, lj = idx & 63;
        T[ci][lj] = qin[(size_t)bt * CD * LL + (size_t)(c0 + ci) * LL + l0 + lj];
    }
    __syncthreads();
    #pragma unroll
    for (int i = 0; i < 16; i++) {
        int idx = tid + i * 256;
        int li = idx >> 6, cj = idx & 63;
        float v = T[cj][li];
        size_t o = (size_t)(bt * LL + l0 + li) * CD + c0 + cj;
        g_x[o] = v;
        __half h = __float2half_rn(v);
        g_xh[o] = h;
        g_xl[o] = __float2half_rn(v - __half2float(h));
    }
}

// ---------------------------------------------------------------------------
// Kernel 0b: convert weights to fp16 hi/lo + reset gmax
// ---------------------------------------------------------------------------
__global__ __launch_bounds__(256) void k_prep_w(const float* __restrict__ wq,
                                                const float* __restrict__ fw) {
    int idx = blockIdx.x * 256 + threadIdx.x;   // 65536 total
    if (idx < NB * NH) g_gmax[idx] = 0;
    float v = wq[idx];
    __half h = __float2half_rn(v);
    g_wqh[idx] = h;
    g_wql[idx] = __float2half_rn(v - __half2float(h));
    float u = fw[idx];
    __half g = __float2half_rn(u);
    g_fwh[idx] = g;
    g_fwl[idx] = __float2half_rn(u - __half2float(g));
}

// ---------------------------------------------------------------------------
// Shared GEMM mainloop: M=128 x N=64 x K=256, fp16 hi/lo 3-MMA, pure cp.async.
// ---------------------------------------------------------------------------
__device__ __forceinline__ void gemm_ml(const char* gah, const char* gal,
                                        const char* gbh, const char* gbl,
                                        uint32_t base, int tid, int wid,
                                        uint32_t laneRow, uint32_t laneCol,
                                        float (&acc)[8][4]) {
    auto pref = [&](int kc) {
        uint32_t st = base + (uint32_t)(kc & 1) * 49152u;
        #pragma unroll
        for (int i = 0; i < 4; i++) {             // A: 1024 chunks
            int idx = tid + i * 256;
            int r = idx >> 3, c8 = idx & 7;
            uint32_t so = SWZ(r * 128 + c8 * 16);
            size_t go = (size_t)r * 512 + (size_t)kc * 128 + c8 * 16;
            cpa16(st + so, gah + go);
            cpa16(st + 16384 + so, gal + go);
        }
        #pragma unroll
        for (int i = 0; i < 2; i++) {             // B: 512 chunks
            int idx = tid + i * 256;
            int r = idx >> 3, c8 = idx & 7;
            uint32_t so = SWZ(r * 128 + c8 * 16);
            size_t go = (size_t)r * 512 + (size_t)kc * 128 + c8 * 16;
            cpa16(st + 32768 + so, gbh + go);
            cpa16(st + 40960 + so, gbl + go);
        }
    };
    pref(0); cpa_commit();
    pref(1); cpa_commit();
    #pragma unroll
    for (int kc = 0; kc < 4; kc++) {
        if (kc < 3) cpa_wait<1>(); else cpa_wait<0>();
        __syncthreads();
        uint32_t sb = base + (uint32_t)(kc & 1) * 49152u;
        #pragma unroll
        for (int s = 0; s < 4; s++) {
            uint32_t ah[4], al[4];
            uint32_t offA = SWZ((wid * 16 + laneRow) * 128 + s * 32 + laneCol);
            ldsm4(ah, sb + offA);
            ldsm4(al, sb + 16384 + offA);
            #pragma unroll
            for (int nf = 0; nf < 4; nf++) {
                uint32_t offB = SWZ((nf * 16 + laneRow) * 128 + s * 32 + laneCol);
                uint32_t b4[4], c4[4];
                ldsm4(b4, sb + 32768 + offB);
                ldsm4(c4, sb + 40960 + offB);
                mma_f16(acc[2 * nf],     ah, b4[0], b4[2]);
                mma_f16(acc[2 * nf],     al, b4[0], b4[2]);
                mma_f16(acc[2 * nf],     ah, c4[0], c4[2]);
                mma_f16(acc[2 * nf + 1], ah, b4[1], b4[3]);
                mma_f16(acc[2 * nf + 1], al, b4[1], b4[3]);
                mma_f16(acc[2 * nf + 1], ah, c4[1], c4[3]);
            }
        }
        __syncthreads();
        if (kc + 2 < 4) { pref(kc + 2); cpa_commit(); }
    }
}

// ---------------------------------------------------------------------------
// Kernel 1: QKV projection (HMMA) -> g_v fp16 + row norms + per-(b,h) max
// ---------------------------------------------------------------------------
__global__ __launch_bounds__(256, 2) void k_qkv_mma() {
    extern __shared__ char smg[];
    const uint32_t base = smem_u32(smg);
    const int tid = threadIdx.x, lane = tid & 31, wid = tid >> 5;
    const int m0 = blockIdx.x * 128;
    const int h = blockIdx.y, bt = blockIdx.z, bh = bt * NH + h;
    const uint32_t laneRow = lane & 15;
    const uint32_t laneCol = ((lane >> 4) & 1) * 16;

    float acc[8][4] = {};
    gemm_ml((const char*)(g_xh + (size_t)(bt * LL + m0) * CD),
            (const char*)(g_xl + (size_t)(bt * LL + m0) * CD),
            (const char*)(g_wqh + (size_t)h * 64 * CD),
            (const char*)(g_wql + (size_t)h * 64 * CD),
            base, tid, wid, laneRow, laneCol, acc);

    __half* gv = g_v + (size_t)bh * LL * DKH;
    const int r = m0 + wid * 16 + (lane >> 2);
    const int cb = (lane & 3) * 2;
    float s0 = 0.f, s1 = 0.f;
    #pragma unroll
    for (int f = 0; f < 8; f++) {
        int c = f * 8 + cb;
        *(uint32_t*)&gv[(size_t)r * DKH + c] = pk_h2(acc[f][0], acc[f][1]);
        *(uint32_t*)&gv[(size_t)(r + 8) * DKH + c] = pk_h2(acc[f][2], acc[f][3]);
        s0 += acc[f][0] * acc[f][0] + acc[f][1] * acc[f][1];
        s1 += acc[f][2] * acc[f][2] + acc[f][3] * acc[f][3];
    }
    s0 += __shfl_xor_sync(0xffffffffu, s0, 1);
    s0 += __shfl_xor_sync(0xffffffffu, s0, 2);
    s1 += __shfl_xor_sync(0xffffffffu, s1, 1);
    s1 += __shfl_xor_sync(0xffffffffu, s1, 2);
    if ((lane & 3) == 0) {
        float n0 = sqrtf(s0), n1 = sqrtf(s1);
        g_norm[(size_t)bh * LL + r] = n0;
        g_norm[(size_t)bh * LL + r + 8] = n1;
        atomicMax(&g_gmax[bh], __float_as_int(fmaxf(n0, n1)));
    }
}

// ---------------------------------------------------------------------------
// Kernel 3: fc GEMM (HMMA) + bias + residual -> g_y fp32
// ---------------------------------------------------------------------------
__global__ __launch_bounds__(256, 2) void k_fc_mma(const float* __restrict__ fb) {
    extern __shared__ char smg[];
    const uint32_t base = smem_u32(smg);
    const int tid = threadIdx.x, lane = tid & 31, wid = tid >> 5;
    const int m0 = blockIdx.x * 128;     // row in [0, B*L)
    const int o0 = blockIdx.y * 64;
    const uint32_t laneRow = lane & 15;
    const uint32_t laneCol = ((lane >> 4) & 1) * 16;

    float acc[8][4] = {};
    gemm_ml((const char*)(g_ath + (size_t)m0 * CD),
            (const char*)(g_atl + (size_t)m0 * CD),
            (const char*)(g_fwh + (size_t)o0 * CD),
            (const char*)(g_fwl + (size_t)o0 * CD),
            base, tid, wid, laneRow, laneCol, acc);

    const int r = m0 + wid * 16 + (lane >> 2);
    const int cb = (lane & 3) * 2;
    #pragma unroll
    for (int f = 0; f < 8; f++) {
        int c = o0 + f * 8 + cb;
        float b0 = fb[c], b1 = fb[c + 1];
        float2 res0 = *(const float2*)&g_x[(size_t)r * CD + c];
        float2 res1 = *(const float2*)&g_x[(size_t)(r + 8) * CD + c];
        *(float2*)&g_y[(size_t)r * CD + c] =
            make_float2(acc[f][0] + b0 + res0.x, acc[f][1] + b1 + res0.y);
        *(float2*)&g_y[(size_t)(r + 8) * CD + c] =
            make_float2(acc[f][2] + b0 + res1.x, acc[f][3] + b1 + res1.y);
    }
}

// ---------------------------------------------------------------------------
// Kernel 2: HMMA flash attention, fixed per-row exp shift (Q==K Cauchy-Schwarz).
// 128 threads / 4 warps per CTA; each warp owns 32 q-rows (2 m-frags);
// CTA = 128 q-rows; grid = 256 CTAs; 2 CTAs/SM run phase-decorrelated so one
// CTA's tensor MMAs overlap the other's softmax (MUFU) phase.
// smem per CTA: 3 x 16KB KV ring + 16KB Q = 64KB.
// ---------------------------------------------------------------------------
__device__ __forceinline__ void prefetch_kv(uint32_t buf, const char* g, int tid) {
    #pragma unroll
    for (int i = 0; i < 8; i++) {
        int c = tid + i * 128;
        int n = c >> 3, c8 = c & 7;
        uint32_t go = n * 128 + c8 * 16;
        cpa16(buf + SWZ(go), g + go);
    }
}

__global__ __launch_bounds__(128, 2) void k_attn_mma() {
    extern __shared__ char sm[];
    const uint32_t base = smem_u32(sm);

    const int tid = threadIdx.x;
    const int lane = tid & 31;
    const int wid = tid >> 5;
    const int bh = blockIdx.y;
    const int m0 = blockIdx.x * 128;

    const char* gvb = (const char*)(g_v + (size_t)bh * LL * DKH);

    const uint32_t laneRow = lane & 15;
    const uint32_t laneCol = ((lane >> 4) & 1) * 16;

    const uint32_t Qb = base + 49152;   // 16KB Q staging after 3x16KB ring

    // ---- stage Q (128 rows) ----
    #pragma unroll
    for (int i = 0; i < 8; i++) {
        int c = tid + i * 128;
        int n = c >> 3, c8 = c & 7;
        cpa16(Qb + SWZ(n * 128 + c8 * 16), gvb + (m0 + n) * 128 + c8 * 16);
    }
    cpa_commit();
    prefetch_kv(base, gvb, tid);
    cpa_commit();
    prefetch_kv(base + 16384, gvb + 16384, tid);
    cpa_commit();

    cpa_wait<2>();
    __syncthreads();

    // ---- Q fragments: 2 m-frags per warp ----
    uint32_t qh[2][4][4];
    #pragma unroll
    for (int mi = 0; mi < 2; mi++) {
        uint32_t rowb = (wid * 32 + mi * 16 + laneRow) * 128;
        #pragma unroll
        for (int c = 0; c < 4; c++)
            ldsm4(qh[mi][c], Qb + SWZ(rowb + c * 32 + laneCol));
    }

    const float c1 = LOG2E * 0.125f;
    const int rbase = m0 + wid * 32 + (lane >> 2);
    const float gmax = __int_as_float(g_gmax[bh]);
    float mc[2][2];
    #pragma unroll
    for (int mi = 0; mi < 2; mi++) {
        mc[mi][0] = g_norm[(size_t)bh * LL + rbase + mi * 16] * gmax * c1;
        mc[mi][1] = g_norm[(size_t)bh * LL + rbase + mi * 16 + 8] * gmax * c1;
    }

    float o[2][8][4] = {};
    float l[2][2] = {};

    const int NT = LL / 128;
    for (int t = 0; t < NT; t++) {
        const uint32_t KVb = base + (uint32_t)(t % 3) * 16384;

        if (t + 1 < NT) cpa_wait<1>(); else cpa_wait<0>();
        __syncthreads();
        if (t + 2 < NT) {
            prefetch_kv(base + (uint32_t)((t + 2) % 3) * 16384,
                        gvb + (size_t)(t + 2) * 16384, tid);
            cpa_commit();
        }

        #pragma unroll
        for (int hf = 0; hf < 2; hf++) {
            const int nb = hf * 64;

            // ---- S = Q K^T, both m-frags share each B ldsm ----
            float s[2][8][4];
            #pragma unroll
            for (int mi = 0; mi < 2; mi++)
                #pragma unroll
                for (int j = 0; j < 8; j++)
                    #pragma unroll
                    for (int k = 0; k < 4; k++) s[mi][j][k] = 0.f;

            #pragma unroll
            for (int jp = 0; jp < 4; jp++) {
                #pragma unroll
                for (int c = 0; c < 4; c++) {
                    uint32_t off = SWZ((nb + jp * 16 + laneRow) * 128 +
                                       c * 32 + laneCol);
                    uint32_t bv[4];
                    ldsm4(bv, KVb + off);
                    mma_f16(s[0][2 * jp],     qh[0][c], bv[0], bv[2]);
                    mma_f16(s[0][2 * jp + 1], qh[0][c], bv[1], bv[3]);
                    mma_f16(s[1][2 * jp],     qh[1][c], bv[0], bv[2]);
                    mma_f16(s[1][2 * jp + 1], qh[1][c], bv[1], bv[3]);
                }
            }

            // ---- p = exp(S*c1 - mc) ----
            uint32_t p[2][8][2];
            #pragma unroll
            for (int mi = 0; mi < 2; mi++) {
                #pragma unroll
                for (int j = 0; j < 8; j++) {
                    float e0 = ex2f(fmaf(s[mi][j][0], c1, -mc[mi][0]));
                    float e1 = ex2f(fmaf(s[mi][j][1], c1, -mc[mi][0]));
                    float e2 = ex2f(fmaf(s[mi][j][2], c1, -mc[mi][1]));
                    float e3 = ex2f(fmaf(s[mi][j][3], c1, -mc[mi][1]));
                    l[mi][0] += e0 + e1;
                    l[mi][1] += e2 + e3;
                    p[mi][j][0] = pk_h2(e0, e1);
                    p[mi][j][1] = pk_h2(e2, e3);
                }
            }

            // ---- O += P @ V, both m-frags share each V ldsm ----
            #pragma unroll
            for (int c = 0; c < 4; c++) {
                #pragma unroll
                for (int vp = 0; vp < 4; vp++) {
                    uint32_t off = SWZ((nb + c * 16 + laneRow) * 128 +
                                       vp * 32 + laneCol);
                    uint32_t bv[4];
                    ldsm4t(bv, KVb + off);
                    mma_f16s(o[0][2 * vp], p[0][2 * c][0], p[0][2 * c][1],
                             p[0][2 * c + 1][0], p[0][2 * c + 1][1],
                             bv[0], bv[1]);
                    mma_f16s(o[0][2 * vp + 1], p[0][2 * c][0], p[0][2 * c][1],
                             p[0][2 * c + 1][0], p[0][2 * c + 1][1],
                             bv[2], bv[3]);
                    mma_f16s(o[1][2 * vp], p[1][2 * c][0], p[1][2 * c][1],
                             p[1][2 * c + 1][0], p[1][2 * c + 1][1],
                             bv[0], bv[1]);
                    mma_f16s(o[1][2 * vp + 1], p[1][2 * c][0], p[1][2 * c][1],
                             p[1][2 * c + 1][0], p[1][2 * c + 1][1],
                             bv[2], bv[3]);
                }
            }
        }
        __syncthreads();
    }

    // ---- epilogue ----
    #pragma unroll
    for (int mi = 0; mi < 2; mi++) {
        #pragma unroll
        for (int hsel = 0; hsel < 2; hsel++) {
            l[mi][hsel] += __shfl_xor_sync(0xffffffffu, l[mi][hsel], 1);
            l[mi][hsel] += __shfl_xor_sync(0xffffffffu, l[mi][hsel], 2);
        }
    }
    const int b = bh >> 2, hd = bh & 3;
    const int cb = (lane & 3) * 2;
    #pragma unroll
    for (int mi = 0; mi < 2; mi++) {
        const float inv0 = 1.f / l[mi][0], inv1 = 1.f / l[mi][1];
        const int r0 = rbase + mi * 16;
        #pragma unroll
        for (int vt = 0; vt < 8; vt++) {
            size_t i0 = (size_t)(b * LL + r0) * CD + hd * 64 + vt * 8 + cb;
            size_t i1 = (size_t)(b * LL + r0 + 8) * CD + hd * 64 + vt * 8 + cb;
            float v00 = o[mi][vt][0] * inv0, v01 = o[mi][vt][1] * inv0;
            float v10 = o[mi][vt][2] * inv1, v11 = o[mi][vt][3] * inv1;
            __half h00 = __float2half_rn(v00), h01 = __float2half_rn(v01);
            __half h10 = __float2half_rn(v10), h11 = __float2half_rn(v11);
            __half2 hh0; hh0.x = h00; hh0.y = h01;
            __half2 hh1; hh1.x = h10; hh1.y = h11;
            *(uint32_t*)&g_ath[i0] = *(uint32_t*)&hh0;
            *(uint32_t*)&g_ath[i1] = *(uint32_t*)&hh1;
            *(uint32_t*)&g_atl[i0] =
                pk_h2(v00 - __half2float(h00), v01 - __half2float(h01));
            *(uint32_t*)&g_atl[i1] =
                pk_h2(v10 - __half2float(h10), v11 - __half2float(h11));
        }
    }
}

// ---------------------------------------------------------------------------
// Kernel 4: LayerNorm over C=256
// ---------------------------------------------------------------------------
__global__ __launch_bounds__(256) void k_ln(const float* __restrict__ gam,
                                            const float* __restrict__ bet,
                                            float* __restrict__ out) {
    const int row = blockIdx.x * 8 + (threadIdx.x >> 5);
    const int lane = threadIdx.x & 31;
    const float* y = g_y + (size_t)row * CD;
    float v[8], s = 0.f, s2 = 0.f;
    #pragma unroll
    for (int k = 0; k < 8; k++) {
        v[k] = y[lane + 32 * k];
        s += v[k];
        s2 += v[k] * v[k];
    }
    #pragma unroll
    for (int off = 16; off; off >>= 1) {
        s  += __shfl_xor_sync(0xffffffffu, s, off);
        s2 += __shfl_xor_sync(0xffffffffu, s2, off);
    }
    const float mu = s * (1.f / CD);
    const float rstd = rsqrtf(s2 * (1.f / CD) - mu * mu + 1e-5f);
    #pragma unroll
    for (int k = 0; k < 8; k++) {
        int c = lane + 32 * k;
        out[(size_t)row * CD + c] = (v[k] - mu) * rstd * gam[c] + bet[c];
    }
}

// ---------------------------------------------------------------------------
extern "C" void kernel_launch(void* const* d_in, const int* in_sizes, int n_in,
                              void* d_out, int out_size) {
    const float* qin = (const float*)d_in[0];
    const float* wq  = (const float*)d_in[1];
    const float* fw  = (const float*)d_in[2];
    const float* fb  = (const float*)d_in[3];
    const float* lg  = (const float*)d_in[4];
    const float* lb  = (const float*)d_in[5];
    float* out = (float*)d_out;

    const int attn_smem = 65536;   // 3 x 16KB ring + 16KB Q (per 128-thr CTA)
    const int gemm_smem = 98304;   // 2 x 48KB
    cudaFuncSetAttribute(k_attn_mma,
                         cudaFuncAttributeMaxDynamicSharedMemorySize, attn_smem);
    cudaFuncSetAttribute(k_qkv_mma,
                         cudaFuncAttributeMaxDynamicSharedMemorySize, gemm_smem);
    cudaFuncSetAttribute(k_fc_mma,
                         cudaFuncAttributeMaxDynamicSharedMemorySize, gemm_smem);

    k_prep<<<dim3(LL / 64, CD / 64, NB), 256>>>(qin);
    k_prep_w<<<CD * CD / 256, 256>>>(wq, fw);
    k_qkv_mma<<<dim3(LL / 128, NH, NB), 256, gemm_smem>>>();
    k_attn_mma<<<dim3(LL / 128, NB * NH), 128, attn_smem>>>();
    k_fc_mma<<<dim3(NB * LL / 128, CD / 64), 256, gemm_smem>>>(fb);
    k_ln<<<NB * LL / 8, 256>>>(lg, lb, out);
}